// round 3
// baseline (speedup 1.0000x reference)
#include <cuda_runtime.h>

// Problem constants
#define B_   2
#define S_   2048
#define D_   1024
#define FF_  4096
#define H_   16
#define DH_  64
#define L_   4
#define MTOK (B_ * S_)   // 4096 tokens

// ---------------------------------------------------------------------------
// Scratch buffers (static device globals; no runtime allocation)
// ---------------------------------------------------------------------------
__device__ float g_x  [MTOK * D_];   // running hidden state
__device__ float g_q  [MTOK * D_];
__device__ float g_k  [MTOK * D_];
__device__ float g_v  [MTOK * D_];
__device__ float g_ctx[MTOK * D_];
__device__ float g_t  [MTOK * D_];   // pre-LN temp
__device__ float g_ff [MTOK * FF_];  // FFN hidden

// ---------------------------------------------------------------------------
// GEMM: C[M,N] = A[M,K] @ W[K,N] + bias (+ residual) (+ ReLU)
// 128x128 block tile, BK=8, 256 threads, 8x8 per-thread microtile,
// single-stage smem with register prefetch of next global tile.
// All dims are multiples of 128/8 for this problem -> no bounds checks.
// ---------------------------------------------------------------------------
__global__ void __launch_bounds__(256) gemm_kernel(
    const float* __restrict__ A, const float* __restrict__ W,
    const float* __restrict__ bias, const float* __restrict__ Rsd,
    float* __restrict__ C, int M, int N, int K, int relu)
{
    __shared__ float As[8][128];   // transposed A tile: As[k][row]
    __shared__ float Bs[8][128];   // natural B tile:    Bs[k][col]

    const int tid = threadIdx.x;
    const int ty = tid >> 4, tx = tid & 15;           // 16x16 compute grid
    const int ar = tid >> 1, ac = (tid & 1) << 2;     // A load: 2 thr/row, float4
    const int br = tid >> 5, bc = (tid & 31) << 2;    // B load: 32 thr/row, float4

    const size_t arow = (size_t)(blockIdx.y * 128 + ar);
    const float* Aptr = A + arow * K + ac;
    const float* Wptr = W + (size_t)br * N + blockIdx.x * 128 + bc;

    float acc[8][8] = {};

    float4 av = *(const float4*)(Aptr);
    float4 bv = *(const float4*)(Wptr);

    for (int k0 = 0; k0 < K; k0 += 8) {
        As[ac + 0][ar] = av.x;
        As[ac + 1][ar] = av.y;
        As[ac + 2][ar] = av.z;
        As[ac + 3][ar] = av.w;
        *(float4*)&Bs[br][bc] = bv;
        __syncthreads();

        if (k0 + 8 < K) {
            av = *(const float4*)(Aptr + k0 + 8);
            bv = *(const float4*)(Wptr + (size_t)(k0 + 8) * N);
        }

        #pragma unroll
        for (int k = 0; k < 8; k++) {
            float a[8], b[8];
            *(float4*)(a)     = *(const float4*)&As[k][ty * 8];
            *(float4*)(a + 4) = *(const float4*)&As[k][ty * 8 + 4];
            *(float4*)(b)     = *(const float4*)&Bs[k][tx * 8];
            *(float4*)(b + 4) = *(const float4*)&Bs[k][tx * 8 + 4];
            #pragma unroll
            for (int i = 0; i < 8; i++)
                #pragma unroll
                for (int j = 0; j < 8; j++)
                    acc[i][j] = fmaf(a[i], b[j], acc[i][j]);
        }
        __syncthreads();
    }

    const int crow0 = blockIdx.y * 128 + ty * 8;
    const int ccol0 = blockIdx.x * 128 + tx * 8;
    #pragma unroll
    for (int i = 0; i < 8; i++) {
        const size_t rb = (size_t)(crow0 + i) * N + ccol0;
        #pragma unroll
        for (int j = 0; j < 8; j++) {
            float v = acc[i][j] + bias[ccol0 + j];
            if (Rsd) v += Rsd[rb + j];
            if (relu) v = fmaxf(v, 0.0f);
            C[rb + j] = v;
        }
    }
}

// ---------------------------------------------------------------------------
// LayerNorm over last dim (D=1024). One block (256 threads) per row.
// ---------------------------------------------------------------------------
__inline__ __device__ float warpSum(float v) {
    #pragma unroll
    for (int o = 16; o > 0; o >>= 1) v += __shfl_xor_sync(0xffffffffu, v, o);
    return v;
}

__global__ void __launch_bounds__(256) ln_kernel(
    const float* __restrict__ in, const float* __restrict__ gamma,
    const float* __restrict__ beta, float* __restrict__ out)
{
    const size_t row = blockIdx.x;
    const float4 val = ((const float4*)(in + row * D_))[threadIdx.x];

    float s  = val.x + val.y + val.z + val.w;
    float sq = val.x * val.x + val.y * val.y + val.z * val.z + val.w * val.w;

    __shared__ float ssum[8], ssq[8];
    s  = warpSum(s);
    sq = warpSum(sq);
    const int wid = threadIdx.x >> 5, lane = threadIdx.x & 31;
    if (lane == 0) { ssum[wid] = s; ssq[wid] = sq; }
    __syncthreads();
    s = 0.f; sq = 0.f;
    #pragma unroll
    for (int i = 0; i < 8; i++) { s += ssum[i]; sq += ssq[i]; }

    const float mean = s * (1.0f / D_);
    const float var  = sq * (1.0f / D_) - mean * mean;
    const float rstd = rsqrtf(var + 1e-6f);

    const int c = threadIdx.x << 2;
    const float4 gv = *(const float4*)(gamma + c);
    const float4 bb = *(const float4*)(beta + c);
    float4 o;
    o.x = (val.x - mean) * rstd * gv.x + bb.x;
    o.y = (val.y - mean) * rstd * gv.y + bb.y;
    o.z = (val.z - mean) * rstd * gv.z + bb.z;
    o.w = (val.w - mean) * rstd * gv.w + bb.w;
    ((float4*)(out + row * D_))[threadIdx.x] = o;
}

// ---------------------------------------------------------------------------
// Fused flash-style attention (fp32). Grid: (S/64, H, B). 256 threads.
// 64-row query tile, iterate 64-key tiles with online softmax.
// smem layouts transposed so the two matmul inner loops are LDS.128-friendly.
// ---------------------------------------------------------------------------
#define APAD 68
#define ATTN_SMEM_FLOATS (4 * 64 * APAD + 4 * 64 + 256)
#define ATTN_SMEM_BYTES  (ATTN_SMEM_FLOATS * 4)

__global__ void __launch_bounds__(256) attn_kernel(
    const float* __restrict__ Qg, const float* __restrict__ Kg,
    const float* __restrict__ Vg, float* __restrict__ Og)
{
    extern __shared__ float sm[];
    float* QsT = sm;                   // [d][q]    64x68
    float* KsT = QsT + 64 * APAD;      // [d][kcol] 64x68
    float* Vs  = KsT + 64 * APAD;      // [kpos][d] 64x68
    float* PsT = Vs  + 64 * APAD;      // [kcol][q] 64x68
    float* m_s = PsT + 64 * APAD;      // running row max   [64]
    float* l_s = m_s + 64;             // running row sum   [64]
    float* a_s = l_s + 64;             // rescale alpha     [64]
    float* m2  = a_s + 64;             // new row max bcast [64]
    float* red = m2 + 64;              // partial reduce    [256]

    const int tid = threadIdx.x;
    const int qt = blockIdx.x, h = blockIdx.y, b = blockIdx.z;
    const int ty = tid >> 4, tx = tid & 15;
    const int srow = tid & 63, spart = tid >> 6;

    // Load Q tile (scaled by 1/sqrt(DH)=0.125), transposed.
    {
        const float* qbase = Qg + ((size_t)(b * S_) + qt * 64) * D_ + h * DH_;
        for (int idx = tid; idx < 64 * 16; idx += 256) {
            const int r = idx >> 4, c4 = (idx & 15) << 2;
            float4 val = *(const float4*)(qbase + (size_t)r * D_ + c4);
            QsT[(c4 + 0) * APAD + r] = val.x * 0.125f;
            QsT[(c4 + 1) * APAD + r] = val.y * 0.125f;
            QsT[(c4 + 2) * APAD + r] = val.z * 0.125f;
            QsT[(c4 + 3) * APAD + r] = val.w * 0.125f;
        }
    }
    if (tid < 64) { m_s[tid] = -1e30f; l_s[tid] = 0.0f; }

    float acc[4][4] = {};
    __syncthreads();

    const float* kbase = Kg + (size_t)(b * S_) * D_ + h * DH_;
    const float* vbase = Vg + (size_t)(b * S_) * D_ + h * DH_;

    for (int j0 = 0; j0 < S_; j0 += 64) {
        // Load K (transposed) and V (natural) tiles
        for (int idx = tid; idx < 64 * 16; idx += 256) {
            const int r = idx >> 4, c4 = (idx & 15) << 2;
            float4 kv = *(const float4*)(kbase + (size_t)(j0 + r) * D_ + c4);
            KsT[(c4 + 0) * APAD + r] = kv.x;
            KsT[(c4 + 1) * APAD + r] = kv.y;
            KsT[(c4 + 2) * APAD + r] = kv.z;
            KsT[(c4 + 3) * APAD + r] = kv.w;
            float4 vv = *(const float4*)(vbase + (size_t)(j0 + r) * D_ + c4);
            *(float4*)&Vs[r * APAD + c4] = vv;
        }
        __syncthreads();

        // S = Q @ K^T  (rows ty*4+i = query, cols tx*4+j = key)
        float s4[4][4] = {};
        #pragma unroll 16
        for (int k = 0; k < 64; k++) {
            float a4[4], b4[4];
            *(float4*)a4 = *(const float4*)&QsT[k * APAD + ty * 4];
            *(float4*)b4 = *(const float4*)&KsT[k * APAD + tx * 4];
            #pragma unroll
            for (int i = 0; i < 4; i++)
                #pragma unroll
                for (int j = 0; j < 4; j++)
                    s4[i][j] = fmaf(a4[i], b4[j], s4[i][j]);
        }
        #pragma unroll
        for (int j = 0; j < 4; j++)
            #pragma unroll
            for (int i = 0; i < 4; i++)
                PsT[(tx * 4 + j) * APAD + ty * 4 + i] = s4[i][j];
        __syncthreads();

        // Online softmax: row max (4 threads/row, 16 cols each)
        float mloc = -1e30f;
        #pragma unroll
        for (int c = 0; c < 16; c++)
            mloc = fmaxf(mloc, PsT[(spart * 16 + c) * APAD + srow]);
        red[tid] = mloc;
        __syncthreads();
        if (tid < 64) {
            const float mo = m_s[tid];
            float mn = fmaxf(fmaxf(red[tid], red[tid + 64]),
                             fmaxf(red[tid + 128], red[tid + 192]));
            mn = fmaxf(mn, mo);
            m2[tid]  = mn;
            a_s[tid] = __expf(mo - mn);
            m_s[tid] = mn;
        }
        __syncthreads();

        // exp + partial row sums
        const float mn = m2[srow];
        float psum = 0.0f;
        #pragma unroll
        for (int c = 0; c < 16; c++) {
            const int off = (spart * 16 + c) * APAD + srow;
            const float p = __expf(PsT[off] - mn);
            PsT[off] = p;
            psum += p;
        }
        red[tid] = psum;
        __syncthreads();
        if (tid < 64)
            l_s[tid] = l_s[tid] * a_s[tid]
                     + red[tid] + red[tid + 64] + red[tid + 128] + red[tid + 192];

        // Rescale running O, then O += P @ V
        float alpha[4];
        #pragma unroll
        for (int i = 0; i < 4; i++) alpha[i] = a_s[ty * 4 + i];
        #pragma unroll
        for (int i = 0; i < 4; i++)
            #pragma unroll
            for (int j = 0; j < 4; j++)
                acc[i][j] *= alpha[i];

        #pragma unroll 16
        for (int k = 0; k < 64; k++) {
            float p4[4], v4[4];
            *(float4*)p4 = *(const float4*)&PsT[k * APAD + ty * 4];
            *(float4*)v4 = *(const float4*)&Vs[k * APAD + tx * 4];
            #pragma unroll
            for (int i = 0; i < 4; i++)
                #pragma unroll
                for (int j = 0; j < 4; j++)
                    acc[i][j] = fmaf(p4[i], v4[j], acc[i][j]);
        }
        __syncthreads();
    }

    // Epilogue: divide by running sum, write ctx
    float linv[4];
    #pragma unroll
    for (int i = 0; i < 4; i++) linv[i] = 1.0f / l_s[ty * 4 + i];
    #pragma unroll
    for (int i = 0; i < 4; i++) {
        float4 o;
        o.x = acc[i][0] * linv[i];
        o.y = acc[i][1] * linv[i];
        o.z = acc[i][2] * linv[i];
        o.w = acc[i][3] * linv[i];
        *(float4*)(Og + ((size_t)(b * S_) + qt * 64 + ty * 4 + i) * D_
                      + h * DH_ + tx * 4) = o;
    }
}

// ---------------------------------------------------------------------------
// Launch
// ---------------------------------------------------------------------------
extern "C" void kernel_launch(void* const* d_in, const int* in_sizes, int n_in,
                              void* d_out, int out_size)
{
    (void)in_sizes; (void)n_in; (void)out_size;

    const float* hs  = (const float*)d_in[0];
    const float* Wq  = (const float*)d_in[1];
    const float* bq  = (const float*)d_in[2];
    const float* Wk  = (const float*)d_in[3];
    const float* bk  = (const float*)d_in[4];
    const float* Wv  = (const float*)d_in[5];
    const float* bv  = (const float*)d_in[6];
    const float* Wp  = (const float*)d_in[7];
    const float* bp  = (const float*)d_in[8];
    const float* g1  = (const float*)d_in[9];
    const float* be1 = (const float*)d_in[10];
    const float* W1  = (const float*)d_in[11];
    const float* b1  = (const float*)d_in[12];
    const float* W2  = (const float*)d_in[13];
    const float* b2  = (const float*)d_in[14];
    const float* g2  = (const float*)d_in[15];
    const float* be2 = (const float*)d_in[16];

    float *x, *q, *k, *v, *ctx, *t, *ff;
    cudaGetSymbolAddress((void**)&x,   g_x);
    cudaGetSymbolAddress((void**)&q,   g_q);
    cudaGetSymbolAddress((void**)&k,   g_k);
    cudaGetSymbolAddress((void**)&v,   g_v);
    cudaGetSymbolAddress((void**)&ctx, g_ctx);
    cudaGetSymbolAddress((void**)&t,   g_t);
    cudaGetSymbolAddress((void**)&ff,  g_ff);

    cudaFuncSetAttribute(attn_kernel,
                         cudaFuncAttributeMaxDynamicSharedMemorySize,
                         ATTN_SMEM_BYTES);

    cudaMemcpyAsync(x, hs, (size_t)MTOK * D_ * sizeof(float),
                    cudaMemcpyDeviceToDevice, 0);

    const dim3 blk(256);
    const dim3 gD(D_ / 128, MTOK / 128);    // (8, 32)
    const dim3 gF(FF_ / 128, MTOK / 128);   // (32, 32)
    const dim3 gA(S_ / 64, H_, B_);         // (32, 16, 2)

    for (int l = 0; l < L_; l++) {
        const float* wq = Wq + (size_t)l * D_ * D_;
        const float* wk = Wk + (size_t)l * D_ * D_;
        const float* wv = Wv + (size_t)l * D_ * D_;
        const float* wp = Wp + (size_t)l * D_ * D_;
        const float* w1 = W1 + (size_t)l * D_ * FF_;
        const float* w2 = W2 + (size_t)l * FF_ * D_;

        gemm_kernel<<<gD, blk>>>(x, wq, bq + (size_t)l * D_, nullptr, q,
                                 MTOK, D_, D_, 0);
        gemm_kernel<<<gD, blk>>>(x, wk, bk + (size_t)l * D_, nullptr, k,
                                 MTOK, D_, D_, 0);
        gemm_kernel<<<gD, blk>>>(x, wv, bv + (size_t)l * D_, nullptr, v,
                                 MTOK, D_, D_, 0);

        attn_kernel<<<gA, blk, ATTN_SMEM_BYTES>>>(q, k, v, ctx);

        gemm_kernel<<<gD, blk>>>(ctx, wp, bp + (size_t)l * D_, x, t,
                                 MTOK, D_, D_, 0);
        ln_kernel<<<MTOK, 256>>>(t, g1 + (size_t)l * D_, be1 + (size_t)l * D_, x);

        gemm_kernel<<<gF, blk>>>(x, w1, b1 + (size_t)l * FF_, nullptr, ff,
                                 MTOK, FF_, D_, 1);
        gemm_kernel<<<gD, blk>>>(ff, w2, b2 + (size_t)l * D_, x, t,
                                 MTOK, D_, FF_, 0);

        float* lnout = (l == L_ - 1) ? (float*)d_out : x;
        ln_kernel<<<MTOK, 256>>>(t, g2 + (size_t)l * D_, be2 + (size_t)l * D_, lnout);
    }
}

// round 5
// speedup vs baseline: 1.7150x; 1.7150x over previous
#include <cuda_runtime.h>
#include <cuda_bf16.h>
#include <cstdint>

// Problem constants
#define B_    2
#define S_    2048
#define D_    1024
#define FF_   4096
#define H_    16
#define DH_   64
#define L_    4
#define MTOK  (B_ * S_)      // 4096 tokens
#define QKV_N (3 * D_)       // 3072

// ---------------------------------------------------------------------------
// Scratch (static device globals; no runtime allocation)
// ---------------------------------------------------------------------------
__device__ float         g_x   [MTOK * D_];           // running hidden (fp32)
__device__ __nv_bfloat16 g_xhi [MTOK * D_];
__device__ __nv_bfloat16 g_xlo [MTOK * D_];
__device__ float         g_qkv [MTOK * QKV_N];        // fused QKV output (fp32)
__device__ __nv_bfloat16 g_chi [MTOK * D_];           // attention ctx hi/lo
__device__ __nv_bfloat16 g_clo [MTOK * D_];
__device__ float         g_t   [MTOK * D_];           // pre-LN temp
__device__ __nv_bfloat16 g_ffhi[MTOK * FF_];
__device__ __nv_bfloat16 g_fflo[MTOK * FF_];

// transposed + hi/lo-split weights ([N, K] row-major, bf16)
__device__ __nv_bfloat16 g_wqkv_hi[L_ * QKV_N * D_];
__device__ __nv_bfloat16 g_wqkv_lo[L_ * QKV_N * D_];
__device__ __nv_bfloat16 g_wp_hi  [L_ * D_ * D_];
__device__ __nv_bfloat16 g_wp_lo  [L_ * D_ * D_];
__device__ __nv_bfloat16 g_w1_hi  [L_ * FF_ * D_];    // [FF, D]
__device__ __nv_bfloat16 g_w1_lo  [L_ * FF_ * D_];
__device__ __nv_bfloat16 g_w2_hi  [L_ * D_ * FF_];    // [D, FF]
__device__ __nv_bfloat16 g_w2_lo  [L_ * D_ * FF_];
__device__ float         g_bqkv  [L_ * QKV_N];

// ---------------------------------------------------------------------------
// Baseline-PTX helpers (sm_80+ features only; no 'a'-suffix features)
// ---------------------------------------------------------------------------
__device__ __forceinline__ uint32_t smem_u32(const void* p) {
    uint32_t a;
    asm("{ .reg .u64 t; cvta.to.shared.u64 t, %1; cvt.u32.u64 %0, t; }"
        : "=r"(a) : "l"(p));
    return a;
}
__device__ __forceinline__ void cp16(uint32_t s, const void* g) {
    asm volatile("cp.async.cg.shared.global [%0], [%1], 16;" :: "r"(s), "l"(g));
}
#define CP_COMMIT() asm volatile("cp.async.commit_group;" ::: "memory")

__device__ __forceinline__ void mma16816(float c[4], const uint32_t a[4],
                                         const uint32_t b[2]) {
    asm volatile(
        "mma.sync.aligned.m16n8k16.row.col.f32.bf16.bf16.f32 "
        "{%0,%1,%2,%3}, {%4,%5,%6,%7}, {%8,%9}, {%0,%1,%2,%3};"
        : "+f"(c[0]), "+f"(c[1]), "+f"(c[2]), "+f"(c[3])
        : "r"(a[0]), "r"(a[1]), "r"(a[2]), "r"(a[3]),
          "r"(b[0]), "r"(b[1]));
}
__device__ __forceinline__ uint32_t pack_bf2(float a, float b) {
    __nv_bfloat162 t(__float2bfloat16(a), __float2bfloat16(b));
    return reinterpret_cast<uint32_t&>(t);
}

// ---------------------------------------------------------------------------
// mma.sync bf16 GEMM:  C[M,N] = (Ahi+Alo)[M,K] @ (Bhi+Blo)[N,K]^T + bias
//                      (+ residual) (+ relu); outputs fp32 and/or bf16 hi/lo.
// Block 128x128, 8 warps (2x4 -> warp tile 64x32), K-stage 32,
// cp.async double-buffered smem, chunk-XOR swizzle, 3-pass hi/lo split.
// Grid: (N/128, M/128), 256 threads.
// ---------------------------------------------------------------------------
// smem: per stage, 4 arrays (Ahi, Alo, Bhi, Blo), each 128 rows x 64B = 8 KB.
// Row r, 16B chunk ch stored at r*64 + (ch ^ (r&3) ^ ((r>>2)&1))*16.
#define GSTAGE  32768
#define GSMEM   (2 * GSTAGE)   // 65536

__device__ __forceinline__ void gemm_load_stage(
    uint32_t sbase, const __nv_bfloat16* __restrict__ Ahi,
    const __nv_bfloat16* __restrict__ Alo,
    const __nv_bfloat16* __restrict__ Bhi,
    const __nv_bfloat16* __restrict__ Blo,
    int m0, int n0, int K, int k0, int tid)
{
    #pragma unroll
    for (int i = 0; i < 2; i++) {
        const int task = tid + i * 256;          // 512 chunk tasks
        const int r = task >> 2, ch = task & 3;
        const uint32_t soff = r * 64 + ((ch ^ (r & 3) ^ ((r >> 2) & 1)) << 4);
        const size_t ga = (size_t)(m0 + r) * K + k0 + ch * 8;
        const size_t gb = (size_t)(n0 + r) * K + k0 + ch * 8;
        cp16(sbase +         soff, Ahi + ga);
        cp16(sbase +  8192 + soff, Alo + ga);
        cp16(sbase + 16384 + soff, Bhi + gb);
        cp16(sbase + 24576 + soff, Blo + gb);
    }
}

__global__ void __launch_bounds__(256, 1) gemm_mma(
    const __nv_bfloat16* __restrict__ Ahi, const __nv_bfloat16* __restrict__ Alo,
    const __nv_bfloat16* __restrict__ Bhi, const __nv_bfloat16* __restrict__ Blo,
    const float* __restrict__ bias, const float* __restrict__ Rsd,
    float* __restrict__ Cf,
    __nv_bfloat16* __restrict__ Chi, __nv_bfloat16* __restrict__ Clo,
    int K, int N, int relu)
{
    extern __shared__ char sm[];
    const uint32_t smb = smem_u32(sm);
    const int tid = threadIdx.x;
    const int wid = tid >> 5, lane = tid & 31;
    const int wm = wid >> 2, wn = wid & 3;          // warp grid 2x4
    const int lq = lane >> 2, lr = lane & 3;
    const int m0 = blockIdx.y * 128, n0 = blockIdx.x * 128;
    const int sw = (lq & 3) ^ ((lq >> 2) & 1);      // per-lane chunk swizzle

    float acc[4][4][4];
    #pragma unroll
    for (int i = 0; i < 4; i++)
        #pragma unroll
        for (int j = 0; j < 4; j++)
            #pragma unroll
            for (int k = 0; k < 4; k++) acc[i][j][k] = 0.0f;

    const int NS = K / 32;

    gemm_load_stage(smb, Ahi, Alo, Bhi, Blo, m0, n0, K, 0, tid);
    CP_COMMIT();

    for (int s = 0; s < NS; s++) {
        if (s + 1 < NS) {
            gemm_load_stage(smb + ((s + 1) & 1) * GSTAGE,
                            Ahi, Alo, Bhi, Blo, m0, n0, K, (s + 1) * 32, tid);
            CP_COMMIT();
            asm volatile("cp.async.wait_group 1;" ::: "memory");
        } else {
            asm volatile("cp.async.wait_group 0;" ::: "memory");
        }
        __syncthreads();

        const char* buf = sm + (s & 1) * GSTAGE;
        const char* sAh = buf;
        const char* sAl = buf + 8192;
        const char* sBh = buf + 16384;
        const char* sBl = buf + 24576;

        #pragma unroll
        for (int kk = 0; kk < 2; kk++) {
            const uint32_t c0 = (uint32_t)((2 * kk + 0) ^ sw) << 4;
            const uint32_t c1 = (uint32_t)((2 * kk + 1) ^ sw) << 4;

            uint32_t ah[4][4], al[4][4], bh[4][2], bl[4][2];
            #pragma unroll
            for (int mt = 0; mt < 4; mt++) {
                const uint32_t ro = (uint32_t)(wm * 4096 + mt * 1024 + lq * 64 + lr * 4);
                ah[mt][0] = *(const uint32_t*)(sAh + ro + c0);
                ah[mt][1] = *(const uint32_t*)(sAh + ro + c0 + 512);
                ah[mt][2] = *(const uint32_t*)(sAh + ro + c1);
                ah[mt][3] = *(const uint32_t*)(sAh + ro + c1 + 512);
                al[mt][0] = *(const uint32_t*)(sAl + ro + c0);
                al[mt][1] = *(const uint32_t*)(sAl + ro + c0 + 512);
                al[mt][2] = *(const uint32_t*)(sAl + ro + c1);
                al[mt][3] = *(const uint32_t*)(sAl + ro + c1 + 512);
            }
            #pragma unroll
            for (int nt = 0; nt < 4; nt++) {
                const uint32_t ro = (uint32_t)(wn * 2048 + nt * 512 + lq * 64 + lr * 4);
                bh[nt][0] = *(const uint32_t*)(sBh + ro + c0);
                bh[nt][1] = *(const uint32_t*)(sBh + ro + c1);
                bl[nt][0] = *(const uint32_t*)(sBl + ro + c0);
                bl[nt][1] = *(const uint32_t*)(sBl + ro + c1);
            }
            #pragma unroll
            for (int mt = 0; mt < 4; mt++)
                #pragma unroll
                for (int nt = 0; nt < 4; nt++) {
                    mma16816(acc[mt][nt], ah[mt], bh[nt]);   // hi*hi
                    mma16816(acc[mt][nt], ah[mt], bl[nt]);   // hi*lo
                    mma16816(acc[mt][nt], al[mt], bh[nt]);   // lo*hi
                }
        }
        __syncthreads();
    }

    // Epilogue: fragment (mt,nt): c0,c1 at (row lq, col lr*2), c2,c3 at row+8.
    const int row0 = m0 + wm * 64;
    const int col0 = n0 + wn * 32;
    #pragma unroll
    for (int mt = 0; mt < 4; mt++) {
        #pragma unroll
        for (int nt = 0; nt < 4; nt++) {
            const int c = col0 + nt * 8 + lr * 2;
            const float b0 = bias[c], b1 = bias[c + 1];
            #pragma unroll
            for (int h = 0; h < 2; h++) {
                const int r = row0 + mt * 16 + lq + h * 8;
                float v0 = acc[mt][nt][2 * h]     + b0;
                float v1 = acc[mt][nt][2 * h + 1] + b1;
                const size_t o = (size_t)r * N + c;
                if (Rsd) {
                    const float2 rv = *(const float2*)(Rsd + o);
                    v0 += rv.x; v1 += rv.y;
                }
                if (relu) { v0 = fmaxf(v0, 0.0f); v1 = fmaxf(v1, 0.0f); }
                if (Cf) *(float2*)(Cf + o) = make_float2(v0, v1);
                if (Chi) {
                    const __nv_bfloat16 h0 = __float2bfloat16(v0);
                    const __nv_bfloat16 h1 = __float2bfloat16(v1);
                    __nv_bfloat162 hh(h0, h1);
                    *(uint32_t*)(Chi + o) = reinterpret_cast<uint32_t&>(hh);
                    *(uint32_t*)(Clo + o) = pack_bf2(v0 - __bfloat162float(h0),
                                                     v1 - __bfloat162float(h1));
                }
            }
        }
    }
}

// ---------------------------------------------------------------------------
// Weight transpose + hi/lo split: W fp32 [K,N] -> Ohi/Olo bf16 [N,K]
// grid (N/32, K/32, L), 256 threads
// ---------------------------------------------------------------------------
__global__ void __launch_bounds__(256) transpose_split(
    const float* __restrict__ W, __nv_bfloat16* __restrict__ Ohi,
    __nv_bfloat16* __restrict__ Olo, int K, int N,
    size_t in_lstride, size_t out_lstride)
{
    __shared__ float t[32][33];
    const int l = blockIdx.z;
    const float* Wl = W + (size_t)l * in_lstride;
    __nv_bfloat16* Hl = Ohi + (size_t)l * out_lstride;
    __nv_bfloat16* Ll = Olo + (size_t)l * out_lstride;
    const int k0 = blockIdx.y * 32, n0 = blockIdx.x * 32;
    const int tx = threadIdx.x & 31, ty = threadIdx.x >> 5;
    #pragma unroll
    for (int i = 0; i < 32; i += 8)
        t[ty + i][tx] = Wl[(size_t)(k0 + ty + i) * N + n0 + tx];
    __syncthreads();
    #pragma unroll
    for (int i = 0; i < 32; i += 8) {
        const float v = t[tx][ty + i];
        const __nv_bfloat16 h = __float2bfloat16(v);
        const size_t o = (size_t)(n0 + ty + i) * K + k0 + tx;
        Hl[o] = h;
        Ll[o] = __float2bfloat16(v - __bfloat162float(h));
    }
}

__global__ void concat_bias(const float* __restrict__ bq, const float* __restrict__ bk,
                            const float* __restrict__ bv, float* __restrict__ out)
{
    const int i = blockIdx.x * 256 + threadIdx.x;       // L * 3072 total
    if (i >= L_ * QKV_N) return;
    const int l = i / QKV_N, j = i % QKV_N;
    float v;
    if (j < D_)            v = bq[l * D_ + j];
    else if (j < 2 * D_)   v = bk[l * D_ + j - D_];
    else                   v = bv[l * D_ + j - 2 * D_];
    out[i] = v;
}

__global__ void split_f32(const float* __restrict__ in,
                          __nv_bfloat16* __restrict__ hi,
                          __nv_bfloat16* __restrict__ lo, int n)
{
    const int i = blockIdx.x * 256 + threadIdx.x;
    if (i >= n) return;
    const float v = in[i];
    const __nv_bfloat16 h = __float2bfloat16(v);
    hi[i] = h;
    lo[i] = __float2bfloat16(v - __bfloat162float(h));
}

// ---------------------------------------------------------------------------
// LayerNorm over last dim (D=1024); fused fp32 + optional bf16 hi/lo output.
// ---------------------------------------------------------------------------
__inline__ __device__ float warpSum(float v) {
    #pragma unroll
    for (int o = 16; o > 0; o >>= 1) v += __shfl_xor_sync(0xffffffffu, v, o);
    return v;
}

__global__ void __launch_bounds__(256) ln_kernel(
    const float* __restrict__ in, const float* __restrict__ gamma,
    const float* __restrict__ beta, float* __restrict__ out,
    __nv_bfloat16* __restrict__ ohi, __nv_bfloat16* __restrict__ olo)
{
    const size_t row = blockIdx.x;
    const float4 val = ((const float4*)(in + row * D_))[threadIdx.x];

    float s  = val.x + val.y + val.z + val.w;
    float sq = val.x * val.x + val.y * val.y + val.z * val.z + val.w * val.w;

    __shared__ float ssum[8], ssq[8];
    s  = warpSum(s);
    sq = warpSum(sq);
    const int wid = threadIdx.x >> 5, lane = threadIdx.x & 31;
    if (lane == 0) { ssum[wid] = s; ssq[wid] = sq; }
    __syncthreads();
    s = 0.f; sq = 0.f;
    #pragma unroll
    for (int i = 0; i < 8; i++) { s += ssum[i]; sq += ssq[i]; }

    const float mean = s * (1.0f / D_);
    const float var  = sq * (1.0f / D_) - mean * mean;
    const float rstd = rsqrtf(var + 1e-6f);

    const int c = threadIdx.x << 2;
    const float4 gv = *(const float4*)(gamma + c);
    const float4 bb = *(const float4*)(beta + c);
    float4 o;
    o.x = (val.x - mean) * rstd * gv.x + bb.x;
    o.y = (val.y - mean) * rstd * gv.y + bb.y;
    o.z = (val.z - mean) * rstd * gv.z + bb.z;
    o.w = (val.w - mean) * rstd * gv.w + bb.w;
    ((float4*)(out + row * D_))[threadIdx.x] = o;

    if (ohi) {
        const __nv_bfloat16 h0 = __float2bfloat16(o.x), h1 = __float2bfloat16(o.y);
        const __nv_bfloat16 h2 = __float2bfloat16(o.z), h3 = __float2bfloat16(o.w);
        __nv_bfloat162 hh0(h0, h1), hh1(h2, h3);
        *(uint2*)(ohi + row * D_ + c) =
            make_uint2(reinterpret_cast<uint32_t&>(hh0),
                       reinterpret_cast<uint32_t&>(hh1));
        *(uint2*)(olo + row * D_ + c) = make_uint2(
            pack_bf2(o.x - __bfloat162float(h0), o.y - __bfloat162float(h1)),
            pack_bf2(o.z - __bfloat162float(h2), o.w - __bfloat162float(h3)));
    }
}

// ---------------------------------------------------------------------------
// Fused flash-style attention (fp32 math). Reads fused QKV buffer (row stride
// 3072); writes ctx as bf16 hi/lo. Grid: (S/64, H, B). 256 threads.
// ---------------------------------------------------------------------------
#define APAD 68
#define ATTN_SMEM_FLOATS (4 * 64 * APAD + 4 * 64 + 256)
#define ATTN_SMEM_BYTES  (ATTN_SMEM_FLOATS * 4)

__global__ void __launch_bounds__(256) attn_kernel(
    const float* __restrict__ Qg, const float* __restrict__ Kg,
    const float* __restrict__ Vg,
    __nv_bfloat16* __restrict__ Chi, __nv_bfloat16* __restrict__ Clo)
{
    extern __shared__ float smf[];
    float* QsT = smf;
    float* KsT = QsT + 64 * APAD;
    float* Vs  = KsT + 64 * APAD;
    float* PsT = Vs  + 64 * APAD;
    float* m_s = PsT + 64 * APAD;
    float* l_s = m_s + 64;
    float* a_s = l_s + 64;
    float* m2  = a_s + 64;
    float* red = m2 + 64;

    const int tid = threadIdx.x;
    const int qt = blockIdx.x, h = blockIdx.y, b = blockIdx.z;
    const int ty = tid >> 4, tx = tid & 15;
    const int srow = tid & 63, spart = tid >> 6;

    {
        const float* qbase = Qg + ((size_t)(b * S_) + qt * 64) * QKV_N + h * DH_;
        for (int idx = tid; idx < 64 * 16; idx += 256) {
            const int r = idx >> 4, c4 = (idx & 15) << 2;
            float4 val = *(const float4*)(qbase + (size_t)r * QKV_N + c4);
            QsT[(c4 + 0) * APAD + r] = val.x * 0.125f;
            QsT[(c4 + 1) * APAD + r] = val.y * 0.125f;
            QsT[(c4 + 2) * APAD + r] = val.z * 0.125f;
            QsT[(c4 + 3) * APAD + r] = val.w * 0.125f;
        }
    }
    if (tid < 64) { m_s[tid] = -1e30f; l_s[tid] = 0.0f; }

    float acc[4][4] = {};
    __syncthreads();

    const float* kbase = Kg + (size_t)(b * S_) * QKV_N + h * DH_;
    const float* vbase = Vg + (size_t)(b * S_) * QKV_N + h * DH_;

    for (int j0 = 0; j0 < S_; j0 += 64) {
        for (int idx = tid; idx < 64 * 16; idx += 256) {
            const int r = idx >> 4, c4 = (idx & 15) << 2;
            float4 kv = *(const float4*)(kbase + (size_t)(j0 + r) * QKV_N + c4);
            KsT[(c4 + 0) * APAD + r] = kv.x;
            KsT[(c4 + 1) * APAD + r] = kv.y;
            KsT[(c4 + 2) * APAD + r] = kv.z;
            KsT[(c4 + 3) * APAD + r] = kv.w;
            float4 vv = *(const float4*)(vbase + (size_t)(j0 + r) * QKV_N + c4);
            *(float4*)&Vs[r * APAD + c4] = vv;
        }
        __syncthreads();

        float s4[4][4] = {};
        #pragma unroll 16
        for (int k = 0; k < 64; k++) {
            float a4[4], b4[4];
            *(float4*)a4 = *(const float4*)&QsT[k * APAD + ty * 4];
            *(float4*)b4 = *(const float4*)&KsT[k * APAD + tx * 4];
            #pragma unroll
            for (int i = 0; i < 4; i++)
                #pragma unroll
                for (int j = 0; j < 4; j++)
                    s4[i][j] = fmaf(a4[i], b4[j], s4[i][j]);
        }
        #pragma unroll
        for (int j = 0; j < 4; j++)
            #pragma unroll
            for (int i = 0; i < 4; i++)
                PsT[(tx * 4 + j) * APAD + ty * 4 + i] = s4[i][j];
        __syncthreads();

        float mloc = -1e30f;
        #pragma unroll
        for (int c = 0; c < 16; c++)
            mloc = fmaxf(mloc, PsT[(spart * 16 + c) * APAD + srow]);
        red[tid] = mloc;
        __syncthreads();
        if (tid < 64) {
            const float mo = m_s[tid];
            float mn = fmaxf(fmaxf(red[tid], red[tid + 64]),
                             fmaxf(red[tid + 128], red[tid + 192]));
            mn = fmaxf(mn, mo);
            m2[tid]  = mn;
            a_s[tid] = __expf(mo - mn);
            m_s[tid] = mn;
        }
        __syncthreads();

        const float mn = m2[srow];
        float psum = 0.0f;
        #pragma unroll
        for (int c = 0; c < 16; c++) {
            const int off = (spart * 16 + c) * APAD + srow;
            const float p = __expf(PsT[off] - mn);
            PsT[off] = p;
            psum += p;
        }
        red[tid] = psum;
        __syncthreads();
        if (tid < 64)
            l_s[tid] = l_s[tid] * a_s[tid]
                     + red[tid] + red[tid + 64] + red[tid + 128] + red[tid + 192];

        float alpha[4];
        #pragma unroll
        for (int i = 0; i < 4; i++) alpha[i] = a_s[ty * 4 + i];
        #pragma unroll
        for (int i = 0; i < 4; i++)
            #pragma unroll
            for (int j = 0; j < 4; j++)
                acc[i][j] *= alpha[i];

        #pragma unroll 16
        for (int k = 0; k < 64; k++) {
            float p4[4], v4[4];
            *(float4*)p4 = *(const float4*)&PsT[k * APAD + ty * 4];
            *(float4*)v4 = *(const float4*)&Vs[k * APAD + tx * 4];
            #pragma unroll
            for (int i = 0; i < 4; i++)
                #pragma unroll
                for (int j = 0; j < 4; j++)
                    acc[i][j] = fmaf(p4[i], v4[j], acc[i][j]);
        }
        __syncthreads();
    }

    float linv[4];
    #pragma unroll
    for (int i = 0; i < 4; i++) linv[i] = 1.0f / l_s[ty * 4 + i];
    #pragma unroll
    for (int i = 0; i < 4; i++) {
        const float o0 = acc[i][0] * linv[i], o1 = acc[i][1] * linv[i];
        const float o2 = acc[i][2] * linv[i], o3 = acc[i][3] * linv[i];
        const size_t base = ((size_t)(b * S_) + qt * 64 + ty * 4 + i) * D_
                          + h * DH_ + tx * 4;
        const __nv_bfloat16 h0 = __float2bfloat16(o0), h1 = __float2bfloat16(o1);
        const __nv_bfloat16 h2 = __float2bfloat16(o2), h3 = __float2bfloat16(o3);
        __nv_bfloat162 hh0(h0, h1), hh1(h2, h3);
        *(uint2*)(Chi + base) = make_uint2(reinterpret_cast<uint32_t&>(hh0),
                                           reinterpret_cast<uint32_t&>(hh1));
        *(uint2*)(Clo + base) = make_uint2(
            pack_bf2(o0 - __bfloat162float(h0), o1 - __bfloat162float(h1)),
            pack_bf2(o2 - __bfloat162float(h2), o3 - __bfloat162float(h3)));
    }
}

// ---------------------------------------------------------------------------
// Launch
// ---------------------------------------------------------------------------
extern "C" void kernel_launch(void* const* d_in, const int* in_sizes, int n_in,
                              void* d_out, int out_size)
{
    (void)in_sizes; (void)n_in; (void)out_size;

    const float* hs  = (const float*)d_in[0];
    const float* Wq  = (const float*)d_in[1];
    const float* bq  = (const float*)d_in[2];
    const float* Wk  = (const float*)d_in[3];
    const float* bk  = (const float*)d_in[4];
    const float* Wv  = (const float*)d_in[5];
    const float* bv  = (const float*)d_in[6];
    const float* Wp  = (const float*)d_in[7];
    const float* bp  = (const float*)d_in[8];
    const float* g1  = (const float*)d_in[9];
    const float* be1 = (const float*)d_in[10];
    const float* W1  = (const float*)d_in[11];
    const float* b1  = (const float*)d_in[12];
    const float* W2  = (const float*)d_in[13];
    const float* b2  = (const float*)d_in[14];
    const float* g2  = (const float*)d_in[15];
    const float* be2 = (const float*)d_in[16];

    float *x, *qkv, *t, *bqkv;
    __nv_bfloat16 *xhi, *xlo, *chi, *clo, *ffhi, *fflo;
    __nv_bfloat16 *wqkvh, *wqkvl, *wph, *wpl, *w1h, *w1l, *w2h, *w2l;
    cudaGetSymbolAddress((void**)&x,    g_x);
    cudaGetSymbolAddress((void**)&qkv,  g_qkv);
    cudaGetSymbolAddress((void**)&t,    g_t);
    cudaGetSymbolAddress((void**)&bqkv, g_bqkv);
    cudaGetSymbolAddress((void**)&xhi,  g_xhi);
    cudaGetSymbolAddress((void**)&xlo,  g_xlo);
    cudaGetSymbolAddress((void**)&chi,  g_chi);
    cudaGetSymbolAddress((void**)&clo,  g_clo);
    cudaGetSymbolAddress((void**)&ffhi, g_ffhi);
    cudaGetSymbolAddress((void**)&fflo, g_fflo);
    cudaGetSymbolAddress((void**)&wqkvh, g_wqkv_hi);
    cudaGetSymbolAddress((void**)&wqkvl, g_wqkv_lo);
    cudaGetSymbolAddress((void**)&wph,  g_wp_hi);
    cudaGetSymbolAddress((void**)&wpl,  g_wp_lo);
    cudaGetSymbolAddress((void**)&w1h,  g_w1_hi);
    cudaGetSymbolAddress((void**)&w1l,  g_w1_lo);
    cudaGetSymbolAddress((void**)&w2h,  g_w2_hi);
    cudaGetSymbolAddress((void**)&w2l,  g_w2_lo);

    cudaFuncSetAttribute(gemm_mma, cudaFuncAttributeMaxDynamicSharedMemorySize,
                         GSMEM);
    cudaFuncSetAttribute(attn_kernel, cudaFuncAttributeMaxDynamicSharedMemorySize,
                         ATTN_SMEM_BYTES);

    // ---- per-replay weight preprocessing (transpose + hi/lo split) ----
    const dim3 tb(256);
    transpose_split<<<dim3(D_/32, D_/32, L_), tb>>>(
        Wq, wqkvh,                 wqkvl,                 D_, D_,
        (size_t)D_ * D_, (size_t)QKV_N * D_);
    transpose_split<<<dim3(D_/32, D_/32, L_), tb>>>(
        Wk, wqkvh + (size_t)D_*D_, wqkvl + (size_t)D_*D_, D_, D_,
        (size_t)D_ * D_, (size_t)QKV_N * D_);
    transpose_split<<<dim3(D_/32, D_/32, L_), tb>>>(
        Wv, wqkvh + (size_t)2*D_*D_, wqkvl + (size_t)2*D_*D_, D_, D_,
        (size_t)D_ * D_, (size_t)QKV_N * D_);
    transpose_split<<<dim3(D_/32, D_/32, L_), tb>>>(
        Wp, wph, wpl, D_, D_, (size_t)D_ * D_, (size_t)D_ * D_);
    transpose_split<<<dim3(FF_/32, D_/32, L_), tb>>>(
        W1, w1h, w1l, D_, FF_, (size_t)D_ * FF_, (size_t)FF_ * D_);
    transpose_split<<<dim3(D_/32, FF_/32, L_), tb>>>(
        W2, w2h, w2l, FF_, D_, (size_t)FF_ * D_, (size_t)D_ * FF_);
    concat_bias<<<(L_ * QKV_N + 255) / 256, tb>>>(bq, bk, bv, bqkv);

    // ---- initial hidden state ----
    cudaMemcpyAsync(x, hs, (size_t)MTOK * D_ * sizeof(float),
                    cudaMemcpyDeviceToDevice, 0);
    split_f32<<<(MTOK * D_ + 255) / 256, tb>>>(hs, xhi, xlo, MTOK * D_);

    const dim3 gQKV(QKV_N / 128, MTOK / 128);   // (24, 32)
    const dim3 gD  (D_    / 128, MTOK / 128);   // (8, 32)
    const dim3 gFF (FF_   / 128, MTOK / 128);   // (32, 32)
    const dim3 gA  (S_ / 64, H_, B_);

    for (int l = 0; l < L_; l++) {
        const size_t lDD = (size_t)l * D_ * D_;
        const size_t lDF = (size_t)l * D_ * FF_;

        gemm_mma<<<gQKV, tb, GSMEM>>>(
            xhi, xlo, wqkvh + (size_t)l * QKV_N * D_, wqkvl + (size_t)l * QKV_N * D_,
            bqkv + (size_t)l * QKV_N, nullptr, qkv, nullptr, nullptr,
            D_, QKV_N, 0);

        attn_kernel<<<gA, tb, ATTN_SMEM_BYTES>>>(qkv, qkv + D_, qkv + 2 * D_,
                                                 chi, clo);

        gemm_mma<<<gD, tb, GSMEM>>>(
            chi, clo, wph + lDD, wpl + lDD, bp + (size_t)l * D_, x,
            t, nullptr, nullptr, D_, D_, 0);
        ln_kernel<<<MTOK, tb>>>(t, g1 + (size_t)l * D_, be1 + (size_t)l * D_,
                                x, xhi, xlo);

        gemm_mma<<<gFF, tb, GSMEM>>>(
            xhi, xlo, w1h + lDF, w1l + lDF, b1 + (size_t)l * FF_, nullptr,
            nullptr, ffhi, fflo, D_, FF_, 1);

        gemm_mma<<<gD, tb, GSMEM>>>(
            ffhi, fflo, w2h + lDF, w2l + lDF, b2 + (size_t)l * D_, x,
            t, nullptr, nullptr, FF_, D_, 0);

        if (l == L_ - 1) {
            ln_kernel<<<MTOK, tb>>>(t, g2 + (size_t)l * D_, be2 + (size_t)l * D_,
                                    (float*)d_out, nullptr, nullptr);
        } else {
            ln_kernel<<<MTOK, tb>>>(t, g2 + (size_t)l * D_, be2 + (size_t)l * D_,
                                    x, xhi, xlo);
        }
    }
}

// round 6
// speedup vs baseline: 2.7333x; 1.5938x over previous
#include <cuda_runtime.h>
#include <cuda_bf16.h>
#include <cstdint>

// Problem constants
#define B_    2
#define S_    2048
#define D_    1024
#define FF_   4096
#define H_    16
#define DH_   64
#define L_    4
#define MTOK  (B_ * S_)      // 4096 tokens
#define QKV_N (3 * D_)       // 3072

// ---------------------------------------------------------------------------
// Scratch (static device globals; no runtime allocation)
// ---------------------------------------------------------------------------
__device__ float         g_x    [MTOK * D_];          // running hidden (fp32)
__device__ __nv_bfloat16 g_xhi  [MTOK * D_];
__device__ __nv_bfloat16 g_xlo  [MTOK * D_];
__device__ __nv_bfloat16 g_qkvhi[MTOK * QKV_N];       // fused QKV (bf16 hi/lo)
__device__ __nv_bfloat16 g_qkvlo[MTOK * QKV_N];
__device__ __nv_bfloat16 g_chi  [MTOK * D_];          // attention ctx hi/lo
__device__ __nv_bfloat16 g_clo  [MTOK * D_];
__device__ float         g_t    [MTOK * D_];          // pre-LN temp
__device__ __nv_bfloat16 g_ffhi [MTOK * FF_];
__device__ __nv_bfloat16 g_fflo [MTOK * FF_];

// transposed + hi/lo-split weights ([N, K] row-major, bf16)
__device__ __nv_bfloat16 g_wqkv_hi[L_ * QKV_N * D_];
__device__ __nv_bfloat16 g_wqkv_lo[L_ * QKV_N * D_];
__device__ __nv_bfloat16 g_wp_hi  [L_ * D_ * D_];
__device__ __nv_bfloat16 g_wp_lo  [L_ * D_ * D_];
__device__ __nv_bfloat16 g_w1_hi  [L_ * FF_ * D_];    // [FF, D]
__device__ __nv_bfloat16 g_w1_lo  [L_ * FF_ * D_];
__device__ __nv_bfloat16 g_w2_hi  [L_ * D_ * FF_];    // [D, FF]
__device__ __nv_bfloat16 g_w2_lo  [L_ * D_ * FF_];
__device__ float         g_bqkv  [L_ * QKV_N];

// ---------------------------------------------------------------------------
// Baseline-PTX helpers (sm_75/80 features only)
// ---------------------------------------------------------------------------
__device__ __forceinline__ uint32_t smem_u32(const void* p) {
    uint32_t a;
    asm("{ .reg .u64 t; cvta.to.shared.u64 t, %1; cvt.u32.u64 %0, t; }"
        : "=r"(a) : "l"(p));
    return a;
}
__device__ __forceinline__ void cp16(uint32_t s, const void* g) {
    asm volatile("cp.async.cg.shared.global [%0], [%1], 16;" :: "r"(s), "l"(g));
}
#define CP_COMMIT() asm volatile("cp.async.commit_group;" ::: "memory")
#define CP_WAIT(n)  asm volatile("cp.async.wait_group %0;" :: "n"(n) : "memory")

__device__ __forceinline__ void ldsm4(uint32_t r[4], uint32_t addr) {
    asm volatile("ldmatrix.sync.aligned.m8n8.x4.shared.b16 {%0,%1,%2,%3}, [%4];"
        : "=r"(r[0]), "=r"(r[1]), "=r"(r[2]), "=r"(r[3]) : "r"(addr));
}
__device__ __forceinline__ void ldsm4t(uint32_t r[4], uint32_t addr) {
    asm volatile("ldmatrix.sync.aligned.m8n8.x4.trans.shared.b16 {%0,%1,%2,%3}, [%4];"
        : "=r"(r[0]), "=r"(r[1]), "=r"(r[2]), "=r"(r[3]) : "r"(addr));
}
__device__ __forceinline__ void mma16816(float c[4], const uint32_t a[4],
                                         const uint32_t b[2]) {
    asm volatile(
        "mma.sync.aligned.m16n8k16.row.col.f32.bf16.bf16.f32 "
        "{%0,%1,%2,%3}, {%4,%5,%6,%7}, {%8,%9}, {%0,%1,%2,%3};"
        : "+f"(c[0]), "+f"(c[1]), "+f"(c[2]), "+f"(c[3])
        : "r"(a[0]), "r"(a[1]), "r"(a[2]), "r"(a[3]),
          "r"(b[0]), "r"(b[1]));
}
__device__ __forceinline__ uint32_t pack_bf2(float a, float b) {
    __nv_bfloat162 t(__float2bfloat16(a), __float2bfloat16(b));
    return reinterpret_cast<uint32_t&>(t);
}

// ---------------------------------------------------------------------------
// mma.sync bf16 GEMM:  C[M,N] = (Ahi+Alo)[M,K] @ (Bhi+Blo)[N,K]^T + bias
//                      (+ residual) (+ relu); outputs fp32 and/or bf16 hi/lo.
// Block 128x128, 8 warps (2x4 -> warp tile 64x32), K-stage 32.
// smem row (per matrix, per stage): 128B = [hi 4x16B | lo 4x16B], 8-chunk XOR
// swizzle (ch ^ (r&7)) -> conflict-free ldmatrix. A array 16KB, B 16KB.
// Double-buffered; cp.async; ldmatrix fragments; 3-pass hi/lo mma.
// ---------------------------------------------------------------------------
#define GSTAGE  32768
#define GSMEM   (2 * GSTAGE)   // 65536

__device__ __forceinline__ void gemm_load_stage(
    uint32_t sbase, const __nv_bfloat16* __restrict__ Ahi,
    const __nv_bfloat16* __restrict__ Alo,
    const __nv_bfloat16* __restrict__ Bhi,
    const __nv_bfloat16* __restrict__ Blo,
    int m0, int n0, int K, int k0, int tid)
{
    #pragma unroll
    for (int i = 0; i < 8; i++) {
        const int task = tid + i * 256;          // 2048 chunk tasks
        const int arr = task >> 10;              // 0=A, 1=B
        const int r = (task >> 3) & 127;
        const int ch = task & 7;
        const uint32_t dst = sbase + arr * 16384 + r * 128
                           + (uint32_t)((ch ^ (r & 7)) << 4);
        const __nv_bfloat16* src;
        if (arr == 0)
            src = (ch < 4) ? Ahi + (size_t)(m0 + r) * K + k0 + ch * 8
                           : Alo + (size_t)(m0 + r) * K + k0 + (ch - 4) * 8;
        else
            src = (ch < 4) ? Bhi + (size_t)(n0 + r) * K + k0 + ch * 8
                           : Blo + (size_t)(n0 + r) * K + k0 + (ch - 4) * 8;
        cp16(dst, src);
    }
}

__global__ void __launch_bounds__(256) gemm_mma(
    const __nv_bfloat16* __restrict__ Ahi, const __nv_bfloat16* __restrict__ Alo,
    const __nv_bfloat16* __restrict__ Bhi, const __nv_bfloat16* __restrict__ Blo,
    const float* __restrict__ bias, const float* __restrict__ Rsd,
    float* __restrict__ Cf,
    __nv_bfloat16* __restrict__ Chi, __nv_bfloat16* __restrict__ Clo,
    int K, int N, int relu)
{
    extern __shared__ char sm[];
    const uint32_t smb = smem_u32(sm);
    const int tid = threadIdx.x;
    const int wid = tid >> 5, lane = tid & 31;
    const int wm = wid >> 2, wn = wid & 3;          // warp grid 2x4
    const int lq = lane >> 2, lr = lane & 3;
    const int m0 = blockIdx.y * 128, n0 = blockIdx.x * 128;

    float acc[4][4][4];
    #pragma unroll
    for (int i = 0; i < 4; i++)
        #pragma unroll
        for (int j = 0; j < 4; j++)
            #pragma unroll
            for (int k = 0; k < 4; k++) acc[i][j][k] = 0.0f;

    const int NS = K / 32;

    gemm_load_stage(smb, Ahi, Alo, Bhi, Blo, m0, n0, K, 0, tid);
    CP_COMMIT();

    // ldmatrix lane-address components (constant per thread)
    const int a_rl = ((lane >> 3) & 1) * 8 + (lane & 7);  // A: g&1 row grp
    const int a_cg = (lane >> 4) & 1;                     // A: g>>1 k-chunk
    const int b_rl = ((lane >> 4) & 1) * 8 + (lane & 7);  // B: g>>1 row grp
    const int b_cg = (lane >> 3) & 1;                     // B: g&1 k-chunk

    for (int s = 0; s < NS; s++) {
        if (s + 1 < NS) {
            gemm_load_stage(smb + ((s + 1) & 1) * GSTAGE,
                            Ahi, Alo, Bhi, Blo, m0, n0, K, (s + 1) * 32, tid);
            CP_COMMIT();
            CP_WAIT(1);
        } else {
            CP_WAIT(0);
        }
        __syncthreads();

        const uint32_t sA = smb + (s & 1) * GSTAGE;
        const uint32_t sB = sA + 16384;

        #pragma unroll
        for (int kk = 0; kk < 2; kk++) {
            uint32_t ah[4][4], al[4][4];
            #pragma unroll
            for (int mt = 0; mt < 4; mt++) {
                const int row = wm * 64 + mt * 16 + a_rl;
                const int chh = a_cg + 2 * kk;
                ldsm4(ah[mt], sA + row * 128 + (((chh)     ^ (row & 7)) << 4));
                ldsm4(al[mt], sA + row * 128 + (((chh + 4) ^ (row & 7)) << 4));
            }
            uint32_t bh[4][2], bl[4][2];
            #pragma unroll
            for (int u = 0; u < 2; u++) {
                const int row = wn * 32 + u * 16 + b_rl;
                const int chh = 2 * kk + b_cg;
                uint32_t t4[4];
                ldsm4(t4, sB + row * 128 + (((chh) ^ (row & 7)) << 4));
                bh[2*u][0] = t4[0]; bh[2*u][1] = t4[1];
                bh[2*u+1][0] = t4[2]; bh[2*u+1][1] = t4[3];
                ldsm4(t4, sB + row * 128 + (((chh + 4) ^ (row & 7)) << 4));
                bl[2*u][0] = t4[0]; bl[2*u][1] = t4[1];
                bl[2*u+1][0] = t4[2]; bl[2*u+1][1] = t4[3];
            }
            #pragma unroll
            for (int mt = 0; mt < 4; mt++)
                #pragma unroll
                for (int nt = 0; nt < 4; nt++) {
                    mma16816(acc[mt][nt], ah[mt], bh[nt]);   // hi*hi
                    mma16816(acc[mt][nt], ah[mt], bl[nt]);   // hi*lo
                    mma16816(acc[mt][nt], al[mt], bh[nt]);   // lo*hi
                }
        }
        __syncthreads();
    }

    // Epilogue (fragment layout: c0,c1 at (lq, 2lr), c2,c3 at (lq+8, 2lr))
    const int row0 = m0 + wm * 64;
    const int col0 = n0 + wn * 32;
    #pragma unroll
    for (int mt = 0; mt < 4; mt++) {
        #pragma unroll
        for (int nt = 0; nt < 4; nt++) {
            const int c = col0 + nt * 8 + lr * 2;
            const float b0 = bias[c], b1 = bias[c + 1];
            #pragma unroll
            for (int h = 0; h < 2; h++) {
                const int r = row0 + mt * 16 + lq + h * 8;
                float v0 = acc[mt][nt][2 * h]     + b0;
                float v1 = acc[mt][nt][2 * h + 1] + b1;
                const size_t o = (size_t)r * N + c;
                if (Rsd) {
                    const float2 rv = *(const float2*)(Rsd + o);
                    v0 += rv.x; v1 += rv.y;
                }
                if (relu) { v0 = fmaxf(v0, 0.0f); v1 = fmaxf(v1, 0.0f); }
                if (Cf) *(float2*)(Cf + o) = make_float2(v0, v1);
                if (Chi) {
                    const __nv_bfloat16 h0 = __float2bfloat16(v0);
                    const __nv_bfloat16 h1 = __float2bfloat16(v1);
                    __nv_bfloat162 hh(h0, h1);
                    *(uint32_t*)(Chi + o) = reinterpret_cast<uint32_t&>(hh);
                    *(uint32_t*)(Clo + o) = pack_bf2(v0 - __bfloat162float(h0),
                                                     v1 - __bfloat162float(h1));
                }
            }
        }
    }
}

// ---------------------------------------------------------------------------
// FA2-style attention, mma.sync bf16 3-pass hi/lo on QK^T and PV.
// Block: 128 q-rows, 8 warps (16 rows each), Bc=64 keys/tile, DH=64.
// smem: Qhi/Qlo 16KB each + 2 stages x (Khi,Klo,Vhi,Vlo @ 8KB) = 96KB.
// Rows 128B, 8-chunk XOR swizzle. Grid: (S/128, H, B), 256 threads.
// ---------------------------------------------------------------------------
#define AQ_HI  0
#define AQ_LO  16384
#define A_STG  32768
#define A_SSZ  32768
#define A_KHI  0
#define A_KLO  8192
#define A_VHI  16384
#define A_VLO  24576
#define ATTN_SMEM (A_STG + 2 * A_SSZ)   // 98304

__device__ __forceinline__ void attn_load_kv(
    uint32_t sbase, const __nv_bfloat16* __restrict__ Qhi,
    const __nv_bfloat16* __restrict__ Qlo,
    size_t krow0, int hcol, int tid)
{
    // 4 arrays x 64 rows x 8 chunks = 2048 tasks
    #pragma unroll
    for (int i = 0; i < 8; i++) {
        const int task = tid + i * 256;
        const int arr = task >> 9;               // 0 Khi,1 Klo,2 Vhi,3 Vlo
        const int r = (task >> 3) & 63;
        const int ch = task & 7;
        const uint32_t dst = sbase + arr * 8192 + r * 128
                           + (uint32_t)((ch ^ (r & 7)) << 4);
        const int col = ((arr >> 1) ? 2 * D_ : D_) + hcol + ch * 8;
        const __nv_bfloat16* base = (arr & 1) ? Qlo : Qhi;
        cp16(dst, base + (krow0 + r) * QKV_N + col);
    }
}

__global__ void __launch_bounds__(256) attn_mma(
    const __nv_bfloat16* __restrict__ QKVhi,
    const __nv_bfloat16* __restrict__ QKVlo,
    __nv_bfloat16* __restrict__ Chi, __nv_bfloat16* __restrict__ Clo)
{
    extern __shared__ char sm[];
    const uint32_t smb = smem_u32(sm);
    const int tid = threadIdx.x;
    const int w = tid >> 5, lane = tid & 31;
    const int lq = lane >> 2, lr = lane & 3;
    const int qt = blockIdx.x, h = blockIdx.y, b = blockIdx.z;
    const size_t qrow0 = (size_t)b * S_ + qt * 128;
    const size_t krowb = (size_t)b * S_;
    const int hcol = h * DH_;

    // ---- load Q tile (hi/lo): 2 arrays x 128 rows x 8 chunks = 2048 tasks
    #pragma unroll
    for (int i = 0; i < 8; i++) {
        const int task = tid + i * 256;
        const int arr = task >> 10;
        const int r = (task >> 3) & 127;
        const int ch = task & 7;
        const uint32_t dst = smb + arr * 16384 + r * 128
                           + (uint32_t)((ch ^ (r & 7)) << 4);
        const __nv_bfloat16* base = arr ? QKVlo : QKVhi;
        cp16(dst, base + (qrow0 + r) * QKV_N + hcol + ch * 8);
    }
    attn_load_kv(smb + A_STG, QKVhi, QKVlo, krowb, hcol, tid);
    CP_COMMIT();

    float m0 = -1e30f, m1 = -1e30f, l0 = 0.0f, l1 = 0.0f;
    float oacc[8][4];
    #pragma unroll
    for (int t = 0; t < 8; t++)
        #pragma unroll
        for (int i = 0; i < 4; i++) oacc[t][i] = 0.0f;

    uint32_t qh[4][4], ql[4][4];

    // ldmatrix lane components
    const int a_rl = ((lane >> 3) & 1) * 8 + (lane & 7);  // row grp = g&1
    const int a_cg = (lane >> 4) & 1;                     // k-chunk = g>>1
    const int b_rl = ((lane >> 4) & 1) * 8 + (lane & 7);  // row grp = g>>1
    const int b_cg = (lane >> 3) & 1;                     // k-chunk = g&1

    const int NT = S_ / 64;   // 32 key tiles
    for (int j = 0; j < NT; j++) {
        if (j + 1 < NT) {
            attn_load_kv(smb + A_STG + ((j + 1) & 1) * A_SSZ,
                         QKVhi, QKVlo, krowb + (size_t)(j + 1) * 64, hcol, tid);
            CP_COMMIT();
            CP_WAIT(1);
        } else {
            CP_WAIT(0);
        }
        __syncthreads();

        if (j == 0) {
            // load Q fragments once; fold in softmax scale 1/8 (exact)
            const __nv_bfloat162 s2 = __float2bfloat162_rn(0.125f);
            #pragma unroll
            for (int kk = 0; kk < 4; kk++) {
                const int row = w * 16 + a_rl;
                const int chh = a_cg + 2 * kk;
                ldsm4(qh[kk], smb + AQ_HI + row * 128 + ((chh ^ (row & 7)) << 4));
                ldsm4(ql[kk], smb + AQ_LO + row * 128 + ((chh ^ (row & 7)) << 4));
                #pragma unroll
                for (int i = 0; i < 4; i++) {
                    __nv_bfloat162 vh = reinterpret_cast<__nv_bfloat162&>(qh[kk][i]);
                    vh = __hmul2(vh, s2);
                    qh[kk][i] = reinterpret_cast<uint32_t&>(vh);
                    __nv_bfloat162 vl = reinterpret_cast<__nv_bfloat162&>(ql[kk][i]);
                    vl = __hmul2(vl, s2);
                    ql[kk][i] = reinterpret_cast<uint32_t&>(vl);
                }
            }
        }

        const uint32_t sK = smb + A_STG + (j & 1) * A_SSZ;
        const uint32_t sV = sK + A_VHI;

        // ---- S = Q @ K^T (3-pass) : S tile 16x64 per warp
        float sacc[8][4];
        #pragma unroll
        for (int t = 0; t < 8; t++)
            #pragma unroll
            for (int i = 0; i < 4; i++) sacc[t][i] = 0.0f;

        #pragma unroll
        for (int kk = 0; kk < 4; kk++) {
            uint32_t kh[8][2], kl[8][2];
            #pragma unroll
            for (int u = 0; u < 4; u++) {
                const int row = u * 16 + b_rl;      // key index
                const int chh = 2 * kk + b_cg;      // d chunk
                uint32_t t4[4];
                ldsm4(t4, sK + A_KHI + row * 128 + ((chh ^ (row & 7)) << 4));
                kh[2*u][0] = t4[0]; kh[2*u][1] = t4[1];
                kh[2*u+1][0] = t4[2]; kh[2*u+1][1] = t4[3];
                ldsm4(t4, sK + A_KLO + row * 128 + ((chh ^ (row & 7)) << 4));
                kl[2*u][0] = t4[0]; kl[2*u][1] = t4[1];
                kl[2*u+1][0] = t4[2]; kl[2*u+1][1] = t4[3];
            }
            #pragma unroll
            for (int t = 0; t < 8; t++) {
                mma16816(sacc[t], qh[kk], kh[t]);
                mma16816(sacc[t], qh[kk], kl[t]);
                mma16816(sacc[t], ql[kk], kh[t]);
            }
        }

        // ---- online softmax (rows lq and lq+8; quad lanes share a row)
        float mx0 = -1e30f, mx1 = -1e30f;
        #pragma unroll
        for (int t = 0; t < 8; t++) {
            mx0 = fmaxf(mx0, fmaxf(sacc[t][0], sacc[t][1]));
            mx1 = fmaxf(mx1, fmaxf(sacc[t][2], sacc[t][3]));
        }
        mx0 = fmaxf(mx0, __shfl_xor_sync(0xffffffffu, mx0, 1));
        mx0 = fmaxf(mx0, __shfl_xor_sync(0xffffffffu, mx0, 2));
        mx1 = fmaxf(mx1, __shfl_xor_sync(0xffffffffu, mx1, 1));
        mx1 = fmaxf(mx1, __shfl_xor_sync(0xffffffffu, mx1, 2));
        const float nm0 = fmaxf(m0, mx0), nm1 = fmaxf(m1, mx1);
        const float al0 = __expf(m0 - nm0), al1 = __expf(m1 - nm1);
        m0 = nm0; m1 = nm1;

        float ps0 = 0.0f, ps1 = 0.0f;
        #pragma unroll
        for (int t = 0; t < 8; t++) {
            sacc[t][0] = __expf(sacc[t][0] - m0);
            sacc[t][1] = __expf(sacc[t][1] - m0);
            sacc[t][2] = __expf(sacc[t][2] - m1);
            sacc[t][3] = __expf(sacc[t][3] - m1);
            ps0 += sacc[t][0] + sacc[t][1];
            ps1 += sacc[t][2] + sacc[t][3];
        }
        ps0 += __shfl_xor_sync(0xffffffffu, ps0, 1);
        ps0 += __shfl_xor_sync(0xffffffffu, ps0, 2);
        ps1 += __shfl_xor_sync(0xffffffffu, ps1, 1);
        ps1 += __shfl_xor_sync(0xffffffffu, ps1, 2);
        l0 = l0 * al0 + ps0;
        l1 = l1 * al1 + ps1;

        #pragma unroll
        for (int t = 0; t < 8; t++) {
            oacc[t][0] *= al0; oacc[t][1] *= al0;
            oacc[t][2] *= al1; oacc[t][3] *= al1;
        }

        // ---- P -> bf16 hi/lo A-fragments (C-layout -> A-layout identity)
        uint32_t ph[4][4], pl[4][4];
        #pragma unroll
        for (int kk = 0; kk < 4; kk++) {
            const int t0 = 2 * kk, t1 = 2 * kk + 1;
            const float p[8] = { sacc[t0][0], sacc[t0][1], sacc[t0][2], sacc[t0][3],
                                 sacc[t1][0], sacc[t1][1], sacc[t1][2], sacc[t1][3] };
            float hi[8];
            #pragma unroll
            for (int i = 0; i < 8; i++)
                hi[i] = __bfloat162float(__float2bfloat16(p[i]));
            ph[kk][0] = pack_bf2(p[0], p[1]);
            ph[kk][1] = pack_bf2(p[2], p[3]);
            ph[kk][2] = pack_bf2(p[4], p[5]);
            ph[kk][3] = pack_bf2(p[6], p[7]);
            pl[kk][0] = pack_bf2(p[0] - hi[0], p[1] - hi[1]);
            pl[kk][1] = pack_bf2(p[2] - hi[2], p[3] - hi[3]);
            pl[kk][2] = pack_bf2(p[4] - hi[4], p[5] - hi[5]);
            pl[kk][3] = pack_bf2(p[6] - hi[6], p[7] - hi[7]);
        }

        // ---- O += P @ V (3-pass); V^T fragments via ldmatrix.trans
        #pragma unroll
        for (int kk = 0; kk < 4; kk++) {           // key window 16*kk
            uint32_t vh[8][2], vl[8][2];
            #pragma unroll
            for (int u = 0; u < 4; u++) {
                const int row = 16 * kk + a_rl;    // key row (g&1 grp)
                const int chh = 2 * u + a_cg;      // d chunk (g>>1)
                uint32_t t4[4];
                ldsm4t(t4, sV + 0    + row * 128 + ((chh ^ (row & 7)) << 4));
                vh[2*u][0] = t4[0]; vh[2*u][1] = t4[1];
                vh[2*u+1][0] = t4[2]; vh[2*u+1][1] = t4[3];
                ldsm4t(t4, sV + 8192 + row * 128 + ((chh ^ (row & 7)) << 4));
                vl[2*u][0] = t4[0]; vl[2*u][1] = t4[1];
                vl[2*u+1][0] = t4[2]; vl[2*u+1][1] = t4[3];
            }
            #pragma unroll
            for (int t = 0; t < 8; t++) {
                mma16816(oacc[t], ph[kk], vh[t]);
                mma16816(oacc[t], ph[kk], vl[t]);
                mma16816(oacc[t], pl[kk], vh[t]);
            }
        }
        __syncthreads();
    }

    // ---- epilogue: O /= l, write ctx bf16 hi/lo
    const float i0 = 1.0f / l0, i1 = 1.0f / l1;
    const size_t r0g = qrow0 + w * 16 + lq;
    #pragma unroll
    for (int t = 0; t < 8; t++) {
        const int col = hcol + t * 8 + 2 * lr;
        const float v0 = oacc[t][0] * i0, v1 = oacc[t][1] * i0;
        const float v2 = oacc[t][2] * i1, v3 = oacc[t][3] * i1;
        const __nv_bfloat16 h0 = __float2bfloat16(v0), h1 = __float2bfloat16(v1);
        const __nv_bfloat16 h2 = __float2bfloat16(v2), h3 = __float2bfloat16(v3);
        __nv_bfloat162 a(h0, h1), c(h2, h3);
        *(uint32_t*)(Chi + r0g * D_ + col) = reinterpret_cast<uint32_t&>(a);
        *(uint32_t*)(Clo + r0g * D_ + col) =
            pack_bf2(v0 - __bfloat162float(h0), v1 - __bfloat162float(h1));
        *(uint32_t*)(Chi + (r0g + 8) * D_ + col) = reinterpret_cast<uint32_t&>(c);
        *(uint32_t*)(Clo + (r0g + 8) * D_ + col) =
            pack_bf2(v2 - __bfloat162float(h2), v3 - __bfloat162float(h3));
    }
}

// ---------------------------------------------------------------------------
// Weight transpose + hi/lo split: W fp32 [K,N] -> Ohi/Olo bf16 [N,K]
// ---------------------------------------------------------------------------
__global__ void __launch_bounds__(256) transpose_split(
    const float* __restrict__ W, __nv_bfloat16* __restrict__ Ohi,
    __nv_bfloat16* __restrict__ Olo, int K, int N,
    size_t in_lstride, size_t out_lstride)
{
    __shared__ float t[32][33];
    const int l = blockIdx.z;
    const float* Wl = W + (size_t)l * in_lstride;
    __nv_bfloat16* Hl = Ohi + (size_t)l * out_lstride;
    __nv_bfloat16* Ll = Olo + (size_t)l * out_lstride;
    const int k0 = blockIdx.y * 32, n0 = blockIdx.x * 32;
    const int tx = threadIdx.x & 31, ty = threadIdx.x >> 5;
    #pragma unroll
    for (int i = 0; i < 32; i += 8)
        t[ty + i][tx] = Wl[(size_t)(k0 + ty + i) * N + n0 + tx];
    __syncthreads();
    #pragma unroll
    for (int i = 0; i < 32; i += 8) {
        const float v = t[tx][ty + i];
        const __nv_bfloat16 h = __float2bfloat16(v);
        const size_t o = (size_t)(n0 + ty + i) * K + k0 + tx;
        Hl[o] = h;
        Ll[o] = __float2bfloat16(v - __bfloat162float(h));
    }
}

__global__ void concat_bias(const float* __restrict__ bq, const float* __restrict__ bk,
                            const float* __restrict__ bv, float* __restrict__ out)
{
    const int i = blockIdx.x * 256 + threadIdx.x;
    if (i >= L_ * QKV_N) return;
    const int l = i / QKV_N, j = i % QKV_N;
    float v;
    if (j < D_)            v = bq[l * D_ + j];
    else if (j < 2 * D_)   v = bk[l * D_ + j - D_];
    else                   v = bv[l * D_ + j - 2 * D_];
    out[i] = v;
}

__global__ void split_f32(const float* __restrict__ in,
                          __nv_bfloat16* __restrict__ hi,
                          __nv_bfloat16* __restrict__ lo, int n)
{
    const int i = blockIdx.x * 256 + threadIdx.x;
    if (i >= n) return;
    const float v = in[i];
    const __nv_bfloat16 h = __float2bfloat16(v);
    hi[i] = h;
    lo[i] = __float2bfloat16(v - __bfloat162float(h));
}

// ---------------------------------------------------------------------------
// LayerNorm over last dim (D=1024); fused fp32 + optional bf16 hi/lo output.
// ---------------------------------------------------------------------------
__inline__ __device__ float warpSum(float v) {
    #pragma unroll
    for (int o = 16; o > 0; o >>= 1) v += __shfl_xor_sync(0xffffffffu, v, o);
    return v;
}

__global__ void __launch_bounds__(256) ln_kernel(
    const float* __restrict__ in, const float* __restrict__ gamma,
    const float* __restrict__ beta, float* __restrict__ out,
    __nv_bfloat16* __restrict__ ohi, __nv_bfloat16* __restrict__ olo)
{
    const size_t row = blockIdx.x;
    const float4 val = ((const float4*)(in + row * D_))[threadIdx.x];

    float s  = val.x + val.y + val.z + val.w;
    float sq = val.x * val.x + val.y * val.y + val.z * val.z + val.w * val.w;

    __shared__ float ssum[8], ssq[8];
    s  = warpSum(s);
    sq = warpSum(sq);
    const int wid = threadIdx.x >> 5, lane = threadIdx.x & 31;
    if (lane == 0) { ssum[wid] = s; ssq[wid] = sq; }
    __syncthreads();
    s = 0.f; sq = 0.f;
    #pragma unroll
    for (int i = 0; i < 8; i++) { s += ssum[i]; sq += ssq[i]; }

    const float mean = s * (1.0f / D_);
    const float var  = sq * (1.0f / D_) - mean * mean;
    const float rstd = rsqrtf(var + 1e-6f);

    const int c = threadIdx.x << 2;
    const float4 gv = *(const float4*)(gamma + c);
    const float4 bb = *(const float4*)(beta + c);
    float4 o;
    o.x = (val.x - mean) * rstd * gv.x + bb.x;
    o.y = (val.y - mean) * rstd * gv.y + bb.y;
    o.z = (val.z - mean) * rstd * gv.z + bb.z;
    o.w = (val.w - mean) * rstd * gv.w + bb.w;
    ((float4*)(out + row * D_))[threadIdx.x] = o;

    if (ohi) {
        const __nv_bfloat16 h0 = __float2bfloat16(o.x), h1 = __float2bfloat16(o.y);
        const __nv_bfloat16 h2 = __float2bfloat16(o.z), h3 = __float2bfloat16(o.w);
        __nv_bfloat162 hh0(h0, h1), hh1(h2, h3);
        *(uint2*)(ohi + row * D_ + c) =
            make_uint2(reinterpret_cast<uint32_t&>(hh0),
                       reinterpret_cast<uint32_t&>(hh1));
        *(uint2*)(olo + row * D_ + c) = make_uint2(
            pack_bf2(o.x - __bfloat162float(h0), o.y - __bfloat162float(h1)),
            pack_bf2(o.z - __bfloat162float(h2), o.w - __bfloat162float(h3)));
    }
}

// ---------------------------------------------------------------------------
// Launch
// ---------------------------------------------------------------------------
extern "C" void kernel_launch(void* const* d_in, const int* in_sizes, int n_in,
                              void* d_out, int out_size)
{
    (void)in_sizes; (void)n_in; (void)out_size;

    const float* hs  = (const float*)d_in[0];
    const float* Wq  = (const float*)d_in[1];
    const float* bq  = (const float*)d_in[2];
    const float* Wk  = (const float*)d_in[3];
    const float* bk  = (const float*)d_in[4];
    const float* Wv  = (const float*)d_in[5];
    const float* bv  = (const float*)d_in[6];
    const float* Wp  = (const float*)d_in[7];
    const float* bp  = (const float*)d_in[8];
    const float* g1  = (const float*)d_in[9];
    const float* be1 = (const float*)d_in[10];
    const float* W1  = (const float*)d_in[11];
    const float* b1  = (const float*)d_in[12];
    const float* W2  = (const float*)d_in[13];
    const float* b2  = (const float*)d_in[14];
    const float* g2  = (const float*)d_in[15];
    const float* be2 = (const float*)d_in[16];

    float *x, *t, *bqkv;
    __nv_bfloat16 *xhi, *xlo, *qkvhi, *qkvlo, *chi, *clo, *ffhi, *fflo;
    __nv_bfloat16 *wqkvh, *wqkvl, *wph, *wpl, *w1h, *w1l, *w2h, *w2l;
    cudaGetSymbolAddress((void**)&x,     g_x);
    cudaGetSymbolAddress((void**)&t,     g_t);
    cudaGetSymbolAddress((void**)&bqkv,  g_bqkv);
    cudaGetSymbolAddress((void**)&xhi,   g_xhi);
    cudaGetSymbolAddress((void**)&xlo,   g_xlo);
    cudaGetSymbolAddress((void**)&qkvhi, g_qkvhi);
    cudaGetSymbolAddress((void**)&qkvlo, g_qkvlo);
    cudaGetSymbolAddress((void**)&chi,   g_chi);
    cudaGetSymbolAddress((void**)&clo,   g_clo);
    cudaGetSymbolAddress((void**)&ffhi,  g_ffhi);
    cudaGetSymbolAddress((void**)&fflo,  g_fflo);
    cudaGetSymbolAddress((void**)&wqkvh, g_wqkv_hi);
    cudaGetSymbolAddress((void**)&wqkvl, g_wqkv_lo);
    cudaGetSymbolAddress((void**)&wph,   g_wp_hi);
    cudaGetSymbolAddress((void**)&wpl,   g_wp_lo);
    cudaGetSymbolAddress((void**)&w1h,   g_w1_hi);
    cudaGetSymbolAddress((void**)&w1l,   g_w1_lo);
    cudaGetSymbolAddress((void**)&w2h,   g_w2_hi);
    cudaGetSymbolAddress((void**)&w2l,   g_w2_lo);

    cudaFuncSetAttribute(gemm_mma, cudaFuncAttributeMaxDynamicSharedMemorySize,
                         GSMEM);
    cudaFuncSetAttribute(attn_mma, cudaFuncAttributeMaxDynamicSharedMemorySize,
                         ATTN_SMEM);

    // ---- per-replay weight preprocessing (transpose + hi/lo split) ----
    const dim3 tb(256);
    transpose_split<<<dim3(D_/32, D_/32, L_), tb>>>(
        Wq, wqkvh,                 wqkvl,                 D_, D_,
        (size_t)D_ * D_, (size_t)QKV_N * D_);
    transpose_split<<<dim3(D_/32, D_/32, L_), tb>>>(
        Wk, wqkvh + (size_t)D_*D_, wqkvl + (size_t)D_*D_, D_, D_,
        (size_t)D_ * D_, (size_t)QKV_N * D_);
    transpose_split<<<dim3(D_/32, D_/32, L_), tb>>>(
        Wv, wqkvh + (size_t)2*D_*D_, wqkvl + (size_t)2*D_*D_, D_, D_,
        (size_t)D_ * D_, (size_t)QKV_N * D_);
    transpose_split<<<dim3(D_/32, D_/32, L_), tb>>>(
        Wp, wph, wpl, D_, D_, (size_t)D_ * D_, (size_t)D_ * D_);
    transpose_split<<<dim3(FF_/32, D_/32, L_), tb>>>(
        W1, w1h, w1l, D_, FF_, (size_t)D_ * FF_, (size_t)FF_ * D_);
    transpose_split<<<dim3(D_/32, FF_/32, L_), tb>>>(
        W2, w2h, w2l, FF_, D_, (size_t)FF_ * D_, (size_t)D_ * FF_);
    concat_bias<<<(L_ * QKV_N + 255) / 256, tb>>>(bq, bk, bv, bqkv);

    // ---- initial hidden state ----
    cudaMemcpyAsync(x, hs, (size_t)MTOK * D_ * sizeof(float),
                    cudaMemcpyDeviceToDevice, 0);
    split_f32<<<(MTOK * D_ + 255) / 256, tb>>>(hs, xhi, xlo, MTOK * D_);

    const dim3 gQKV(QKV_N / 128, MTOK / 128);   // (24, 32)
    const dim3 gD  (D_    / 128, MTOK / 128);   // (8, 32)
    const dim3 gFF (FF_   / 128, MTOK / 128);   // (32, 32)
    const dim3 gA  (S_ / 128, H_, B_);          // (16, 16, 2)

    for (int l = 0; l < L_; l++) {
        const size_t lDD = (size_t)l * D_ * D_;
        const size_t lDF = (size_t)l * D_ * FF_;

        gemm_mma<<<gQKV, tb, GSMEM>>>(
            xhi, xlo, wqkvh + (size_t)l * QKV_N * D_, wqkvl + (size_t)l * QKV_N * D_,
            bqkv + (size_t)l * QKV_N, nullptr, nullptr, qkvhi, qkvlo,
            D_, QKV_N, 0);

        attn_mma<<<gA, tb, ATTN_SMEM>>>(qkvhi, qkvlo, chi, clo);

        gemm_mma<<<gD, tb, GSMEM>>>(
            chi, clo, wph + lDD, wpl + lDD, bp + (size_t)l * D_, x,
            t, nullptr, nullptr, D_, D_, 0);
        ln_kernel<<<MTOK, tb>>>(t, g1 + (size_t)l * D_, be1 + (size_t)l * D_,
                                x, xhi, xlo);

        gemm_mma<<<gFF, tb, GSMEM>>>(
            xhi, xlo, w1h + lDF, w1l + lDF, b1 + (size_t)l * FF_, nullptr,
            nullptr, ffhi, fflo, D_, FF_, 1);

        gemm_mma<<<gD, tb, GSMEM>>>(
            ffhi, fflo, w2h + lDF, w2l + lDF, b2 + (size_t)l * D_, x,
            t, nullptr, nullptr, FF_, D_, 0);

        if (l == L_ - 1) {
            ln_kernel<<<MTOK, tb>>>(t, g2 + (size_t)l * D_, be2 + (size_t)l * D_,
                                    (float*)d_out, nullptr, nullptr);
        } else {
            ln_kernel<<<MTOK, tb>>>(t, g2 + (size_t)l * D_, be2 + (size_t)l * D_,
                                    x, xhi, xlo);
        }
    }
}

// round 8
// speedup vs baseline: 2.9643x; 1.0845x over previous
#include <cuda_runtime.h>
#include <cuda_bf16.h>
#include <cstdint>

// Problem constants
#define B_    2
#define S_    2048
#define D_    1024
#define FF_   4096
#define H_    16
#define DH_   64
#define L_    4
#define MTOK  (B_ * S_)      // 4096 tokens
#define QKV_N (3 * D_)       // 3072

// ---------------------------------------------------------------------------
// Scratch (static device globals; no runtime allocation)
// ---------------------------------------------------------------------------
__device__ float         g_x    [MTOK * D_];          // running hidden (fp32)
__device__ __nv_bfloat16 g_xhi  [MTOK * D_];
__device__ __nv_bfloat16 g_xlo  [MTOK * D_];
__device__ __nv_bfloat16 g_qkvhi[MTOK * QKV_N];       // fused QKV (bf16 hi/lo)
__device__ __nv_bfloat16 g_qkvlo[MTOK * QKV_N];
__device__ __nv_bfloat16 g_chi  [MTOK * D_];          // attention ctx hi/lo
__device__ __nv_bfloat16 g_clo  [MTOK * D_];
__device__ float         g_t    [MTOK * D_];          // pre-LN temp
__device__ __nv_bfloat16 g_ffhi [MTOK * FF_];
__device__ __nv_bfloat16 g_fflo [MTOK * FF_];

// transposed + hi/lo-split weights ([N, K] row-major, bf16)
__device__ __nv_bfloat16 g_wqkv_hi[L_ * QKV_N * D_];
__device__ __nv_bfloat16 g_wqkv_lo[L_ * QKV_N * D_];
__device__ __nv_bfloat16 g_wp_hi  [L_ * D_ * D_];
__device__ __nv_bfloat16 g_wp_lo  [L_ * D_ * D_];
__device__ __nv_bfloat16 g_w1_hi  [L_ * FF_ * D_];    // [FF, D]
__device__ __nv_bfloat16 g_w1_lo  [L_ * FF_ * D_];
__device__ __nv_bfloat16 g_w2_hi  [L_ * D_ * FF_];    // [D, FF]
__device__ __nv_bfloat16 g_w2_lo  [L_ * D_ * FF_];
__device__ float         g_bqkv  [L_ * QKV_N];

// ---------------------------------------------------------------------------
// Baseline-PTX helpers (sm_75/80 features only)
// ---------------------------------------------------------------------------
__device__ __forceinline__ uint32_t smem_u32(const void* p) {
    uint32_t a;
    asm("{ .reg .u64 t; cvta.to.shared.u64 t, %1; cvt.u32.u64 %0, t; }"
        : "=r"(a) : "l"(p));
    return a;
}
__device__ __forceinline__ void cp16(uint32_t s, const void* g) {
    asm volatile("cp.async.cg.shared.global [%0], [%1], 16;" :: "r"(s), "l"(g));
}
#define CP_COMMIT() asm volatile("cp.async.commit_group;" ::: "memory")
#define CP_WAIT(n)  asm volatile("cp.async.wait_group %0;" :: "n"(n) : "memory")

__device__ __forceinline__ void ldsm4(uint32_t r[4], uint32_t addr) {
    asm volatile("ldmatrix.sync.aligned.m8n8.x4.shared.b16 {%0,%1,%2,%3}, [%4];"
        : "=r"(r[0]), "=r"(r[1]), "=r"(r[2]), "=r"(r[3]) : "r"(addr));
}
__device__ __forceinline__ void ldsm4t(uint32_t r[4], uint32_t addr) {
    asm volatile("ldmatrix.sync.aligned.m8n8.x4.trans.shared.b16 {%0,%1,%2,%3}, [%4];"
        : "=r"(r[0]), "=r"(r[1]), "=r"(r[2]), "=r"(r[3]) : "r"(addr));
}
__device__ __forceinline__ void mma16816(float c[4], const uint32_t a[4],
                                         const uint32_t b[2]) {
    asm volatile(
        "mma.sync.aligned.m16n8k16.row.col.f32.bf16.bf16.f32 "
        "{%0,%1,%2,%3}, {%4,%5,%6,%7}, {%8,%9}, {%0,%1,%2,%3};"
        : "+f"(c[0]), "+f"(c[1]), "+f"(c[2]), "+f"(c[3])
        : "r"(a[0]), "r"(a[1]), "r"(a[2]), "r"(a[3]),
          "r"(b[0]), "r"(b[1]));
}
__device__ __forceinline__ uint32_t pack_bf2(float a, float b) {
    __nv_bfloat162 t(__float2bfloat16(a), __float2bfloat16(b));
    return reinterpret_cast<uint32_t&>(t);
}

// ---------------------------------------------------------------------------
// mma.sync bf16 GEMM:  C[M,N] = (Ahi+Alo)[M,K] @ (Bhi+Blo)[N,K]^T + bias
//                      (+ residual) (+ relu); outputs fp32 and/or bf16 hi/lo.
// Block 128x128, 8 warps (2x4 -> warp tile 64x32), K-stage 32.
// smem row (per matrix, per stage): 128B = [hi 4x16B | lo 4x16B], 8-chunk XOR
// swizzle (ch ^ (r&7)) -> conflict-free ldmatrix. A array 16KB, B 16KB.
// Double-buffered; cp.async; ldmatrix fragments; 3-pass hi/lo mma.
// 2 CTAs/SM (128KB smem total, 128-reg cap) for latency hiding.
// ---------------------------------------------------------------------------
#define GSTAGE  32768
#define GSMEM   (2 * GSTAGE)   // 65536

__device__ __forceinline__ void gemm_load_stage(
    uint32_t sbase, const __nv_bfloat16* __restrict__ Ahi,
    const __nv_bfloat16* __restrict__ Alo,
    const __nv_bfloat16* __restrict__ Bhi,
    const __nv_bfloat16* __restrict__ Blo,
    int m0, int n0, int K, int k0, int tid)
{
    #pragma unroll
    for (int i = 0; i < 8; i++) {
        const int task = tid + i * 256;          // 2048 chunk tasks
        const int arr = task >> 10;              // 0=A, 1=B
        const int r = (task >> 3) & 127;
        const int ch = task & 7;
        const uint32_t dst = sbase + arr * 16384 + r * 128
                           + (uint32_t)((ch ^ (r & 7)) << 4);
        const __nv_bfloat16* src;
        if (arr == 0)
            src = (ch < 4) ? Ahi + (size_t)(m0 + r) * K + k0 + ch * 8
                           : Alo + (size_t)(m0 + r) * K + k0 + (ch - 4) * 8;
        else
            src = (ch < 4) ? Bhi + (size_t)(n0 + r) * K + k0 + ch * 8
                           : Blo + (size_t)(n0 + r) * K + k0 + (ch - 4) * 8;
        cp16(dst, src);
    }
}

__global__ void __launch_bounds__(256, 2) gemm_mma(
    const __nv_bfloat16* __restrict__ Ahi, const __nv_bfloat16* __restrict__ Alo,
    const __nv_bfloat16* __restrict__ Bhi, const __nv_bfloat16* __restrict__ Blo,
    const float* __restrict__ bias, const float* __restrict__ Rsd,
    float* __restrict__ Cf,
    __nv_bfloat16* __restrict__ Chi, __nv_bfloat16* __restrict__ Clo,
    int K, int N, int relu)
{
    extern __shared__ char sm[];
    const uint32_t smb = smem_u32(sm);
    const int tid = threadIdx.x;
    const int wid = tid >> 5, lane = tid & 31;
    const int wm = wid >> 2, wn = wid & 3;          // warp grid 2x4
    const int lq = lane >> 2, lr = lane & 3;
    const int m0 = blockIdx.y * 128, n0 = blockIdx.x * 128;

    float acc[4][4][4];
    #pragma unroll
    for (int i = 0; i < 4; i++)
        #pragma unroll
        for (int j = 0; j < 4; j++)
            #pragma unroll
            for (int k = 0; k < 4; k++) acc[i][j][k] = 0.0f;

    const int NS = K / 32;

    gemm_load_stage(smb, Ahi, Alo, Bhi, Blo, m0, n0, K, 0, tid);
    CP_COMMIT();

    // ldmatrix lane-address components (constant per thread)
    const int a_rl = ((lane >> 3) & 1) * 8 + (lane & 7);  // A: g&1 row grp
    const int a_cg = (lane >> 4) & 1;                     // A: g>>1 k-chunk
    const int b_rl = ((lane >> 4) & 1) * 8 + (lane & 7);  // B: g>>1 row grp
    const int b_cg = (lane >> 3) & 1;                     // B: g&1 k-chunk

    for (int s = 0; s < NS; s++) {
        if (s + 1 < NS) {
            gemm_load_stage(smb + ((s + 1) & 1) * GSTAGE,
                            Ahi, Alo, Bhi, Blo, m0, n0, K, (s + 1) * 32, tid);
            CP_COMMIT();
            CP_WAIT(1);
        } else {
            CP_WAIT(0);
        }
        __syncthreads();

        const uint32_t sA = smb + (s & 1) * GSTAGE;
        const uint32_t sB = sA + 16384;

        #pragma unroll
        for (int kk = 0; kk < 2; kk++) {
            uint32_t ah[4][4], al[4][4];
            #pragma unroll
            for (int mt = 0; mt < 4; mt++) {
                const int row = wm * 64 + mt * 16 + a_rl;
                const int chh = a_cg + 2 * kk;
                ldsm4(ah[mt], sA + row * 128 + (((chh)     ^ (row & 7)) << 4));
                ldsm4(al[mt], sA + row * 128 + (((chh + 4) ^ (row & 7)) << 4));
            }
            uint32_t bh[4][2], bl[4][2];
            #pragma unroll
            for (int u = 0; u < 2; u++) {
                const int row = wn * 32 + u * 16 + b_rl;
                const int chh = 2 * kk + b_cg;
                uint32_t t4[4];
                ldsm4(t4, sB + row * 128 + (((chh) ^ (row & 7)) << 4));
                bh[2*u][0] = t4[0]; bh[2*u][1] = t4[1];
                bh[2*u+1][0] = t4[2]; bh[2*u+1][1] = t4[3];
                ldsm4(t4, sB + row * 128 + (((chh + 4) ^ (row & 7)) << 4));
                bl[2*u][0] = t4[0]; bl[2*u][1] = t4[1];
                bl[2*u+1][0] = t4[2]; bl[2*u+1][1] = t4[3];
            }
            #pragma unroll
            for (int mt = 0; mt < 4; mt++)
                #pragma unroll
                for (int nt = 0; nt < 4; nt++) {
                    mma16816(acc[mt][nt], ah[mt], bh[nt]);   // hi*hi
                    mma16816(acc[mt][nt], ah[mt], bl[nt]);   // hi*lo
                    mma16816(acc[mt][nt], al[mt], bh[nt]);   // lo*hi
                }
        }
        __syncthreads();
    }

    // Epilogue (fragment layout: c0,c1 at (lq, 2lr), c2,c3 at (lq+8, 2lr))
    const int row0 = m0 + wm * 64;
    const int col0 = n0 + wn * 32;
    #pragma unroll
    for (int mt = 0; mt < 4; mt++) {
        #pragma unroll
        for (int nt = 0; nt < 4; nt++) {
            const int c = col0 + nt * 8 + lr * 2;
            const float b0 = bias[c], b1 = bias[c + 1];
            #pragma unroll
            for (int h = 0; h < 2; h++) {
                const int r = row0 + mt * 16 + lq + h * 8;
                float v0 = acc[mt][nt][2 * h]     + b0;
                float v1 = acc[mt][nt][2 * h + 1] + b1;
                const size_t o = (size_t)r * N + c;
                if (Rsd) {
                    const float2 rv = *(const float2*)(Rsd + o);
                    v0 += rv.x; v1 += rv.y;
                }
                if (relu) { v0 = fmaxf(v0, 0.0f); v1 = fmaxf(v1, 0.0f); }
                if (Cf) *(float2*)(Cf + o) = make_float2(v0, v1);
                if (Chi) {
                    const __nv_bfloat16 h0 = __float2bfloat16(v0);
                    const __nv_bfloat16 h1 = __float2bfloat16(v1);
                    __nv_bfloat162 hh(h0, h1);
                    *(uint32_t*)(Chi + o) = reinterpret_cast<uint32_t&>(hh);
                    *(uint32_t*)(Clo + o) = pack_bf2(v0 - __bfloat162float(h0),
                                                     v1 - __bfloat162float(h1));
                }
            }
        }
    }
}

// ---------------------------------------------------------------------------
// FA2-style attention, mma.sync bf16 3-pass hi/lo on QK^T and PV.
// Block: 64 q-rows, 4 warps (16 rows each), Bc=64 keys/tile, DH=64.
// smem: Qhi/Qlo 8KB each + 2 stages x (Khi,Klo,Vhi,Vlo @ 8KB) = 80KB.
// 2 CTAs/SM (160KB smem, 256 threads -> 256-reg budget, no spills):
// one CTA's softmax overlaps the other's MMAs.
// Rows 128B, 8-chunk XOR swizzle. Grid: (S/64, H, B), 128 threads.
// ---------------------------------------------------------------------------
#define AQ_HI  0
#define AQ_LO  8192
#define A_STG  16384
#define A_SSZ  32768
#define A_KHI  0
#define A_KLO  8192
#define A_VHI  16384
#define A_VLO  24576
#define ATTN_SMEM (A_STG + 2 * A_SSZ)   // 81920

__device__ __forceinline__ void attn_load_kv(
    uint32_t sbase, const __nv_bfloat16* __restrict__ Qhi,
    const __nv_bfloat16* __restrict__ Qlo,
    size_t krow0, int hcol, int tid)
{
    // 4 arrays x 64 rows x 8 chunks = 2048 tasks, 128 threads
    #pragma unroll
    for (int i = 0; i < 16; i++) {
        const int task = tid + i * 128;
        const int arr = task >> 9;               // 0 Khi,1 Klo,2 Vhi,3 Vlo
        const int r = (task >> 3) & 63;
        const int ch = task & 7;
        const uint32_t dst = sbase + arr * 8192 + r * 128
                           + (uint32_t)((ch ^ (r & 7)) << 4);
        const int col = ((arr >> 1) ? 2 * D_ : D_) + hcol + ch * 8;
        const __nv_bfloat16* base = (arr & 1) ? Qlo : Qhi;
        cp16(dst, base + (krow0 + r) * QKV_N + col);
    }
}

__global__ void __launch_bounds__(128, 2) attn_mma(
    const __nv_bfloat16* __restrict__ QKVhi,
    const __nv_bfloat16* __restrict__ QKVlo,
    __nv_bfloat16* __restrict__ Chi, __nv_bfloat16* __restrict__ Clo)
{
    extern __shared__ char sm[];
    const uint32_t smb = smem_u32(sm);
    const int tid = threadIdx.x;
    const int w = tid >> 5, lane = tid & 31;
    const int lq = lane >> 2, lr = lane & 3;
    const int qt = blockIdx.x, h = blockIdx.y, b = blockIdx.z;
    const size_t qrow0 = (size_t)b * S_ + qt * 64;
    const size_t krowb = (size_t)b * S_;
    const int hcol = h * DH_;

    // ---- load Q tile (hi/lo): 2 arrays x 64 rows x 8 chunks = 1024 tasks
    #pragma unroll
    for (int i = 0; i < 8; i++) {
        const int task = tid + i * 128;
        const int arr = task >> 9;
        const int r = (task >> 3) & 63;
        const int ch = task & 7;
        const uint32_t dst = smb + arr * 8192 + r * 128
                           + (uint32_t)((ch ^ (r & 7)) << 4);
        const __nv_bfloat16* base = arr ? QKVlo : QKVhi;
        cp16(dst, base + (qrow0 + r) * QKV_N + hcol + ch * 8);
    }
    attn_load_kv(smb + A_STG, QKVhi, QKVlo, krowb, hcol, tid);
    CP_COMMIT();

    float m0 = -1e30f, m1 = -1e30f, l0 = 0.0f, l1 = 0.0f;
    float oacc[8][4];
    #pragma unroll
    for (int t = 0; t < 8; t++)
        #pragma unroll
        for (int i = 0; i < 4; i++) oacc[t][i] = 0.0f;

    uint32_t qh[4][4], ql[4][4];

    // ldmatrix lane components
    const int a_rl = ((lane >> 3) & 1) * 8 + (lane & 7);  // row grp = g&1
    const int a_cg = (lane >> 4) & 1;                     // k-chunk = g>>1
    const int b_rl = ((lane >> 4) & 1) * 8 + (lane & 7);  // row grp = g>>1
    const int b_cg = (lane >> 3) & 1;                     // k-chunk = g&1

    const int NT = S_ / 64;   // 32 key tiles
    for (int j = 0; j < NT; j++) {
        if (j + 1 < NT) {
            attn_load_kv(smb + A_STG + ((j + 1) & 1) * A_SSZ,
                         QKVhi, QKVlo, krowb + (size_t)(j + 1) * 64, hcol, tid);
            CP_COMMIT();
            CP_WAIT(1);
        } else {
            CP_WAIT(0);
        }
        __syncthreads();

        if (j == 0) {
            // load Q fragments once; fold in softmax scale 1/8 (exact)
            const __nv_bfloat162 s2 = __float2bfloat162_rn(0.125f);
            #pragma unroll
            for (int kk = 0; kk < 4; kk++) {
                const int row = w * 16 + a_rl;
                const int chh = a_cg + 2 * kk;
                ldsm4(qh[kk], smb + AQ_HI + row * 128 + ((chh ^ (row & 7)) << 4));
                ldsm4(ql[kk], smb + AQ_LO + row * 128 + ((chh ^ (row & 7)) << 4));
                #pragma unroll
                for (int i = 0; i < 4; i++) {
                    __nv_bfloat162 vh = reinterpret_cast<__nv_bfloat162&>(qh[kk][i]);
                    vh = __hmul2(vh, s2);
                    qh[kk][i] = reinterpret_cast<uint32_t&>(vh);
                    __nv_bfloat162 vl = reinterpret_cast<__nv_bfloat162&>(ql[kk][i]);
                    vl = __hmul2(vl, s2);
                    ql[kk][i] = reinterpret_cast<uint32_t&>(vl);
                }
            }
        }

        const uint32_t sK = smb + A_STG + (j & 1) * A_SSZ;
        const uint32_t sV = sK + A_VHI;

        // ---- S = Q @ K^T (3-pass) : S tile 16x64 per warp
        float sacc[8][4];
        #pragma unroll
        for (int t = 0; t < 8; t++)
            #pragma unroll
            for (int i = 0; i < 4; i++) sacc[t][i] = 0.0f;

        #pragma unroll
        for (int kk = 0; kk < 4; kk++) {
            uint32_t kh[8][2], kl[8][2];
            #pragma unroll
            for (int u = 0; u < 4; u++) {
                const int row = u * 16 + b_rl;      // key index
                const int chh = 2 * kk + b_cg;      // d chunk
                uint32_t t4[4];
                ldsm4(t4, sK + A_KHI + row * 128 + ((chh ^ (row & 7)) << 4));
                kh[2*u][0] = t4[0]; kh[2*u][1] = t4[1];
                kh[2*u+1][0] = t4[2]; kh[2*u+1][1] = t4[3];
                ldsm4(t4, sK + A_KLO + row * 128 + ((chh ^ (row & 7)) << 4));
                kl[2*u][0] = t4[0]; kl[2*u][1] = t4[1];
                kl[2*u+1][0] = t4[2]; kl[2*u+1][1] = t4[3];
            }
            #pragma unroll
            for (int t = 0; t < 8; t++) {
                mma16816(sacc[t], qh[kk], kh[t]);
                mma16816(sacc[t], qh[kk], kl[t]);
                mma16816(sacc[t], ql[kk], kh[t]);
            }
        }

        // ---- online softmax (rows lq and lq+8; quad lanes share a row)
        float mx0 = -1e30f, mx1 = -1e30f;
        #pragma unroll
        for (int t = 0; t < 8; t++) {
            mx0 = fmaxf(mx0, fmaxf(sacc[t][0], sacc[t][1]));
            mx1 = fmaxf(mx1, fmaxf(sacc[t][2], sacc[t][3]));
        }
        mx0 = fmaxf(mx0, __shfl_xor_sync(0xffffffffu, mx0, 1));
        mx0 = fmaxf(mx0, __shfl_xor_sync(0xffffffffu, mx0, 2));
        mx1 = fmaxf(mx1, __shfl_xor_sync(0xffffffffu, mx1, 1));
        mx1 = fmaxf(mx1, __shfl_xor_sync(0xffffffffu, mx1, 2));
        const float nm0 = fmaxf(m0, mx0), nm1 = fmaxf(m1, mx1);
        const float al0 = __expf(m0 - nm0), al1 = __expf(m1 - nm1);
        m0 = nm0; m1 = nm1;

        float ps0 = 0.0f, ps1 = 0.0f;
        #pragma unroll
        for (int t = 0; t < 8; t++) {
            sacc[t][0] = __expf(sacc[t][0] - m0);
            sacc[t][1] = __expf(sacc[t][1] - m0);
            sacc[t][2] = __expf(sacc[t][2] - m1);
            sacc[t][3] = __expf(sacc[t][3] - m1);
            ps0 += sacc[t][0] + sacc[t][1];
            ps1 += sacc[t][2] + sacc[t][3];
        }
        ps0 += __shfl_xor_sync(0xffffffffu, ps0, 1);
        ps0 += __shfl_xor_sync(0xffffffffu, ps0, 2);
        ps1 += __shfl_xor_sync(0xffffffffu, ps1, 1);
        ps1 += __shfl_xor_sync(0xffffffffu, ps1, 2);
        l0 = l0 * al0 + ps0;
        l1 = l1 * al1 + ps1;

        #pragma unroll
        for (int t = 0; t < 8; t++) {
            oacc[t][0] *= al0; oacc[t][1] *= al0;
            oacc[t][2] *= al1; oacc[t][3] *= al1;
        }

        // ---- P -> bf16 hi/lo A-fragments (C-layout -> A-layout identity)
        uint32_t ph[4][4], pl[4][4];
        #pragma unroll
        for (int kk = 0; kk < 4; kk++) {
            const int t0 = 2 * kk, t1 = 2 * kk + 1;
            const float p[8] = { sacc[t0][0], sacc[t0][1], sacc[t0][2], sacc[t0][3],
                                 sacc[t1][0], sacc[t1][1], sacc[t1][2], sacc[t1][3] };
            float hi[8];
            #pragma unroll
            for (int i = 0; i < 8; i++)
                hi[i] = __bfloat162float(__float2bfloat16(p[i]));
            ph[kk][0] = pack_bf2(p[0], p[1]);
            ph[kk][1] = pack_bf2(p[2], p[3]);
            ph[kk][2] = pack_bf2(p[4], p[5]);
            ph[kk][3] = pack_bf2(p[6], p[7]);
            pl[kk][0] = pack_bf2(p[0] - hi[0], p[1] - hi[1]);
            pl[kk][1] = pack_bf2(p[2] - hi[2], p[3] - hi[3]);
            pl[kk][2] = pack_bf2(p[4] - hi[4], p[5] - hi[5]);
            pl[kk][3] = pack_bf2(p[6] - hi[6], p[7] - hi[7]);
        }

        // ---- O += P @ V (3-pass); V^T fragments via ldmatrix.trans
        #pragma unroll
        for (int kk = 0; kk < 4; kk++) {           // key window 16*kk
            uint32_t vh[8][2], vl[8][2];
            #pragma unroll
            for (int u = 0; u < 4; u++) {
                const int row = 16 * kk + a_rl;    // key row (g&1 grp)
                const int chh = 2 * u + a_cg;      // d chunk (g>>1)
                uint32_t t4[4];
                ldsm4t(t4, sV + 0    + row * 128 + ((chh ^ (row & 7)) << 4));
                vh[2*u][0] = t4[0]; vh[2*u][1] = t4[1];
                vh[2*u+1][0] = t4[2]; vh[2*u+1][1] = t4[3];
                ldsm4t(t4, sV + 8192 + row * 128 + ((chh ^ (row & 7)) << 4));
                vl[2*u][0] = t4[0]; vl[2*u][1] = t4[1];
                vl[2*u+1][0] = t4[2]; vl[2*u+1][1] = t4[3];
            }
            #pragma unroll
            for (int t = 0; t < 8; t++) {
                mma16816(oacc[t], ph[kk], vh[t]);
                mma16816(oacc[t], ph[kk], vl[t]);
                mma16816(oacc[t], pl[kk], vh[t]);
            }
        }
        __syncthreads();
    }

    // ---- epilogue: O /= l, write ctx bf16 hi/lo
    const float i0 = 1.0f / l0, i1 = 1.0f / l1;
    const size_t r0g = qrow0 + w * 16 + lq;
    #pragma unroll
    for (int t = 0; t < 8; t++) {
        const int col = hcol + t * 8 + 2 * lr;
        const float v0 = oacc[t][0] * i0, v1 = oacc[t][1] * i0;
        const float v2 = oacc[t][2] * i1, v3 = oacc[t][3] * i1;
        const __nv_bfloat16 h0 = __float2bfloat16(v0), h1 = __float2bfloat16(v1);
        const __nv_bfloat16 h2 = __float2bfloat16(v2), h3 = __float2bfloat16(v3);
        __nv_bfloat162 a(h0, h1), c(h2, h3);
        *(uint32_t*)(Chi + r0g * D_ + col) = reinterpret_cast<uint32_t&>(a);
        *(uint32_t*)(Clo + r0g * D_ + col) =
            pack_bf2(v0 - __bfloat162float(h0), v1 - __bfloat162float(h1));
        *(uint32_t*)(Chi + (r0g + 8) * D_ + col) = reinterpret_cast<uint32_t&>(c);
        *(uint32_t*)(Clo + (r0g + 8) * D_ + col) =
            pack_bf2(v2 - __bfloat162float(h2), v3 - __bfloat162float(h3));
    }
}

// ---------------------------------------------------------------------------
// Weight transpose + hi/lo split: W fp32 [K,N] -> Ohi/Olo bf16 [N,K]
// ---------------------------------------------------------------------------
__global__ void __launch_bounds__(256) transpose_split(
    const float* __restrict__ W, __nv_bfloat16* __restrict__ Ohi,
    __nv_bfloat16* __restrict__ Olo, int K, int N,
    size_t in_lstride, size_t out_lstride)
{
    __shared__ float t[32][33];
    const int l = blockIdx.z;
    const float* Wl = W + (size_t)l * in_lstride;
    __nv_bfloat16* Hl = Ohi + (size_t)l * out_lstride;
    __nv_bfloat16* Ll = Olo + (size_t)l * out_lstride;
    const int k0 = blockIdx.y * 32, n0 = blockIdx.x * 32;
    const int tx = threadIdx.x & 31, ty = threadIdx.x >> 5;
    #pragma unroll
    for (int i = 0; i < 32; i += 8)
        t[ty + i][tx] = Wl[(size_t)(k0 + ty + i) * N + n0 + tx];
    __syncthreads();
    #pragma unroll
    for (int i = 0; i < 32; i += 8) {
        const float v = t[tx][ty + i];
        const __nv_bfloat16 h = __float2bfloat16(v);
        const size_t o = (size_t)(n0 + ty + i) * K + k0 + tx;
        Hl[o] = h;
        Ll[o] = __float2bfloat16(v - __bfloat162float(h));
    }
}

__global__ void concat_bias(const float* __restrict__ bq, const float* __restrict__ bk,
                            const float* __restrict__ bv, float* __restrict__ out)
{
    const int i = blockIdx.x * 256 + threadIdx.x;
    if (i >= L_ * QKV_N) return;
    const int l = i / QKV_N, j = i % QKV_N;
    float v;
    if (j < D_)            v = bq[l * D_ + j];
    else if (j < 2 * D_)   v = bk[l * D_ + j - D_];
    else                   v = bv[l * D_ + j - 2 * D_];
    out[i] = v;
}

__global__ void split_f32(const float* __restrict__ in,
                          __nv_bfloat16* __restrict__ hi,
                          __nv_bfloat16* __restrict__ lo, int n)
{
    const int i = blockIdx.x * 256 + threadIdx.x;
    if (i >= n) return;
    const float v = in[i];
    const __nv_bfloat16 h = __float2bfloat16(v);
    hi[i] = h;
    lo[i] = __float2bfloat16(v - __bfloat162float(h));
}

// ---------------------------------------------------------------------------
// LayerNorm over last dim (D=1024); fused fp32 + optional bf16 hi/lo output.
// ---------------------------------------------------------------------------
__inline__ __device__ float warpSum(float v) {
    #pragma unroll
    for (int o = 16; o > 0; o >>= 1) v += __shfl_xor_sync(0xffffffffu, v, o);
    return v;
}

__global__ void __launch_bounds__(256) ln_kernel(
    const float* __restrict__ in, const float* __restrict__ gamma,
    const float* __restrict__ beta, float* __restrict__ out,
    __nv_bfloat16* __restrict__ ohi, __nv_bfloat16* __restrict__ olo)
{
    const size_t row = blockIdx.x;
    const float4 val = ((const float4*)(in + row * D_))[threadIdx.x];

    float s  = val.x + val.y + val.z + val.w;
    float sq = val.x * val.x + val.y * val.y + val.z * val.z + val.w * val.w;

    __shared__ float ssum[8], ssq[8];
    s  = warpSum(s);
    sq = warpSum(sq);
    const int wid = threadIdx.x >> 5, lane = threadIdx.x & 31;
    if (lane == 0) { ssum[wid] = s; ssq[wid] = sq; }
    __syncthreads();
    s = 0.f; sq = 0.f;
    #pragma unroll
    for (int i = 0; i < 8; i++) { s += ssum[i]; sq += ssq[i]; }

    const float mean = s * (1.0f / D_);
    const float var  = sq * (1.0f / D_) - mean * mean;
    const float rstd = rsqrtf(var + 1e-6f);

    const int c = threadIdx.x << 2;
    const float4 gv = *(const float4*)(gamma + c);
    const float4 bb = *(const float4*)(beta + c);
    float4 o;
    o.x = (val.x - mean) * rstd * gv.x + bb.x;
    o.y = (val.y - mean) * rstd * gv.y + bb.y;
    o.z = (val.z - mean) * rstd * gv.z + bb.z;
    o.w = (val.w - mean) * rstd * gv.w + bb.w;
    ((float4*)(out + row * D_))[threadIdx.x] = o;

    if (ohi) {
        const __nv_bfloat16 h0 = __float2bfloat16(o.x), h1 = __float2bfloat16(o.y);
        const __nv_bfloat16 h2 = __float2bfloat16(o.z), h3 = __float2bfloat16(o.w);
        __nv_bfloat162 hh0(h0, h1), hh1(h2, h3);
        *(uint2*)(ohi + row * D_ + c) =
            make_uint2(reinterpret_cast<uint32_t&>(hh0),
                       reinterpret_cast<uint32_t&>(hh1));
        *(uint2*)(olo + row * D_ + c) = make_uint2(
            pack_bf2(o.x - __bfloat162float(h0), o.y - __bfloat162float(h1)),
            pack_bf2(o.z - __bfloat162float(h2), o.w - __bfloat162float(h3)));
    }
}

// ---------------------------------------------------------------------------
// Launch
// ---------------------------------------------------------------------------
extern "C" void kernel_launch(void* const* d_in, const int* in_sizes, int n_in,
                              void* d_out, int out_size)
{
    (void)in_sizes; (void)n_in; (void)out_size;

    const float* hs  = (const float*)d_in[0];
    const float* Wq  = (const float*)d_in[1];
    const float* bq  = (const float*)d_in[2];
    const float* Wk  = (const float*)d_in[3];
    const float* bk  = (const float*)d_in[4];
    const float* Wv  = (const float*)d_in[5];
    const float* bv  = (const float*)d_in[6];
    const float* Wp  = (const float*)d_in[7];
    const float* bp  = (const float*)d_in[8];
    const float* g1  = (const float*)d_in[9];
    const float* be1 = (const float*)d_in[10];
    const float* W1  = (const float*)d_in[11];
    const float* b1  = (const float*)d_in[12];
    const float* W2  = (const float*)d_in[13];
    const float* b2  = (const float*)d_in[14];
    const float* g2  = (const float*)d_in[15];
    const float* be2 = (const float*)d_in[16];

    float *x, *t, *bqkv;
    __nv_bfloat16 *xhi, *xlo, *qkvhi, *qkvlo, *chi, *clo, *ffhi, *fflo;
    __nv_bfloat16 *wqkvh, *wqkvl, *wph, *wpl, *w1h, *w1l, *w2h, *w2l;
    cudaGetSymbolAddress((void**)&x,     g_x);
    cudaGetSymbolAddress((void**)&t,     g_t);
    cudaGetSymbolAddress((void**)&bqkv,  g_bqkv);
    cudaGetSymbolAddress((void**)&xhi,   g_xhi);
    cudaGetSymbolAddress((void**)&xlo,   g_xlo);
    cudaGetSymbolAddress((void**)&qkvhi, g_qkvhi);
    cudaGetSymbolAddress((void**)&qkvlo, g_qkvlo);
    cudaGetSymbolAddress((void**)&chi,   g_chi);
    cudaGetSymbolAddress((void**)&clo,   g_clo);
    cudaGetSymbolAddress((void**)&ffhi,  g_ffhi);
    cudaGetSymbolAddress((void**)&fflo,  g_fflo);
    cudaGetSymbolAddress((void**)&wqkvh, g_wqkv_hi);
    cudaGetSymbolAddress((void**)&wqkvl, g_wqkv_lo);
    cudaGetSymbolAddress((void**)&wph,   g_wp_hi);
    cudaGetSymbolAddress((void**)&wpl,   g_wp_lo);
    cudaGetSymbolAddress((void**)&w1h,   g_w1_hi);
    cudaGetSymbolAddress((void**)&w1l,   g_w1_lo);
    cudaGetSymbolAddress((void**)&w2h,   g_w2_hi);
    cudaGetSymbolAddress((void**)&w2l,   g_w2_lo);

    cudaFuncSetAttribute(gemm_mma, cudaFuncAttributeMaxDynamicSharedMemorySize,
                         GSMEM);
    cudaFuncSetAttribute(attn_mma, cudaFuncAttributeMaxDynamicSharedMemorySize,
                         ATTN_SMEM);

    // ---- per-replay weight preprocessing (transpose + hi/lo split) ----
    const dim3 tb(256);
    transpose_split<<<dim3(D_/32, D_/32, L_), tb>>>(
        Wq, wqkvh,                 wqkvl,                 D_, D_,
        (size_t)D_ * D_, (size_t)QKV_N * D_);
    transpose_split<<<dim3(D_/32, D_/32, L_), tb>>>(
        Wk, wqkvh + (size_t)D_*D_, wqkvl + (size_t)D_*D_, D_, D_,
        (size_t)D_ * D_, (size_t)QKV_N * D_);
    transpose_split<<<dim3(D_/32, D_/32, L_), tb>>>(
        Wv, wqkvh + (size_t)2*D_*D_, wqkvl + (size_t)2*D_*D_, D_, D_,
        (size_t)D_ * D_, (size_t)QKV_N * D_);
    transpose_split<<<dim3(D_/32, D_/32, L_), tb>>>(
        Wp, wph, wpl, D_, D_, (size_t)D_ * D_, (size_t)D_ * D_);
    transpose_split<<<dim3(FF_/32, D_/32, L_), tb>>>(
        W1, w1h, w1l, D_, FF_, (size_t)D_ * FF_, (size_t)FF_ * D_);
    transpose_split<<<dim3(D_/32, FF_/32, L_), tb>>>(
        W2, w2h, w2l, FF_, D_, (size_t)FF_ * D_, (size_t)D_ * FF_);
    concat_bias<<<(L_ * QKV_N + 255) / 256, tb>>>(bq, bk, bv, bqkv);

    // ---- initial hidden state ----
    cudaMemcpyAsync(x, hs, (size_t)MTOK * D_ * sizeof(float),
                    cudaMemcpyDeviceToDevice, 0);
    split_f32<<<(MTOK * D_ + 255) / 256, tb>>>(hs, xhi, xlo, MTOK * D_);

    const dim3 gQKV(QKV_N / 128, MTOK / 128);   // (24, 32)
    const dim3 gD  (D_    / 128, MTOK / 128);   // (8, 32)
    const dim3 gFF (FF_   / 128, MTOK / 128);   // (32, 32)
    const dim3 gA  (S_ / 64, H_, B_);           // (32, 16, 2)

    for (int l = 0; l < L_; l++) {
        const size_t lDD = (size_t)l * D_ * D_;
        const size_t lDF = (size_t)l * D_ * FF_;

        gemm_mma<<<gQKV, tb, GSMEM>>>(
            xhi, xlo, wqkvh + (size_t)l * QKV_N * D_, wqkvl + (size_t)l * QKV_N * D_,
            bqkv + (size_t)l * QKV_N, nullptr, nullptr, qkvhi, qkvlo,
            D_, QKV_N, 0);

        attn_mma<<<gA, dim3(128), ATTN_SMEM>>>(qkvhi, qkvlo, chi, clo);

        gemm_mma<<<gD, tb, GSMEM>>>(
            chi, clo, wph + lDD, wpl + lDD, bp + (size_t)l * D_, x,
            t, nullptr, nullptr, D_, D_, 0);
        ln_kernel<<<MTOK, tb>>>(t, g1 + (size_t)l * D_, be1 + (size_t)l * D_,
                                x, xhi, xlo);

        gemm_mma<<<gFF, tb, GSMEM>>>(
            xhi, xlo, w1h + lDF, w1l + lDF, b1 + (size_t)l * FF_, nullptr,
            nullptr, ffhi, fflo, D_, FF_, 1);

        gemm_mma<<<gD, tb, GSMEM>>>(
            ffhi, fflo, w2h + lDF, w2l + lDF, b2 + (size_t)l * D_, x,
            t, nullptr, nullptr, FF_, D_, 0);

        if (l == L_ - 1) {
            ln_kernel<<<MTOK, tb>>>(t, g2 + (size_t)l * D_, be2 + (size_t)l * D_,
                                    (float*)d_out, nullptr, nullptr);
        } else {
            ln_kernel<<<MTOK, tb>>>(t, g2 + (size_t)l * D_, be2 + (size_t)l * D_,
                                    x, xhi, xlo);
        }
    }
}

// round 9
// speedup vs baseline: 4.0557x; 1.3682x over previous
#include <cuda_runtime.h>
#include <cuda_fp16.h>
#include <cstdint>

// Problem constants
#define B_    2
#define S_    2048
#define D_    1024
#define FF_   4096
#define H_    16
#define DH_   64
#define L_    4
#define MTOK  (B_ * S_)      // 4096 tokens
#define QKV_N (3 * D_)       // 3072

// ---------------------------------------------------------------------------
// Scratch (static device globals; no runtime allocation)
// ---------------------------------------------------------------------------
__device__ float  g_x    [MTOK * D_];          // running hidden (fp32)
__device__ __half g_xhi  [MTOK * D_];
__device__ __half g_xlo  [MTOK * D_];
__device__ __half g_qkvhi[MTOK * QKV_N];       // fused QKV (fp16 hi/lo)
__device__ __half g_qkvlo[MTOK * QKV_N];
__device__ __half g_chi  [MTOK * D_];          // attention ctx hi/lo
__device__ __half g_clo  [MTOK * D_];
__device__ float  g_t    [MTOK * D_];          // pre-LN temp
__device__ __half g_ffhi [MTOK * FF_];
__device__ __half g_fflo [MTOK * FF_];

// transposed fp16 weights ([N, K] row-major) — single precision level (B-side)
__device__ __half g_wqkv[L_ * QKV_N * D_];
__device__ __half g_wp  [L_ * D_ * D_];
__device__ __half g_w1  [L_ * FF_ * D_];       // [FF, D]
__device__ __half g_w2  [L_ * D_ * FF_];       // [D, FF]
__device__ float  g_bqkv[L_ * QKV_N];

// ---------------------------------------------------------------------------
// Baseline-PTX helpers (sm_75/80 features only)
// ---------------------------------------------------------------------------
__device__ __forceinline__ uint32_t smem_u32(const void* p) {
    uint32_t a;
    asm("{ .reg .u64 t; cvta.to.shared.u64 t, %1; cvt.u32.u64 %0, t; }"
        : "=r"(a) : "l"(p));
    return a;
}
__device__ __forceinline__ void cp16(uint32_t s, const void* g) {
    asm volatile("cp.async.cg.shared.global [%0], [%1], 16;" :: "r"(s), "l"(g));
}
#define CP_COMMIT() asm volatile("cp.async.commit_group;" ::: "memory")
#define CP_WAIT(n)  asm volatile("cp.async.wait_group %0;" :: "n"(n) : "memory")

__device__ __forceinline__ void ldsm4(uint32_t r[4], uint32_t addr) {
    asm volatile("ldmatrix.sync.aligned.m8n8.x4.shared.b16 {%0,%1,%2,%3}, [%4];"
        : "=r"(r[0]), "=r"(r[1]), "=r"(r[2]), "=r"(r[3]) : "r"(addr));
}
__device__ __forceinline__ void ldsm4t(uint32_t r[4], uint32_t addr) {
    asm volatile("ldmatrix.sync.aligned.m8n8.x4.trans.shared.b16 {%0,%1,%2,%3}, [%4];"
        : "=r"(r[0]), "=r"(r[1]), "=r"(r[2]), "=r"(r[3]) : "r"(addr));
}
__device__ __forceinline__ void mma16816(float c[4], const uint32_t a[4],
                                         const uint32_t b[2]) {
    asm volatile(
        "mma.sync.aligned.m16n8k16.row.col.f32.f16.f16.f32 "
        "{%0,%1,%2,%3}, {%4,%5,%6,%7}, {%8,%9}, {%0,%1,%2,%3};"
        : "+f"(c[0]), "+f"(c[1]), "+f"(c[2]), "+f"(c[3])
        : "r"(a[0]), "r"(a[1]), "r"(a[2]), "r"(a[3]),
          "r"(b[0]), "r"(b[1]));
}
__device__ __forceinline__ uint32_t pack_hf2(float a, float b) {
    __half2 t = __halves2half2(__float2half_rn(a), __float2half_rn(b));
    return reinterpret_cast<uint32_t&>(t);
}

// ---------------------------------------------------------------------------
// fp16 "A-exact" GEMM:  C[M,N] = (Ahi+Alo)[M,K] @ Bh[N,K]^T + bias
//                       (+ residual) (+ relu); outputs fp32 and/or fp16 hi/lo.
// Exactly A @ fp16(B) in 2 MMA passes (A split is lossless in the product).
// Block 128x128, 8 warps (2x4), K-stage 32, cp.async double-buffered.
// A smem row: 128B = [hi 4x16B | lo 4x16B], swizzle ch^(r&7). 16KB/stage.
// B smem: two 64B rows packed per 128B phys row; slot=(j&1)*4+c, XOR p&7.
// 8KB/stage. Stage 24KB, x2 = 48KB; 2 CTAs/SM.
// ---------------------------------------------------------------------------
#define GSTAGE  24576
#define GSMEM   (2 * GSTAGE)   // 49152

__device__ __forceinline__ void gemm_load_stage(
    uint32_t sbase, const __half* __restrict__ Ahi,
    const __half* __restrict__ Alo, const __half* __restrict__ Bh,
    int m0, int n0, int K, int k0, int tid)
{
    #pragma unroll
    for (int i = 0; i < 6; i++) {
        const int task = tid + i * 256;          // 1536 tasks
        if (task < 1024) {                       // A: 128 rows x 8 chunks
            const int r = task >> 3, ch = task & 7;
            const uint32_t dst = sbase + r * 128
                               + (uint32_t)((ch ^ (r & 7)) << 4);
            const __half* src = (ch < 4)
                ? Ahi + (size_t)(m0 + r) * K + k0 + ch * 8
                : Alo + (size_t)(m0 + r) * K + k0 + (ch - 4) * 8;
            cp16(dst, src);
        } else {                                 // B: 128 rows x 4 chunks
            const int idx = task - 1024;
            const int j = idx >> 2, c = idx & 3;
            const int p = j >> 1, slot = ((j & 1) << 2) + c;
            const uint32_t dst = sbase + 16384 + p * 128
                               + (uint32_t)((slot ^ (p & 7)) << 4);
            cp16(dst, Bh + (size_t)(n0 + j) * K + k0 + c * 8);
        }
    }
}

__global__ void __launch_bounds__(256, 2) gemm_mma(
    const __half* __restrict__ Ahi, const __half* __restrict__ Alo,
    const __half* __restrict__ Bh,
    const float* __restrict__ bias, const float* __restrict__ Rsd,
    float* __restrict__ Cf,
    __half* __restrict__ Chi, __half* __restrict__ Clo,
    int K, int N, int relu)
{
    extern __shared__ char sm[];
    const uint32_t smb = smem_u32(sm);
    const int tid = threadIdx.x;
    const int wid = tid >> 5, lane = tid & 31;
    const int wm = wid >> 2, wn = wid & 3;          // warp grid 2x4
    const int lq = lane >> 2, lr = lane & 3;
    const int m0 = blockIdx.y * 128, n0 = blockIdx.x * 128;

    float acc[4][4][4];
    #pragma unroll
    for (int i = 0; i < 4; i++)
        #pragma unroll
        for (int j = 0; j < 4; j++)
            #pragma unroll
            for (int k = 0; k < 4; k++) acc[i][j][k] = 0.0f;

    const int NS = K / 32;

    gemm_load_stage(smb, Ahi, Alo, Bh, m0, n0, K, 0, tid);
    CP_COMMIT();

    const int a_rl = ((lane >> 3) & 1) * 8 + (lane & 7);  // A row grp
    const int a_cg = (lane >> 4) & 1;                     // A k-chunk
    const int b_rl = ((lane >> 4) & 1) * 8 + (lane & 7);  // B row grp
    const int b_cg = (lane >> 3) & 1;                     // B k-chunk

    for (int s = 0; s < NS; s++) {
        if (s + 1 < NS) {
            gemm_load_stage(smb + ((s + 1) & 1) * GSTAGE,
                            Ahi, Alo, Bh, m0, n0, K, (s + 1) * 32, tid);
            CP_COMMIT();
            CP_WAIT(1);
        } else {
            CP_WAIT(0);
        }
        __syncthreads();

        const uint32_t sA = smb + (s & 1) * GSTAGE;
        const uint32_t sB = sA + 16384;

        #pragma unroll
        for (int kk = 0; kk < 2; kk++) {
            uint32_t ah[4][4], al[4][4];
            #pragma unroll
            for (int mt = 0; mt < 4; mt++) {
                const int row = wm * 64 + mt * 16 + a_rl;
                const int chh = a_cg + 2 * kk;
                ldsm4(ah[mt], sA + row * 128 + (((chh)     ^ (row & 7)) << 4));
                ldsm4(al[mt], sA + row * 128 + (((chh + 4) ^ (row & 7)) << 4));
            }
            uint32_t bh[4][2];
            #pragma unroll
            for (int u = 0; u < 2; u++) {
                const int j = wn * 32 + u * 16 + b_rl;
                const int c = 2 * kk + b_cg;
                const int p = j >> 1, slot = ((j & 1) << 2) + c;
                uint32_t t4[4];
                ldsm4(t4, sB + p * 128 + ((slot ^ (p & 7)) << 4));
                bh[2*u][0] = t4[0]; bh[2*u][1] = t4[1];
                bh[2*u+1][0] = t4[2]; bh[2*u+1][1] = t4[3];
            }
            #pragma unroll
            for (int mt = 0; mt < 4; mt++)
                #pragma unroll
                for (int nt = 0; nt < 4; nt++) {
                    mma16816(acc[mt][nt], ah[mt], bh[nt]);   // hi pass
                    mma16816(acc[mt][nt], al[mt], bh[nt]);   // lo pass
                }
        }
        __syncthreads();
    }

    // Epilogue (fragment: c0,c1 at (lq, 2lr), c2,c3 at (lq+8, 2lr))
    const int row0 = m0 + wm * 64;
    const int col0 = n0 + wn * 32;
    #pragma unroll
    for (int mt = 0; mt < 4; mt++) {
        #pragma unroll
        for (int nt = 0; nt < 4; nt++) {
            const int c = col0 + nt * 8 + lr * 2;
            const float b0 = bias[c], b1 = bias[c + 1];
            #pragma unroll
            for (int h = 0; h < 2; h++) {
                const int r = row0 + mt * 16 + lq + h * 8;
                float v0 = acc[mt][nt][2 * h]     + b0;
                float v1 = acc[mt][nt][2 * h + 1] + b1;
                const size_t o = (size_t)r * N + c;
                if (Rsd) {
                    const float2 rv = *(const float2*)(Rsd + o);
                    v0 += rv.x; v1 += rv.y;
                }
                if (relu) { v0 = fmaxf(v0, 0.0f); v1 = fmaxf(v1, 0.0f); }
                if (Cf) *(float2*)(Cf + o) = make_float2(v0, v1);
                if (Chi) {
                    const __half h0 = __float2half_rn(v0);
                    const __half h1 = __float2half_rn(v1);
                    __half2 hh = __halves2half2(h0, h1);
                    *(uint32_t*)(Chi + o) = reinterpret_cast<uint32_t&>(hh);
                    *(uint32_t*)(Clo + o) = pack_hf2(v0 - __half2float(h0),
                                                     v1 - __half2float(h1));
                }
            }
        }
    }
}

// ---------------------------------------------------------------------------
// FA2-style attention, fp16 A-exact 2-pass on QK^T and PV.
// Q split hi/lo (exact); K,V single fp16. Block 64 q-rows, 4 warps, Bc=64.
// smem: Qhi 8KB + Qlo 8KB + 2 stages x (K 8KB + V 8KB) = 48KB. 3 CTAs/SM.
// fp16 rows are naturally 128B (64 halves); swizzle ch^(r&7).
// Grid: (S/64, H, B), 128 threads.
// ---------------------------------------------------------------------------
#define AQ_HI  0
#define AQ_LO  8192
#define A_STG  16384
#define A_SSZ  16384
#define ATTN_SMEM (A_STG + 2 * A_SSZ)   // 49152

__device__ __forceinline__ void attn_load_kv(
    uint32_t sbase, const __half* __restrict__ QKVhi,
    size_t krow0, int hcol, int tid)
{
    // 2 arrays (K, V) x 64 rows x 8 chunks = 1024 tasks, 128 threads
    #pragma unroll
    for (int i = 0; i < 8; i++) {
        const int task = tid + i * 128;
        const int arr = task >> 9;               // 0 = K, 1 = V
        const int r = (task >> 3) & 63;
        const int ch = task & 7;
        const uint32_t dst = sbase + arr * 8192 + r * 128
                           + (uint32_t)((ch ^ (r & 7)) << 4);
        const int col = (arr ? 2 * D_ : D_) + hcol + ch * 8;
        cp16(dst, QKVhi + (krow0 + r) * QKV_N + col);
    }
}

__global__ void __launch_bounds__(128, 3) attn_mma(
    const __half* __restrict__ QKVhi, const __half* __restrict__ QKVlo,
    __half* __restrict__ Chi, __half* __restrict__ Clo)
{
    extern __shared__ char sm[];
    const uint32_t smb = smem_u32(sm);
    const int tid = threadIdx.x;
    const int w = tid >> 5, lane = tid & 31;
    const int lq = lane >> 2, lr = lane & 3;
    const int qt = blockIdx.x, h = blockIdx.y, b = blockIdx.z;
    const size_t qrow0 = (size_t)b * S_ + qt * 64;
    const size_t krowb = (size_t)b * S_;
    const int hcol = h * DH_;

    // ---- load Q tile: hi + lo arrays, 64 rows x 8 chunks each = 1024 tasks
    #pragma unroll
    for (int i = 0; i < 8; i++) {
        const int task = tid + i * 128;
        const int arr = task >> 9;               // 0 = hi, 1 = lo
        const int r = (task >> 3) & 63;
        const int ch = task & 7;
        const uint32_t dst = smb + arr * 8192 + r * 128
                           + (uint32_t)((ch ^ (r & 7)) << 4);
        const __half* base = arr ? QKVlo : QKVhi;
        cp16(dst, base + (qrow0 + r) * QKV_N + hcol + ch * 8);
    }
    attn_load_kv(smb + A_STG, QKVhi, krowb, hcol, tid);
    CP_COMMIT();

    float m0 = -1e30f, m1 = -1e30f, l0 = 0.0f, l1 = 0.0f;
    float oacc[8][4];
    #pragma unroll
    for (int t = 0; t < 8; t++)
        #pragma unroll
        for (int i = 0; i < 4; i++) oacc[t][i] = 0.0f;

    uint32_t qh[4][4], ql[4][4];

    const int a_rl = ((lane >> 3) & 1) * 8 + (lane & 7);
    const int a_cg = (lane >> 4) & 1;
    const int b_rl = ((lane >> 4) & 1) * 8 + (lane & 7);
    const int b_cg = (lane >> 3) & 1;

    const int NT = S_ / 64;   // 32 key tiles
    for (int j = 0; j < NT; j++) {
        if (j + 1 < NT) {
            attn_load_kv(smb + A_STG + ((j + 1) & 1) * A_SSZ,
                         QKVhi, krowb + (size_t)(j + 1) * 64, hcol, tid);
            CP_COMMIT();
            CP_WAIT(1);
        } else {
            CP_WAIT(0);
        }
        __syncthreads();

        if (j == 0) {
            // load Q fragments once; fold in softmax scale 1/8 (exact)
            const __half2 s2 = __float2half2_rn(0.125f);
            #pragma unroll
            for (int kk = 0; kk < 4; kk++) {
                const int row = w * 16 + a_rl;
                const int chh = a_cg + 2 * kk;
                ldsm4(qh[kk], smb + AQ_HI + row * 128 + ((chh ^ (row & 7)) << 4));
                ldsm4(ql[kk], smb + AQ_LO + row * 128 + ((chh ^ (row & 7)) << 4));
                #pragma unroll
                for (int i = 0; i < 4; i++) {
                    __half2 vh = reinterpret_cast<__half2&>(qh[kk][i]);
                    vh = __hmul2(vh, s2);
                    qh[kk][i] = reinterpret_cast<uint32_t&>(vh);
                    __half2 vl = reinterpret_cast<__half2&>(ql[kk][i]);
                    vl = __hmul2(vl, s2);
                    ql[kk][i] = reinterpret_cast<uint32_t&>(vl);
                }
            }
        }

        const uint32_t sK = smb + A_STG + (j & 1) * A_SSZ;
        const uint32_t sV = sK + 8192;

        // ---- S = Q @ K^T (2-pass, K single fp16): 16x64 per warp
        float sacc[8][4];
        #pragma unroll
        for (int t = 0; t < 8; t++)
            #pragma unroll
            for (int i = 0; i < 4; i++) sacc[t][i] = 0.0f;

        #pragma unroll
        for (int kk = 0; kk < 4; kk++) {
            uint32_t kh[8][2];
            #pragma unroll
            for (int u = 0; u < 4; u++) {
                const int row = u * 16 + b_rl;      // key index
                const int chh = 2 * kk + b_cg;      // d chunk
                uint32_t t4[4];
                ldsm4(t4, sK + row * 128 + ((chh ^ (row & 7)) << 4));
                kh[2*u][0] = t4[0]; kh[2*u][1] = t4[1];
                kh[2*u+1][0] = t4[2]; kh[2*u+1][1] = t4[3];
            }
            #pragma unroll
            for (int t = 0; t < 8; t++) {
                mma16816(sacc[t], qh[kk], kh[t]);
                mma16816(sacc[t], ql[kk], kh[t]);
            }
        }

        // ---- online softmax (rows lq and lq+8)
        float mx0 = -1e30f, mx1 = -1e30f;
        #pragma unroll
        for (int t = 0; t < 8; t++) {
            mx0 = fmaxf(mx0, fmaxf(sacc[t][0], sacc[t][1]));
            mx1 = fmaxf(mx1, fmaxf(sacc[t][2], sacc[t][3]));
        }
        mx0 = fmaxf(mx0, __shfl_xor_sync(0xffffffffu, mx0, 1));
        mx0 = fmaxf(mx0, __shfl_xor_sync(0xffffffffu, mx0, 2));
        mx1 = fmaxf(mx1, __shfl_xor_sync(0xffffffffu, mx1, 1));
        mx1 = fmaxf(mx1, __shfl_xor_sync(0xffffffffu, mx1, 2));
        const float nm0 = fmaxf(m0, mx0), nm1 = fmaxf(m1, mx1);
        const float al0 = __expf(m0 - nm0), al1 = __expf(m1 - nm1);
        m0 = nm0; m1 = nm1;

        float ps0 = 0.0f, ps1 = 0.0f;
        #pragma unroll
        for (int t = 0; t < 8; t++) {
            sacc[t][0] = __expf(sacc[t][0] - m0);
            sacc[t][1] = __expf(sacc[t][1] - m0);
            sacc[t][2] = __expf(sacc[t][2] - m1);
            sacc[t][3] = __expf(sacc[t][3] - m1);
            ps0 += sacc[t][0] + sacc[t][1];
            ps1 += sacc[t][2] + sacc[t][3];
        }
        ps0 += __shfl_xor_sync(0xffffffffu, ps0, 1);
        ps0 += __shfl_xor_sync(0xffffffffu, ps0, 2);
        ps1 += __shfl_xor_sync(0xffffffffu, ps1, 1);
        ps1 += __shfl_xor_sync(0xffffffffu, ps1, 2);
        l0 = l0 * al0 + ps0;
        l1 = l1 * al1 + ps1;

        #pragma unroll
        for (int t = 0; t < 8; t++) {
            oacc[t][0] *= al0; oacc[t][1] *= al0;
            oacc[t][2] *= al1; oacc[t][3] *= al1;
        }

        // ---- P -> fp16 hi/lo A-fragments (exact split of P)
        uint32_t ph[4][4], pl[4][4];
        #pragma unroll
        for (int kk = 0; kk < 4; kk++) {
            const int t0 = 2 * kk, t1 = 2 * kk + 1;
            const float p[8] = { sacc[t0][0], sacc[t0][1], sacc[t0][2], sacc[t0][3],
                                 sacc[t1][0], sacc[t1][1], sacc[t1][2], sacc[t1][3] };
            float hi[8];
            #pragma unroll
            for (int i = 0; i < 8; i++)
                hi[i] = __half2float(__float2half_rn(p[i]));
            ph[kk][0] = pack_hf2(p[0], p[1]);
            ph[kk][1] = pack_hf2(p[2], p[3]);
            ph[kk][2] = pack_hf2(p[4], p[5]);
            ph[kk][3] = pack_hf2(p[6], p[7]);
            pl[kk][0] = pack_hf2(p[0] - hi[0], p[1] - hi[1]);
            pl[kk][1] = pack_hf2(p[2] - hi[2], p[3] - hi[3]);
            pl[kk][2] = pack_hf2(p[4] - hi[4], p[5] - hi[5]);
            pl[kk][3] = pack_hf2(p[6] - hi[6], p[7] - hi[7]);
        }

        // ---- O += P @ V (2-pass, V single fp16); V^T via ldmatrix.trans
        #pragma unroll
        for (int kk = 0; kk < 4; kk++) {           // key window 16*kk
            uint32_t vh[8][2];
            #pragma unroll
            for (int u = 0; u < 4; u++) {
                const int row = 16 * kk + a_rl;    // key row
                const int chh = 2 * u + a_cg;      // d chunk
                uint32_t t4[4];
                ldsm4t(t4, sV + row * 128 + ((chh ^ (row & 7)) << 4));
                vh[2*u][0] = t4[0]; vh[2*u][1] = t4[1];
                vh[2*u+1][0] = t4[2]; vh[2*u+1][1] = t4[3];
            }
            #pragma unroll
            for (int t = 0; t < 8; t++) {
                mma16816(oacc[t], ph[kk], vh[t]);
                mma16816(oacc[t], pl[kk], vh[t]);
            }
        }
        __syncthreads();
    }

    // ---- epilogue: O /= l, write ctx fp16 hi/lo
    const float i0 = 1.0f / l0, i1 = 1.0f / l1;
    const size_t r0g = qrow0 + w * 16 + lq;
    #pragma unroll
    for (int t = 0; t < 8; t++) {
        const int col = hcol + t * 8 + 2 * lr;
        const float v0 = oacc[t][0] * i0, v1 = oacc[t][1] * i0;
        const float v2 = oacc[t][2] * i1, v3 = oacc[t][3] * i1;
        const __half h0 = __float2half_rn(v0), h1 = __float2half_rn(v1);
        const __half h2 = __float2half_rn(v2), h3 = __float2half_rn(v3);
        __half2 a = __halves2half2(h0, h1), c = __halves2half2(h2, h3);
        *(uint32_t*)(Chi + r0g * D_ + col) = reinterpret_cast<uint32_t&>(a);
        *(uint32_t*)(Clo + r0g * D_ + col) =
            pack_hf2(v0 - __half2float(h0), v1 - __half2float(h1));
        *(uint32_t*)(Chi + (r0g + 8) * D_ + col) = reinterpret_cast<uint32_t&>(c);
        *(uint32_t*)(Clo + (r0g + 8) * D_ + col) =
            pack_hf2(v2 - __half2float(h2), v3 - __half2float(h3));
    }
}

// ---------------------------------------------------------------------------
// Weight transpose + fp16 cast: W fp32 [K,N] -> O fp16 [N,K]
// ---------------------------------------------------------------------------
__global__ void __launch_bounds__(256) transpose_cast(
    const float* __restrict__ W, __half* __restrict__ O, int K, int N,
    size_t in_lstride, size_t out_lstride)
{
    __shared__ float t[32][33];
    const int l = blockIdx.z;
    const float* Wl = W + (size_t)l * in_lstride;
    __half* Ol = O + (size_t)l * out_lstride;
    const int k0 = blockIdx.y * 32, n0 = blockIdx.x * 32;
    const int tx = threadIdx.x & 31, ty = threadIdx.x >> 5;
    #pragma unroll
    for (int i = 0; i < 32; i += 8)
        t[ty + i][tx] = Wl[(size_t)(k0 + ty + i) * N + n0 + tx];
    __syncthreads();
    #pragma unroll
    for (int i = 0; i < 32; i += 8)
        Ol[(size_t)(n0 + ty + i) * K + k0 + tx] = __float2half_rn(t[tx][ty + i]);
}

__global__ void concat_bias(const float* __restrict__ bq, const float* __restrict__ bk,
                            const float* __restrict__ bv, float* __restrict__ out)
{
    const int i = blockIdx.x * 256 + threadIdx.x;
    if (i >= L_ * QKV_N) return;
    const int l = i / QKV_N, j = i % QKV_N;
    float v;
    if (j < D_)            v = bq[l * D_ + j];
    else if (j < 2 * D_)   v = bk[l * D_ + j - D_];
    else                   v = bv[l * D_ + j - 2 * D_];
    out[i] = v;
}

__global__ void split_f32(const float* __restrict__ in,
                          __half* __restrict__ hi,
                          __half* __restrict__ lo, int n)
{
    const int i = blockIdx.x * 256 + threadIdx.x;
    if (i >= n) return;
    const float v = in[i];
    const __half h = __float2half_rn(v);
    hi[i] = h;
    lo[i] = __float2half_rn(v - __half2float(h));
}

// ---------------------------------------------------------------------------
// LayerNorm over last dim (D=1024); fused fp32 + optional fp16 hi/lo output.
// ---------------------------------------------------------------------------
__inline__ __device__ float warpSum(float v) {
    #pragma unroll
    for (int o = 16; o > 0; o >>= 1) v += __shfl_xor_sync(0xffffffffu, v, o);
    return v;
}

__global__ void __launch_bounds__(256) ln_kernel(
    const float* __restrict__ in, const float* __restrict__ gamma,
    const float* __restrict__ beta, float* __restrict__ out,
    __half* __restrict__ ohi, __half* __restrict__ olo)
{
    const size_t row = blockIdx.x;
    const float4 val = ((const float4*)(in + row * D_))[threadIdx.x];

    float s  = val.x + val.y + val.z + val.w;
    float sq = val.x * val.x + val.y * val.y + val.z * val.z + val.w * val.w;

    __shared__ float ssum[8], ssq[8];
    s  = warpSum(s);
    sq = warpSum(sq);
    const int wid = threadIdx.x >> 5, lane = threadIdx.x & 31;
    if (lane == 0) { ssum[wid] = s; ssq[wid] = sq; }
    __syncthreads();
    s = 0.f; sq = 0.f;
    #pragma unroll
    for (int i = 0; i < 8; i++) { s += ssum[i]; sq += ssq[i]; }

    const float mean = s * (1.0f / D_);
    const float var  = sq * (1.0f / D_) - mean * mean;
    const float rstd = rsqrtf(var + 1e-6f);

    const int c = threadIdx.x << 2;
    const float4 gv = *(const float4*)(gamma + c);
    const float4 bb = *(const float4*)(beta + c);
    float4 o;
    o.x = (val.x - mean) * rstd * gv.x + bb.x;
    o.y = (val.y - mean) * rstd * gv.y + bb.y;
    o.z = (val.z - mean) * rstd * gv.z + bb.z;
    o.w = (val.w - mean) * rstd * gv.w + bb.w;
    ((float4*)(out + row * D_))[threadIdx.x] = o;

    if (ohi) {
        const __half h0 = __float2half_rn(o.x), h1 = __float2half_rn(o.y);
        const __half h2 = __float2half_rn(o.z), h3 = __float2half_rn(o.w);
        __half2 hh0 = __halves2half2(h0, h1), hh1 = __halves2half2(h2, h3);
        *(uint2*)(ohi + row * D_ + c) =
            make_uint2(reinterpret_cast<uint32_t&>(hh0),
                       reinterpret_cast<uint32_t&>(hh1));
        *(uint2*)(olo + row * D_ + c) = make_uint2(
            pack_hf2(o.x - __half2float(h0), o.y - __half2float(h1)),
            pack_hf2(o.z - __half2float(h2), o.w - __half2float(h3)));
    }
}

// ---------------------------------------------------------------------------
// Launch
// ---------------------------------------------------------------------------
extern "C" void kernel_launch(void* const* d_in, const int* in_sizes, int n_in,
                              void* d_out, int out_size)
{
    (void)in_sizes; (void)n_in; (void)out_size;

    const float* hs  = (const float*)d_in[0];
    const float* Wq  = (const float*)d_in[1];
    const float* bq  = (const float*)d_in[2];
    const float* Wk  = (const float*)d_in[3];
    const float* bk  = (const float*)d_in[4];
    const float* Wv  = (const float*)d_in[5];
    const float* bv  = (const float*)d_in[6];
    const float* Wp  = (const float*)d_in[7];
    const float* bp  = (const float*)d_in[8];
    const float* g1  = (const float*)d_in[9];
    const float* be1 = (const float*)d_in[10];
    const float* W1  = (const float*)d_in[11];
    const float* b1  = (const float*)d_in[12];
    const float* W2  = (const float*)d_in[13];
    const float* b2  = (const float*)d_in[14];
    const float* g2  = (const float*)d_in[15];
    const float* be2 = (const float*)d_in[16];

    float *x, *t, *bqkv;
    __half *xhi, *xlo, *qkvhi, *qkvlo, *chi, *clo, *ffhi, *fflo;
    __half *wqkv, *wp, *w1, *w2;
    cudaGetSymbolAddress((void**)&x,     g_x);
    cudaGetSymbolAddress((void**)&t,     g_t);
    cudaGetSymbolAddress((void**)&bqkv,  g_bqkv);
    cudaGetSymbolAddress((void**)&xhi,   g_xhi);
    cudaGetSymbolAddress((void**)&xlo,   g_xlo);
    cudaGetSymbolAddress((void**)&qkvhi, g_qkvhi);
    cudaGetSymbolAddress((void**)&qkvlo, g_qkvlo);
    cudaGetSymbolAddress((void**)&chi,   g_chi);
    cudaGetSymbolAddress((void**)&clo,   g_clo);
    cudaGetSymbolAddress((void**)&ffhi,  g_ffhi);
    cudaGetSymbolAddress((void**)&fflo,  g_fflo);
    cudaGetSymbolAddress((void**)&wqkv,  g_wqkv);
    cudaGetSymbolAddress((void**)&wp,    g_wp);
    cudaGetSymbolAddress((void**)&w1,    g_w1);
    cudaGetSymbolAddress((void**)&w2,    g_w2);

    cudaFuncSetAttribute(gemm_mma, cudaFuncAttributeMaxDynamicSharedMemorySize,
                         GSMEM);
    cudaFuncSetAttribute(attn_mma, cudaFuncAttributeMaxDynamicSharedMemorySize,
                         ATTN_SMEM);

    // ---- per-replay weight preprocessing (transpose + fp16 cast) ----
    const dim3 tb(256);
    transpose_cast<<<dim3(D_/32, D_/32, L_), tb>>>(
        Wq, wqkv,                  D_, D_, (size_t)D_ * D_, (size_t)QKV_N * D_);
    transpose_cast<<<dim3(D_/32, D_/32, L_), tb>>>(
        Wk, wqkv + (size_t)D_*D_,  D_, D_, (size_t)D_ * D_, (size_t)QKV_N * D_);
    transpose_cast<<<dim3(D_/32, D_/32, L_), tb>>>(
        Wv, wqkv + (size_t)2*D_*D_, D_, D_, (size_t)D_ * D_, (size_t)QKV_N * D_);
    transpose_cast<<<dim3(D_/32, D_/32, L_), tb>>>(
        Wp, wp, D_, D_, (size_t)D_ * D_, (size_t)D_ * D_);
    transpose_cast<<<dim3(FF_/32, D_/32, L_), tb>>>(
        W1, w1, D_, FF_, (size_t)D_ * FF_, (size_t)FF_ * D_);
    transpose_cast<<<dim3(D_/32, FF_/32, L_), tb>>>(
        W2, w2, FF_, D_, (size_t)FF_ * D_, (size_t)D_ * FF_);
    concat_bias<<<(L_ * QKV_N + 255) / 256, tb>>>(bq, bk, bv, bqkv);

    // ---- initial hidden state ----
    cudaMemcpyAsync(x, hs, (size_t)MTOK * D_ * sizeof(float),
                    cudaMemcpyDeviceToDevice, 0);
    split_f32<<<(MTOK * D_ + 255) / 256, tb>>>(hs, xhi, xlo, MTOK * D_);

    const dim3 gQKV(QKV_N / 128, MTOK / 128);   // (24, 32)
    const dim3 gD  (D_    / 128, MTOK / 128);   // (8, 32)
    const dim3 gFF (FF_   / 128, MTOK / 128);   // (32, 32)
    const dim3 gA  (S_ / 64, H_, B_);           // (32, 16, 2)

    for (int l = 0; l < L_; l++) {
        const size_t lDD = (size_t)l * D_ * D_;
        const size_t lDF = (size_t)l * D_ * FF_;

        gemm_mma<<<gQKV, tb, GSMEM>>>(
            xhi, xlo, wqkv + (size_t)l * QKV_N * D_,
            bqkv + (size_t)l * QKV_N, nullptr, nullptr, qkvhi, qkvlo,
            D_, QKV_N, 0);

        attn_mma<<<gA, dim3(128), ATTN_SMEM>>>(qkvhi, qkvlo, chi, clo);

        gemm_mma<<<gD, tb, GSMEM>>>(
            chi, clo, wp + lDD, bp + (size_t)l * D_, x,
            t, nullptr, nullptr, D_, D_, 0);
        ln_kernel<<<MTOK, tb>>>(t, g1 + (size_t)l * D_, be1 + (size_t)l * D_,
                                x, xhi, xlo);

        gemm_mma<<<gFF, tb, GSMEM>>>(
            xhi, xlo, w1 + lDF, b1 + (size_t)l * FF_, nullptr,
            nullptr, ffhi, fflo, D_, FF_, 1);

        gemm_mma<<<gD, tb, GSMEM>>>(
            ffhi, fflo, w2 + lDF, b2 + (size_t)l * D_, x,
            t, nullptr, nullptr, FF_, D_, 0);

        if (l == L_ - 1) {
            ln_kernel<<<MTOK, tb>>>(t, g2 + (size_t)l * D_, be2 + (size_t)l * D_,
                                    (float*)d_out, nullptr, nullptr);
        } else {
            ln_kernel<<<MTOK, tb>>>(t, g2 + (size_t)l * D_, be2 + (size_t)l * D_,
                                    x, xhi, xlo);
        }
    }
}

// round 12
// speedup vs baseline: 6.9851x; 1.7223x over previous
#include <cuda_runtime.h>
#include <cuda_fp16.h>
#include <cstdint>

// Problem constants
#define B_    2
#define S_    2048
#define D_    1024
#define FF_   4096
#define H_    16
#define DH_   64
#define L_    4
#define MTOK  (B_ * S_)      // 4096 tokens
#define QKV_N (3 * D_)       // 3072

// ---------------------------------------------------------------------------
// Scratch (static device globals; no runtime allocation)
// ---------------------------------------------------------------------------
__device__ float  g_x   [MTOK * D_];          // running hidden (fp32)
__device__ __half g_xh  [MTOK * D_];          // fp16 hidden
__device__ __half g_qkv [MTOK * QKV_N];       // fused QKV (fp16)
__device__ __half g_ch  [MTOK * D_];          // attention ctx (fp16)
__device__ float  g_t   [MTOK * D_];          // pre-LN temp
__device__ __half g_ff  [MTOK * FF_];         // FFN hidden (fp16)

// transposed fp16 weights ([N, K] row-major)
__device__ __half g_wqkv[L_ * QKV_N * D_];
__device__ __half g_wp  [L_ * D_ * D_];
__device__ __half g_w1  [L_ * FF_ * D_];      // [FF, D]
__device__ __half g_w2  [L_ * D_ * FF_];      // [D, FF]
__device__ float  g_bqkv[L_ * QKV_N];

// ---------------------------------------------------------------------------
// Baseline-PTX helpers (sm_75/80 features only)
// ---------------------------------------------------------------------------
__device__ __forceinline__ uint32_t smem_u32(const void* p) {
    uint32_t a;
    asm("{ .reg .u64 t; cvta.to.shared.u64 t, %1; cvt.u32.u64 %0, t; }"
        : "=r"(a) : "l"(p));
    return a;
}
__device__ __forceinline__ void cp16(uint32_t s, const void* g) {
    asm volatile("cp.async.cg.shared.global [%0], [%1], 16;" :: "r"(s), "l"(g));
}
#define CP_COMMIT() asm volatile("cp.async.commit_group;" ::: "memory")
#define CP_WAIT(n)  asm volatile("cp.async.wait_group %0;" :: "n"(n) : "memory")

__device__ __forceinline__ void ldsm4(uint32_t r[4], uint32_t addr) {
    asm volatile("ldmatrix.sync.aligned.m8n8.x4.shared.b16 {%0,%1,%2,%3}, [%4];"
        : "=r"(r[0]), "=r"(r[1]), "=r"(r[2]), "=r"(r[3]) : "r"(addr));
}
__device__ __forceinline__ void ldsm4t(uint32_t r[4], uint32_t addr) {
    asm volatile("ldmatrix.sync.aligned.m8n8.x4.trans.shared.b16 {%0,%1,%2,%3}, [%4];"
        : "=r"(r[0]), "=r"(r[1]), "=r"(r[2]), "=r"(r[3]) : "r"(addr));
}
__device__ __forceinline__ void mma16816(float c[4], const uint32_t a[4],
                                         const uint32_t b[2]) {
    asm volatile(
        "mma.sync.aligned.m16n8k16.row.col.f32.f16.f16.f32 "
        "{%0,%1,%2,%3}, {%4,%5,%6,%7}, {%8,%9}, {%0,%1,%2,%3};"
        : "+f"(c[0]), "+f"(c[1]), "+f"(c[2]), "+f"(c[3])
        : "r"(a[0]), "r"(a[1]), "r"(a[2]), "r"(a[3]),
          "r"(b[0]), "r"(b[1]));
}
__device__ __forceinline__ uint32_t pack_hf2(float a, float b) {
    __half2 t = __halves2half2(__float2half_rn(a), __float2half_rn(b));
    return reinterpret_cast<uint32_t&>(t);
}

// ---------------------------------------------------------------------------
// fp16 1-pass GEMM:  C[M,N] = A[M,K] @ B[N,K]^T + bias (+residual) (+relu)
// Block 128x128, 8 warps (2x4), K-stage 32, cp.async double-buffered.
// smem (per matrix per stage): 64B rows packed two-per-128B phys row,
// slot = (r&1)*4 + c, XOR (p&7) -> conflict-free cp.async + ldmatrix
// (scheme validated as the R9 B-side layout). 8KB per matrix; stage 16KB.
// 2 CTAs/SM.
// ---------------------------------------------------------------------------
#define GSTAGE  16384
#define GSMEM   (2 * GSTAGE)   // 32768

__device__ __forceinline__ void gemm_load_stage(
    uint32_t sbase, const __half* __restrict__ Ah,
    const __half* __restrict__ Bh,
    int m0, int n0, int K, int k0, int tid)
{
    #pragma unroll
    for (int i = 0; i < 4; i++) {
        const int task = tid + i * 256;          // 1024 tasks
        const int arr = task >> 9;               // 0=A, 1=B
        const int idx = task & 511;
        const int r = idx >> 2, c = idx & 3;
        const int p = r >> 1, slot = ((r & 1) << 2) + c;
        const uint32_t dst = sbase + arr * 8192 + p * 128
                           + (uint32_t)((slot ^ (p & 7)) << 4);
        const __half* src = arr
            ? Bh + (size_t)(n0 + r) * K + k0 + c * 8
            : Ah + (size_t)(m0 + r) * K + k0 + c * 8;
        cp16(dst, src);
    }
}

__global__ void __launch_bounds__(256, 2) gemm_mma(
    const __half* __restrict__ Ah, const __half* __restrict__ Bh,
    const float* __restrict__ bias, const float* __restrict__ Rsd,
    float* __restrict__ Cf, __half* __restrict__ Ch,
    int K, int N, int relu)
{
    extern __shared__ char sm[];
    const uint32_t smb = smem_u32(sm);
    const int tid = threadIdx.x;
    const int wid = tid >> 5, lane = tid & 31;
    const int wm = wid >> 2, wn = wid & 3;          // warp grid 2x4
    const int lq = lane >> 2, lr = lane & 3;
    const int m0 = blockIdx.y * 128, n0 = blockIdx.x * 128;

    float acc[4][4][4];
    #pragma unroll
    for (int i = 0; i < 4; i++)
        #pragma unroll
        for (int j = 0; j < 4; j++)
            #pragma unroll
            for (int k = 0; k < 4; k++) acc[i][j][k] = 0.0f;

    const int NS = K / 32;

    gemm_load_stage(smb, Ah, Bh, m0, n0, K, 0, tid);
    CP_COMMIT();

    const int a_rl = ((lane >> 3) & 1) * 8 + (lane & 7);  // A row grp
    const int a_cg = (lane >> 4) & 1;                     // A k-chunk
    const int b_rl = ((lane >> 4) & 1) * 8 + (lane & 7);  // B row grp
    const int b_cg = (lane >> 3) & 1;                     // B k-chunk

    for (int s = 0; s < NS; s++) {
        if (s + 1 < NS) {
            gemm_load_stage(smb + ((s + 1) & 1) * GSTAGE,
                            Ah, Bh, m0, n0, K, (s + 1) * 32, tid);
            CP_COMMIT();
            CP_WAIT(1);
        } else {
            CP_WAIT(0);
        }
        __syncthreads();

        const uint32_t sA = smb + (s & 1) * GSTAGE;
        const uint32_t sB = sA + 8192;

        #pragma unroll
        for (int kk = 0; kk < 2; kk++) {
            uint32_t ah[4][4];
            #pragma unroll
            for (int mt = 0; mt < 4; mt++) {
                const int row = wm * 64 + mt * 16 + a_rl;
                const int c = 2 * kk + a_cg;
                const int p = row >> 1, slot = ((row & 1) << 2) + c;
                ldsm4(ah[mt], sA + p * 128 + ((slot ^ (p & 7)) << 4));
            }
            uint32_t bh[4][2];
            #pragma unroll
            for (int u = 0; u < 2; u++) {
                const int j = wn * 32 + u * 16 + b_rl;
                const int c = 2 * kk + b_cg;
                const int p = j >> 1, slot = ((j & 1) << 2) + c;
                uint32_t t4[4];
                ldsm4(t4, sB + p * 128 + ((slot ^ (p & 7)) << 4));
                bh[2*u][0] = t4[0]; bh[2*u][1] = t4[1];
                bh[2*u+1][0] = t4[2]; bh[2*u+1][1] = t4[3];
            }
            #pragma unroll
            for (int mt = 0; mt < 4; mt++)
                #pragma unroll
                for (int nt = 0; nt < 4; nt++)
                    mma16816(acc[mt][nt], ah[mt], bh[nt]);
        }
        __syncthreads();
    }

    // Epilogue (fragment: c0,c1 at (lq, 2lr), c2,c3 at (lq+8, 2lr))
    const int row0 = m0 + wm * 64;
    const int col0 = n0 + wn * 32;
    #pragma unroll
    for (int mt = 0; mt < 4; mt++) {
        #pragma unroll
        for (int nt = 0; nt < 4; nt++) {
            const int c = col0 + nt * 8 + lr * 2;
            const float b0 = bias[c], b1 = bias[c + 1];
            #pragma unroll
            for (int h = 0; h < 2; h++) {
                const int r = row0 + mt * 16 + lq + h * 8;
                float v0 = acc[mt][nt][2 * h]     + b0;
                float v1 = acc[mt][nt][2 * h + 1] + b1;
                const size_t o = (size_t)r * N + c;
                if (Rsd) {
                    const float2 rv = *(const float2*)(Rsd + o);
                    v0 += rv.x; v1 += rv.y;
                }
                if (relu) { v0 = fmaxf(v0, 0.0f); v1 = fmaxf(v1, 0.0f); }
                if (Cf) *(float2*)(Cf + o) = make_float2(v0, v1);
                if (Ch) *(uint32_t*)(Ch + o) = pack_hf2(v0, v1);
            }
        }
    }
}

// ---------------------------------------------------------------------------
// FA2-style attention, pure fp16 1-pass on QK^T and PV.
// Block 64 q-rows, 4 warps, Bc=64, DH=64 (rows naturally 128B).
// smem: Q 8KB + 2 stages x (K 8KB + V 8KB) = 40KB -> 3 CTAs/SM.
// Swizzle ch^(r&7). Grid: (S/64, H, B), 128 threads.
// ---------------------------------------------------------------------------
#define A_STG  8192
#define A_SSZ  16384
#define ATTN_SMEM (A_STG + 2 * A_SSZ)   // 40960

__device__ __forceinline__ void attn_load_kv(
    uint32_t sbase, const __half* __restrict__ QKV,
    size_t krow0, int hcol, int tid)
{
    // 2 arrays (K, V) x 64 rows x 8 chunks = 1024 tasks, 128 threads
    #pragma unroll
    for (int i = 0; i < 8; i++) {
        const int task = tid + i * 128;
        const int arr = task >> 9;               // 0 = K, 1 = V
        const int r = (task >> 3) & 63;
        const int ch = task & 7;
        const uint32_t dst = sbase + arr * 8192 + r * 128
                           + (uint32_t)((ch ^ (r & 7)) << 4);
        const int col = (arr ? 2 * D_ : D_) + hcol + ch * 8;
        cp16(dst, QKV + (krow0 + r) * QKV_N + col);
    }
}

__global__ void __launch_bounds__(128, 3) attn_mma(
    const __half* __restrict__ QKV, __half* __restrict__ Ch)
{
    extern __shared__ char sm[];
    const uint32_t smb = smem_u32(sm);
    const int tid = threadIdx.x;
    const int w = tid >> 5, lane = tid & 31;
    const int lq = lane >> 2, lr = lane & 3;
    const int qt = blockIdx.x, h = blockIdx.y, b = blockIdx.z;
    const size_t qrow0 = (size_t)b * S_ + qt * 64;
    const size_t krowb = (size_t)b * S_;
    const int hcol = h * DH_;

    // ---- load Q tile: 64 rows x 8 chunks = 512 tasks
    #pragma unroll
    for (int i = 0; i < 4; i++) {
        const int task = tid + i * 128;
        const int r = task >> 3, ch = task & 7;
        const uint32_t dst = smb + r * 128 + (uint32_t)((ch ^ (r & 7)) << 4);
        cp16(dst, QKV + (qrow0 + r) * QKV_N + hcol + ch * 8);
    }
    attn_load_kv(smb + A_STG, QKV, krowb, hcol, tid);
    CP_COMMIT();

    float m0 = -1e30f, m1 = -1e30f, l0 = 0.0f, l1 = 0.0f;
    float oacc[8][4];
    #pragma unroll
    for (int t = 0; t < 8; t++)
        #pragma unroll
        for (int i = 0; i < 4; i++) oacc[t][i] = 0.0f;

    uint32_t qh[4][4];

    const int a_rl = ((lane >> 3) & 1) * 8 + (lane & 7);
    const int a_cg = (lane >> 4) & 1;
    const int b_rl = ((lane >> 4) & 1) * 8 + (lane & 7);
    const int b_cg = (lane >> 3) & 1;

    const int NT = S_ / 64;   // 32 key tiles
    for (int j = 0; j < NT; j++) {
        if (j + 1 < NT) {
            attn_load_kv(smb + A_STG + ((j + 1) & 1) * A_SSZ,
                         QKV, krowb + (size_t)(j + 1) * 64, hcol, tid);
            CP_COMMIT();
            CP_WAIT(1);
        } else {
            CP_WAIT(0);
        }
        __syncthreads();

        if (j == 0) {
            // load Q fragments once; fold in softmax scale 1/8 (exact)
            const __half2 s2 = __float2half2_rn(0.125f);
            #pragma unroll
            for (int kk = 0; kk < 4; kk++) {
                const int row = w * 16 + a_rl;
                const int chh = a_cg + 2 * kk;
                ldsm4(qh[kk], smb + row * 128 + ((chh ^ (row & 7)) << 4));
                #pragma unroll
                for (int i = 0; i < 4; i++) {
                    __half2 vh = reinterpret_cast<__half2&>(qh[kk][i]);
                    vh = __hmul2(vh, s2);
                    qh[kk][i] = reinterpret_cast<uint32_t&>(vh);
                }
            }
        }

        const uint32_t sK = smb + A_STG + (j & 1) * A_SSZ;
        const uint32_t sV = sK + 8192;

        // ---- S = Q @ K^T (1 pass): 16x64 per warp
        float sacc[8][4];
        #pragma unroll
        for (int t = 0; t < 8; t++)
            #pragma unroll
            for (int i = 0; i < 4; i++) sacc[t][i] = 0.0f;

        #pragma unroll
        for (int kk = 0; kk < 4; kk++) {
            uint32_t kh[8][2];
            #pragma unroll
            for (int u = 0; u < 4; u++) {
                const int row = u * 16 + b_rl;      // key index
                const int chh = 2 * kk + b_cg;      // d chunk
                uint32_t t4[4];
                ldsm4(t4, sK + row * 128 + ((chh ^ (row & 7)) << 4));
                kh[2*u][0] = t4[0]; kh[2*u][1] = t4[1];
                kh[2*u+1][0] = t4[2]; kh[2*u+1][1] = t4[3];
            }
            #pragma unroll
            for (int t = 0; t < 8; t++)
                mma16816(sacc[t], qh[kk], kh[t]);
        }

        // ---- online softmax (rows lq and lq+8)
        float mx0 = -1e30f, mx1 = -1e30f;
        #pragma unroll
        for (int t = 0; t < 8; t++) {
            mx0 = fmaxf(mx0, fmaxf(sacc[t][0], sacc[t][1]));
            mx1 = fmaxf(mx1, fmaxf(sacc[t][2], sacc[t][3]));
        }
        mx0 = fmaxf(mx0, __shfl_xor_sync(0xffffffffu, mx0, 1));
        mx0 = fmaxf(mx0, __shfl_xor_sync(0xffffffffu, mx0, 2));
        mx1 = fmaxf(mx1, __shfl_xor_sync(0xffffffffu, mx1, 1));
        mx1 = fmaxf(mx1, __shfl_xor_sync(0xffffffffu, mx1, 2));
        const float nm0 = fmaxf(m0, mx0), nm1 = fmaxf(m1, mx1);
        const float al0 = __expf(m0 - nm0), al1 = __expf(m1 - nm1);
        m0 = nm0; m1 = nm1;

        float ps0 = 0.0f, ps1 = 0.0f;
        #pragma unroll
        for (int t = 0; t < 8; t++) {
            sacc[t][0] = __expf(sacc[t][0] - m0);
            sacc[t][1] = __expf(sacc[t][1] - m0);
            sacc[t][2] = __expf(sacc[t][2] - m1);
            sacc[t][3] = __expf(sacc[t][3] - m1);
            ps0 += sacc[t][0] + sacc[t][1];
            ps1 += sacc[t][2] + sacc[t][3];
        }
        ps0 += __shfl_xor_sync(0xffffffffu, ps0, 1);
        ps0 += __shfl_xor_sync(0xffffffffu, ps0, 2);
        ps1 += __shfl_xor_sync(0xffffffffu, ps1, 1);
        ps1 += __shfl_xor_sync(0xffffffffu, ps1, 2);
        l0 = l0 * al0 + ps0;
        l1 = l1 * al1 + ps1;

        #pragma unroll
        for (int t = 0; t < 8; t++) {
            oacc[t][0] *= al0; oacc[t][1] *= al0;
            oacc[t][2] *= al1; oacc[t][3] *= al1;
        }

        // ---- P -> fp16 A-fragments (C-layout -> A-layout identity)
        uint32_t ph[4][4];
        #pragma unroll
        for (int kk = 0; kk < 4; kk++) {
            const int t0 = 2 * kk, t1 = 2 * kk + 1;
            ph[kk][0] = pack_hf2(sacc[t0][0], sacc[t0][1]);
            ph[kk][1] = pack_hf2(sacc[t0][2], sacc[t0][3]);
            ph[kk][2] = pack_hf2(sacc[t1][0], sacc[t1][1]);
            ph[kk][3] = pack_hf2(sacc[t1][2], sacc[t1][3]);
        }

        // ---- O += P @ V (1 pass); V^T via ldmatrix.trans
        #pragma unroll
        for (int kk = 0; kk < 4; kk++) {           // key window 16*kk
            uint32_t vh[8][2];
            #pragma unroll
            for (int u = 0; u < 4; u++) {
                const int row = 16 * kk + a_rl;    // key row
                const int chh = 2 * u + a_cg;      // d chunk
                uint32_t t4[4];
                ldsm4t(t4, sV + row * 128 + ((chh ^ (row & 7)) << 4));
                vh[2*u][0] = t4[0]; vh[2*u][1] = t4[1];
                vh[2*u+1][0] = t4[2]; vh[2*u+1][1] = t4[3];
            }
            #pragma unroll
            for (int t = 0; t < 8; t++)
                mma16816(oacc[t], ph[kk], vh[t]);
        }
        __syncthreads();
    }

    // ---- epilogue: O /= l, write ctx fp16
    const float i0 = 1.0f / l0, i1 = 1.0f / l1;
    const size_t r0g = qrow0 + w * 16 + lq;
    #pragma unroll
    for (int t = 0; t < 8; t++) {
        const int col = hcol + t * 8 + 2 * lr;
        *(uint32_t*)(Ch + r0g * D_ + col) =
            pack_hf2(oacc[t][0] * i0, oacc[t][1] * i0);
        *(uint32_t*)(Ch + (r0g + 8) * D_ + col) =
            pack_hf2(oacc[t][2] * i1, oacc[t][3] * i1);
    }
}

// ---------------------------------------------------------------------------
// Weight transpose + fp16 cast: W fp32 [K,N] -> O fp16 [N,K]
// ---------------------------------------------------------------------------
__global__ void __launch_bounds__(256) transpose_cast(
    const float* __restrict__ W, __half* __restrict__ O, int K, int N,
    size_t in_lstride, size_t out_lstride)
{
    __shared__ float t[32][33];
    const int l = blockIdx.z;
    const float* Wl = W + (size_t)l * in_lstride;
    __half* Ol = O + (size_t)l * out_lstride;
    const int k0 = blockIdx.y * 32, n0 = blockIdx.x * 32;
    const int tx = threadIdx.x & 31, ty = threadIdx.x >> 5;
    #pragma unroll
    for (int i = 0; i < 32; i += 8)
        t[ty + i][tx] = Wl[(size_t)(k0 + ty + i) * N + n0 + tx];
    __syncthreads();
    #pragma unroll
    for (int i = 0; i < 32; i += 8)
        Ol[(size_t)(n0 + ty + i) * K + k0 + tx] = __float2half_rn(t[tx][ty + i]);
}

__global__ void concat_bias(const float* __restrict__ bq, const float* __restrict__ bk,
                            const float* __restrict__ bv, float* __restrict__ out)
{
    const int i = blockIdx.x * 256 + threadIdx.x;
    if (i >= L_ * QKV_N) return;
    const int l = i / QKV_N, j = i % QKV_N;
    float v;
    if (j < D_)            v = bq[l * D_ + j];
    else if (j < 2 * D_)   v = bk[l * D_ + j - D_];
    else                   v = bv[l * D_ + j - 2 * D_];
    out[i] = v;
}

__global__ void cast_f16(const float* __restrict__ in,
                         __half* __restrict__ out, int n)
{
    const int i = blockIdx.x * 256 + threadIdx.x;
    if (i >= n) return;
    out[i] = __float2half_rn(in[i]);
}

// ---------------------------------------------------------------------------
// LayerNorm over last dim (D=1024); fused fp32 + optional fp16 output.
// ---------------------------------------------------------------------------
__inline__ __device__ float warpSum(float v) {
    #pragma unroll
    for (int o = 16; o > 0; o >>= 1) v += __shfl_xor_sync(0xffffffffu, v, o);
    return v;
}

__global__ void __launch_bounds__(256) ln_kernel(
    const float* __restrict__ in, const float* __restrict__ gamma,
    const float* __restrict__ beta, float* __restrict__ out,
    __half* __restrict__ oh)
{
    const size_t row = blockIdx.x;
    const float4 val = ((const float4*)(in + row * D_))[threadIdx.x];

    float s  = val.x + val.y + val.z + val.w;
    float sq = val.x * val.x + val.y * val.y + val.z * val.z + val.w * val.w;

    __shared__ float ssum[8], ssq[8];
    s  = warpSum(s);
    sq = warpSum(sq);
    const int wid = threadIdx.x >> 5, lane = threadIdx.x & 31;
    if (lane == 0) { ssum[wid] = s; ssq[wid] = sq; }
    __syncthreads();
    s = 0.f; sq = 0.f;
    #pragma unroll
    for (int i = 0; i < 8; i++) { s += ssum[i]; sq += ssq[i]; }

    const float mean = s * (1.0f / D_);
    const float var  = sq * (1.0f / D_) - mean * mean;
    const float rstd = rsqrtf(var + 1e-6f);

    const int c = threadIdx.x << 2;
    const float4 gv = *(const float4*)(gamma + c);
    const float4 bb = *(const float4*)(beta + c);
    float4 o;
    o.x = (val.x - mean) * rstd * gv.x + bb.x;
    o.y = (val.y - mean) * rstd * gv.y + bb.y;
    o.z = (val.z - mean) * rstd * gv.z + bb.z;
    o.w = (val.w - mean) * rstd * gv.w + bb.w;
    ((float4*)(out + row * D_))[threadIdx.x] = o;

    if (oh) {
        *(uint2*)(oh + row * D_ + c) =
            make_uint2(pack_hf2(o.x, o.y), pack_hf2(o.z, o.w));
    }
}

// ---------------------------------------------------------------------------
// Launch
// ---------------------------------------------------------------------------
extern "C" void kernel_launch(void* const* d_in, const int* in_sizes, int n_in,
                              void* d_out, int out_size)
{
    (void)in_sizes; (void)n_in; (void)out_size;

    const float* hs  = (const float*)d_in[0];
    const float* Wq  = (const float*)d_in[1];
    const float* bq  = (const float*)d_in[2];
    const float* Wk  = (const float*)d_in[3];
    const float* bk  = (const float*)d_in[4];
    const float* Wv  = (const float*)d_in[5];
    const float* bv  = (const float*)d_in[6];
    const float* Wp  = (const float*)d_in[7];
    const float* bp  = (const float*)d_in[8];
    const float* g1  = (const float*)d_in[9];
    const float* be1 = (const float*)d_in[10];
    const float* W1  = (const float*)d_in[11];
    const float* b1  = (const float*)d_in[12];
    const float* W2  = (const float*)d_in[13];
    const float* b2  = (const float*)d_in[14];
    const float* g2  = (const float*)d_in[15];
    const float* be2 = (const float*)d_in[16];

    float *x, *t, *bqkv;
    __half *xh, *qkv, *ch, *ff, *wqkv, *wp, *w1, *w2;
    cudaGetSymbolAddress((void**)&x,    g_x);
    cudaGetSymbolAddress((void**)&t,    g_t);
    cudaGetSymbolAddress((void**)&bqkv, g_bqkv);
    cudaGetSymbolAddress((void**)&xh,   g_xh);
    cudaGetSymbolAddress((void**)&qkv,  g_qkv);
    cudaGetSymbolAddress((void**)&ch,   g_ch);
    cudaGetSymbolAddress((void**)&ff,   g_ff);
    cudaGetSymbolAddress((void**)&wqkv, g_wqkv);
    cudaGetSymbolAddress((void**)&wp,   g_wp);
    cudaGetSymbolAddress((void**)&w1,   g_w1);
    cudaGetSymbolAddress((void**)&w2,   g_w2);

    cudaFuncSetAttribute(gemm_mma, cudaFuncAttributeMaxDynamicSharedMemorySize,
                         GSMEM);
    cudaFuncSetAttribute(attn_mma, cudaFuncAttributeMaxDynamicSharedMemorySize,
                         ATTN_SMEM);

    // ---- per-replay weight preprocessing (transpose + fp16 cast) ----
    const dim3 tb(256);
    transpose_cast<<<dim3(D_/32, D_/32, L_), tb>>>(
        Wq, wqkv,                  D_, D_, (size_t)D_ * D_, (size_t)QKV_N * D_);
    transpose_cast<<<dim3(D_/32, D_/32, L_), tb>>>(
        Wk, wqkv + (size_t)D_*D_,  D_, D_, (size_t)D_ * D_, (size_t)QKV_N * D_);
    transpose_cast<<<dim3(D_/32, D_/32, L_), tb>>>(
        Wv, wqkv + (size_t)2*D_*D_, D_, D_, (size_t)D_ * D_, (size_t)QKV_N * D_);
    transpose_cast<<<dim3(D_/32, D_/32, L_), tb>>>(
        Wp, wp, D_, D_, (size_t)D_ * D_, (size_t)D_ * D_);
    transpose_cast<<<dim3(FF_/32, D_/32, L_), tb>>>(
        W1, w1, D_, FF_, (size_t)D_ * FF_, (size_t)FF_ * D_);
    transpose_cast<<<dim3(D_/32, FF_/32, L_), tb>>>(
        W2, w2, FF_, D_, (size_t)FF_ * D_, (size_t)D_ * FF_);
    concat_bias<<<(L_ * QKV_N + 255) / 256, tb>>>(bq, bk, bv, bqkv);

    // ---- initial hidden state ----
    cudaMemcpyAsync(x, hs, (size_t)MTOK * D_ * sizeof(float),
                    cudaMemcpyDeviceToDevice, 0);
    cast_f16<<<(MTOK * D_ + 255) / 256, tb>>>(hs, xh, MTOK * D_);

    const dim3 gQKV(QKV_N / 128, MTOK / 128);   // (24, 32)
    const dim3 gD  (D_    / 128, MTOK / 128);   // (8, 32)
    const dim3 gFF (FF_   / 128, MTOK / 128);   // (32, 32)
    const dim3 gA  (S_ / 64, H_, B_);           // (32, 16, 2)

    for (int l = 0; l < L_; l++) {
        const size_t lDD = (size_t)l * D_ * D_;
        const size_t lDF = (size_t)l * D_ * FF_;

        gemm_mma<<<gQKV, tb, GSMEM>>>(
            xh, wqkv + (size_t)l * QKV_N * D_,
            bqkv + (size_t)l * QKV_N, nullptr, nullptr, qkv,
            D_, QKV_N, 0);

        attn_mma<<<gA, dim3(128), ATTN_SMEM>>>(qkv, ch);

        gemm_mma<<<gD, tb, GSMEM>>>(
            ch, wp + lDD, bp + (size_t)l * D_, x,
            t, nullptr, D_, D_, 0);
        ln_kernel<<<MTOK, tb>>>(t, g1 + (size_t)l * D_, be1 + (size_t)l * D_,
                                x, xh);

        gemm_mma<<<gFF, tb, GSMEM>>>(
            xh, w1 + lDF, b1 + (size_t)l * FF_, nullptr,
            nullptr, ff, D_, FF_, 1);

        gemm_mma<<<gD, tb, GSMEM>>>(
            ff, w2 + lDF, b2 + (size_t)l * D_, x,
            t, nullptr, FF_, D_, 0);

        if (l == L_ - 1) {
            ln_kernel<<<MTOK, tb>>>(t, g2 + (size_t)l * D_, be2 + (size_t)l * D_,
                                    (float*)d_out, nullptr);
        } else {
            ln_kernel<<<MTOK, tb>>>(t, g2 + (size_t)l * D_, be2 + (size_t)l * D_,
                                    x, xh);
        }
    }
}

// round 13
// speedup vs baseline: 7.1554x; 1.0244x over previous
#include <cuda_runtime.h>
#include <cuda_fp16.h>
#include <cstdint>

// Problem constants
#define B_    2
#define S_    2048
#define D_    1024
#define FF_   4096
#define H_    16
#define DH_   64
#define L_    4
#define MTOK  (B_ * S_)      // 4096 tokens
#define QKV_N (3 * D_)       // 3072

// ---------------------------------------------------------------------------
// Scratch (static device globals; no runtime allocation)
// ---------------------------------------------------------------------------
__device__ float  g_x   [MTOK * D_];          // running hidden (fp32)
__device__ __half g_xh  [MTOK * D_];          // fp16 hidden
__device__ __half g_qkv [MTOK * QKV_N];       // fused QKV (fp16)
__device__ __half g_ch  [MTOK * D_];          // attention ctx (fp16)
__device__ float  g_t   [MTOK * D_];          // pre-LN temp
__device__ __half g_ff  [MTOK * FF_];         // FFN hidden (fp16)

// transposed fp16 weights ([N, K] row-major)
__device__ __half g_wqkv[L_ * QKV_N * D_];
__device__ __half g_wp  [L_ * D_ * D_];
__device__ __half g_w1  [L_ * FF_ * D_];      // [FF, D]
__device__ __half g_w2  [L_ * D_ * FF_];      // [D, FF]
__device__ float  g_bqkv[L_ * QKV_N];

// ---------------------------------------------------------------------------
// Baseline-PTX helpers (sm_75/80 features only)
// ---------------------------------------------------------------------------
__device__ __forceinline__ uint32_t smem_u32(const void* p) {
    uint32_t a;
    asm("{ .reg .u64 t; cvta.to.shared.u64 t, %1; cvt.u32.u64 %0, t; }"
        : "=r"(a) : "l"(p));
    return a;
}
__device__ __forceinline__ void cp16(uint32_t s, const void* g) {
    asm volatile("cp.async.cg.shared.global [%0], [%1], 16;" :: "r"(s), "l"(g));
}
#define CP_COMMIT() asm volatile("cp.async.commit_group;" ::: "memory")

__device__ __forceinline__ void cp_wait_dyn(int more) {
    if (more) asm volatile("cp.async.wait_group 1;" ::: "memory");
    else      asm volatile("cp.async.wait_group 0;" ::: "memory");
}

__device__ __forceinline__ void ldsm4(uint32_t r[4], uint32_t addr) {
    asm volatile("ldmatrix.sync.aligned.m8n8.x4.shared.b16 {%0,%1,%2,%3}, [%4];"
        : "=r"(r[0]), "=r"(r[1]), "=r"(r[2]), "=r"(r[3]) : "r"(addr));
}
__device__ __forceinline__ void ldsm4t(uint32_t r[4], uint32_t addr) {
    asm volatile("ldmatrix.sync.aligned.m8n8.x4.trans.shared.b16 {%0,%1,%2,%3}, [%4];"
        : "=r"(r[0]), "=r"(r[1]), "=r"(r[2]), "=r"(r[3]) : "r"(addr));
}
__device__ __forceinline__ void mma16816(float c[4], const uint32_t a[4],
                                         const uint32_t b[2]) {
    asm volatile(
        "mma.sync.aligned.m16n8k16.row.col.f32.f16.f16.f32 "
        "{%0,%1,%2,%3}, {%4,%5,%6,%7}, {%8,%9}, {%0,%1,%2,%3};"
        : "+f"(c[0]), "+f"(c[1]), "+f"(c[2]), "+f"(c[3])
        : "r"(a[0]), "r"(a[1]), "r"(a[2]), "r"(a[3]),
          "r"(b[0]), "r"(b[1]));
}
__device__ __forceinline__ uint32_t pack_hf2(float a, float b) {
    __half2 t = __halves2half2(__float2half_rn(a), __float2half_rn(b));
    return reinterpret_cast<uint32_t&>(t);
}

// ---------------------------------------------------------------------------
// fp16 1-pass GEMM:  C[M,N] = A[M,K] @ B[N,K]^T + bias (+residual) (+relu)
// Block 128x128, 8 warps (2x4), K-stage 32, cp.async 3-stage ring with a
// SINGLE __syncthreads per stage (loads for s+2 issued after the top barrier;
// that buffer was last read at s-1, which the barrier fences).
// smem per matrix per stage: 64B rows packed two-per-128B phys row,
// slot = (r&1)*4 + c, XOR (p&7). 8KB per matrix; stage 16KB; 48KB total.
// 2 CTAs/SM.
// ---------------------------------------------------------------------------
#define GSTAGE  16384
#define GSMEM   (3 * GSTAGE)   // 49152

__device__ __forceinline__ void gemm_load_stage(
    uint32_t sbase, const __half* __restrict__ Ah,
    const __half* __restrict__ Bh,
    int m0, int n0, int K, int k0, int tid)
{
    #pragma unroll
    for (int i = 0; i < 4; i++) {
        const int task = tid + i * 256;          // 1024 tasks
        const int arr = task >> 9;               // 0=A, 1=B
        const int idx = task & 511;
        const int r = idx >> 2, c = idx & 3;
        const int p = r >> 1, slot = ((r & 1) << 2) + c;
        const uint32_t dst = sbase + arr * 8192 + p * 128
                           + (uint32_t)((slot ^ (p & 7)) << 4);
        const __half* src = arr
            ? Bh + (size_t)(n0 + r) * K + k0 + c * 8
            : Ah + (size_t)(m0 + r) * K + k0 + c * 8;
        cp16(dst, src);
    }
}

__global__ void __launch_bounds__(256, 2) gemm_mma(
    const __half* __restrict__ Ah, const __half* __restrict__ Bh,
    const float* __restrict__ bias, const float* __restrict__ Rsd,
    float* __restrict__ Cf, __half* __restrict__ Ch,
    int K, int N, int relu)
{
    extern __shared__ char sm[];
    const uint32_t smb = smem_u32(sm);
    const int tid = threadIdx.x;
    const int wid = tid >> 5, lane = tid & 31;
    const int wm = wid >> 2, wn = wid & 3;          // warp grid 2x4
    const int lq = lane >> 2, lr = lane & 3;
    const int m0 = blockIdx.y * 128, n0 = blockIdx.x * 128;

    float acc[4][4][4];
    #pragma unroll
    for (int i = 0; i < 4; i++)
        #pragma unroll
        for (int j = 0; j < 4; j++)
            #pragma unroll
            for (int k = 0; k < 4; k++) acc[i][j][k] = 0.0f;

    const int NS = K / 32;    // >= 32 for all our shapes

    gemm_load_stage(smb,          Ah, Bh, m0, n0, K, 0,  tid);
    CP_COMMIT();
    gemm_load_stage(smb + GSTAGE, Ah, Bh, m0, n0, K, 32, tid);
    CP_COMMIT();

    const int a_rl = ((lane >> 3) & 1) * 8 + (lane & 7);  // A row grp
    const int a_cg = (lane >> 4) & 1;                     // A k-chunk
    const int b_rl = ((lane >> 4) & 1) * 8 + (lane & 7);  // B row grp
    const int b_cg = (lane >> 3) & 1;                     // B k-chunk

    int bufc = 0;                  // s % 3
    int bufn = 2;                  // (s+2) % 3
    for (int s = 0; s < NS; s++) {
        cp_wait_dyn(s + 1 < NS);
        __syncthreads();
        if (s + 2 < NS) {
            gemm_load_stage(smb + bufn * GSTAGE,
                            Ah, Bh, m0, n0, K, (s + 2) * 32, tid);
            CP_COMMIT();
        }

        const uint32_t sA = smb + bufc * GSTAGE;
        const uint32_t sB = sA + 8192;
        bufc = (bufc == 2) ? 0 : bufc + 1;
        bufn = (bufn == 2) ? 0 : bufn + 1;

        #pragma unroll
        for (int kk = 0; kk < 2; kk++) {
            uint32_t ah[4][4];
            #pragma unroll
            for (int mt = 0; mt < 4; mt++) {
                const int row = wm * 64 + mt * 16 + a_rl;
                const int c = 2 * kk + a_cg;
                const int p = row >> 1, slot = ((row & 1) << 2) + c;
                ldsm4(ah[mt], sA + p * 128 + ((slot ^ (p & 7)) << 4));
            }
            uint32_t bh[4][2];
            #pragma unroll
            for (int u = 0; u < 2; u++) {
                const int j = wn * 32 + u * 16 + b_rl;
                const int c = 2 * kk + b_cg;
                const int p = j >> 1, slot = ((j & 1) << 2) + c;
                uint32_t t4[4];
                ldsm4(t4, sB + p * 128 + ((slot ^ (p & 7)) << 4));
                bh[2*u][0] = t4[0]; bh[2*u][1] = t4[1];
                bh[2*u+1][0] = t4[2]; bh[2*u+1][1] = t4[3];
            }
            #pragma unroll
            for (int mt = 0; mt < 4; mt++)
                #pragma unroll
                for (int nt = 0; nt < 4; nt++)
                    mma16816(acc[mt][nt], ah[mt], bh[nt]);
        }
    }

    // Epilogue (fragment: c0,c1 at (lq, 2lr), c2,c3 at (lq+8, 2lr))
    const int row0 = m0 + wm * 64;
    const int col0 = n0 + wn * 32;
    #pragma unroll
    for (int mt = 0; mt < 4; mt++) {
        #pragma unroll
        for (int nt = 0; nt < 4; nt++) {
            const int c = col0 + nt * 8 + lr * 2;
            const float b0 = bias[c], b1 = bias[c + 1];
            #pragma unroll
            for (int h = 0; h < 2; h++) {
                const int r = row0 + mt * 16 + lq + h * 8;
                float v0 = acc[mt][nt][2 * h]     + b0;
                float v1 = acc[mt][nt][2 * h + 1] + b1;
                const size_t o = (size_t)r * N + c;
                if (Rsd) {
                    const float2 rv = *(const float2*)(Rsd + o);
                    v0 += rv.x; v1 += rv.y;
                }
                if (relu) { v0 = fmaxf(v0, 0.0f); v1 = fmaxf(v1, 0.0f); }
                if (Cf) *(float2*)(Cf + o) = make_float2(v0, v1);
                if (Ch) *(uint32_t*)(Ch + o) = pack_hf2(v0, v1);
            }
        }
    }
}

// ---------------------------------------------------------------------------
// FA2-style attention, pure fp16 1-pass on QK^T and PV.
// Block 64 q-rows, 4 warps, Bc=64, DH=64 (rows naturally 128B).
// 3-stage KV ring, single __syncthreads per key tile.
// smem: Q 8KB + 3 stages x (K 8KB + V 8KB) = 56KB -> 3 CTAs/SM.
// Swizzle ch^(r&7). Grid: (S/64, H, B), 128 threads.
// ---------------------------------------------------------------------------
#define A_STG  8192
#define A_SSZ  16384
#define ATTN_SMEM (A_STG + 3 * A_SSZ)   // 57344

__device__ __forceinline__ void attn_load_kv(
    uint32_t sbase, const __half* __restrict__ QKV,
    size_t krow0, int hcol, int tid)
{
    // 2 arrays (K, V) x 64 rows x 8 chunks = 1024 tasks, 128 threads
    #pragma unroll
    for (int i = 0; i < 8; i++) {
        const int task = tid + i * 128;
        const int arr = task >> 9;               // 0 = K, 1 = V
        const int r = (task >> 3) & 63;
        const int ch = task & 7;
        const uint32_t dst = sbase + arr * 8192 + r * 128
                           + (uint32_t)((ch ^ (r & 7)) << 4);
        const int col = (arr ? 2 * D_ : D_) + hcol + ch * 8;
        cp16(dst, QKV + (krow0 + r) * QKV_N + col);
    }
}

__global__ void __launch_bounds__(128, 3) attn_mma(
    const __half* __restrict__ QKV, __half* __restrict__ Ch)
{
    extern __shared__ char sm[];
    const uint32_t smb = smem_u32(sm);
    const int tid = threadIdx.x;
    const int w = tid >> 5, lane = tid & 31;
    const int lq = lane >> 2, lr = lane & 3;
    const int qt = blockIdx.x, h = blockIdx.y, b = blockIdx.z;
    const size_t qrow0 = (size_t)b * S_ + qt * 64;
    const size_t krowb = (size_t)b * S_;
    const int hcol = h * DH_;

    // ---- load Q tile (512 tasks) + KV stage 0 -> group 0; KV stage 1 -> grp 1
    #pragma unroll
    for (int i = 0; i < 4; i++) {
        const int task = tid + i * 128;
        const int r = task >> 3, ch = task & 7;
        const uint32_t dst = smb + r * 128 + (uint32_t)((ch ^ (r & 7)) << 4);
        cp16(dst, QKV + (qrow0 + r) * QKV_N + hcol + ch * 8);
    }
    attn_load_kv(smb + A_STG, QKV, krowb, hcol, tid);
    CP_COMMIT();
    attn_load_kv(smb + A_STG + A_SSZ, QKV, krowb + 64, hcol, tid);
    CP_COMMIT();

    float m0 = -1e30f, m1 = -1e30f, l0 = 0.0f, l1 = 0.0f;
    float oacc[8][4];
    #pragma unroll
    for (int t = 0; t < 8; t++)
        #pragma unroll
        for (int i = 0; i < 4; i++) oacc[t][i] = 0.0f;

    uint32_t qh[4][4];

    const int a_rl = ((lane >> 3) & 1) * 8 + (lane & 7);
    const int a_cg = (lane >> 4) & 1;
    const int b_rl = ((lane >> 4) & 1) * 8 + (lane & 7);
    const int b_cg = (lane >> 3) & 1;

    const int NT = S_ / 64;   // 32 key tiles
    int bufc = 0, bufn = 2;
    for (int j = 0; j < NT; j++) {
        cp_wait_dyn(j + 1 < NT);
        __syncthreads();
        if (j + 2 < NT) {
            attn_load_kv(smb + A_STG + bufn * A_SSZ,
                         QKV, krowb + (size_t)(j + 2) * 64, hcol, tid);
            CP_COMMIT();
        }

        if (j == 0) {
            // load Q fragments once; fold in softmax scale 1/8 (exact)
            const __half2 s2 = __float2half2_rn(0.125f);
            #pragma unroll
            for (int kk = 0; kk < 4; kk++) {
                const int row = w * 16 + a_rl;
                const int chh = a_cg + 2 * kk;
                ldsm4(qh[kk], smb + row * 128 + ((chh ^ (row & 7)) << 4));
                #pragma unroll
                for (int i = 0; i < 4; i++) {
                    __half2 vh = reinterpret_cast<__half2&>(qh[kk][i]);
                    vh = __hmul2(vh, s2);
                    qh[kk][i] = reinterpret_cast<uint32_t&>(vh);
                }
            }
        }

        const uint32_t sK = smb + A_STG + bufc * A_SSZ;
        const uint32_t sV = sK + 8192;
        bufc = (bufc == 2) ? 0 : bufc + 1;
        bufn = (bufn == 2) ? 0 : bufn + 1;

        // ---- S = Q @ K^T (1 pass): 16x64 per warp
        float sacc[8][4];
        #pragma unroll
        for (int t = 0; t < 8; t++)
            #pragma unroll
            for (int i = 0; i < 4; i++) sacc[t][i] = 0.0f;

        #pragma unroll
        for (int kk = 0; kk < 4; kk++) {
            uint32_t kh[8][2];
            #pragma unroll
            for (int u = 0; u < 4; u++) {
                const int row = u * 16 + b_rl;      // key index
                const int chh = 2 * kk + b_cg;      // d chunk
                uint32_t t4[4];
                ldsm4(t4, sK + row * 128 + ((chh ^ (row & 7)) << 4));
                kh[2*u][0] = t4[0]; kh[2*u][1] = t4[1];
                kh[2*u+1][0] = t4[2]; kh[2*u+1][1] = t4[3];
            }
            #pragma unroll
            for (int t = 0; t < 8; t++)
                mma16816(sacc[t], qh[kk], kh[t]);
        }

        // ---- online softmax (rows lq and lq+8)
        float mx0 = -1e30f, mx1 = -1e30f;
        #pragma unroll
        for (int t = 0; t < 8; t++) {
            mx0 = fmaxf(mx0, fmaxf(sacc[t][0], sacc[t][1]));
            mx1 = fmaxf(mx1, fmaxf(sacc[t][2], sacc[t][3]));
        }
        mx0 = fmaxf(mx0, __shfl_xor_sync(0xffffffffu, mx0, 1));
        mx0 = fmaxf(mx0, __shfl_xor_sync(0xffffffffu, mx0, 2));
        mx1 = fmaxf(mx1, __shfl_xor_sync(0xffffffffu, mx1, 1));
        mx1 = fmaxf(mx1, __shfl_xor_sync(0xffffffffu, mx1, 2));
        const float nm0 = fmaxf(m0, mx0), nm1 = fmaxf(m1, mx1);
        const float al0 = __expf(m0 - nm0), al1 = __expf(m1 - nm1);
        m0 = nm0; m1 = nm1;

        float ps0 = 0.0f, ps1 = 0.0f;
        #pragma unroll
        for (int t = 0; t < 8; t++) {
            sacc[t][0] = __expf(sacc[t][0] - m0);
            sacc[t][1] = __expf(sacc[t][1] - m0);
            sacc[t][2] = __expf(sacc[t][2] - m1);
            sacc[t][3] = __expf(sacc[t][3] - m1);
            ps0 += sacc[t][0] + sacc[t][1];
            ps1 += sacc[t][2] + sacc[t][3];
        }
        ps0 += __shfl_xor_sync(0xffffffffu, ps0, 1);
        ps0 += __shfl_xor_sync(0xffffffffu, ps0, 2);
        ps1 += __shfl_xor_sync(0xffffffffu, ps1, 1);
        ps1 += __shfl_xor_sync(0xffffffffu, ps1, 2);
        l0 = l0 * al0 + ps0;
        l1 = l1 * al1 + ps1;

        #pragma unroll
        for (int t = 0; t < 8; t++) {
            oacc[t][0] *= al0; oacc[t][1] *= al0;
            oacc[t][2] *= al1; oacc[t][3] *= al1;
        }

        // ---- P -> fp16 A-fragments (C-layout -> A-layout identity)
        uint32_t ph[4][4];
        #pragma unroll
        for (int kk = 0; kk < 4; kk++) {
            const int t0 = 2 * kk, t1 = 2 * kk + 1;
            ph[kk][0] = pack_hf2(sacc[t0][0], sacc[t0][1]);
            ph[kk][1] = pack_hf2(sacc[t0][2], sacc[t0][3]);
            ph[kk][2] = pack_hf2(sacc[t1][0], sacc[t1][1]);
            ph[kk][3] = pack_hf2(sacc[t1][2], sacc[t1][3]);
        }

        // ---- O += P @ V (1 pass); V^T via ldmatrix.trans
        #pragma unroll
        for (int kk = 0; kk < 4; kk++) {           // key window 16*kk
            uint32_t vh[8][2];
            #pragma unroll
            for (int u = 0; u < 4; u++) {
                const int row = 16 * kk + a_rl;    // key row
                const int chh = 2 * u + a_cg;      // d chunk
                uint32_t t4[4];
                ldsm4t(t4, sV + row * 128 + ((chh ^ (row & 7)) << 4));
                vh[2*u][0] = t4[0]; vh[2*u][1] = t4[1];
                vh[2*u+1][0] = t4[2]; vh[2*u+1][1] = t4[3];
            }
            #pragma unroll
            for (int t = 0; t < 8; t++)
                mma16816(oacc[t], ph[kk], vh[t]);
        }
    }

    // ---- epilogue: O /= l, write ctx fp16
    const float i0 = 1.0f / l0, i1 = 1.0f / l1;
    const size_t r0g = qrow0 + w * 16 + lq;
    #pragma unroll
    for (int t = 0; t < 8; t++) {
        const int col = hcol + t * 8 + 2 * lr;
        *(uint32_t*)(Ch + r0g * D_ + col) =
            pack_hf2(oacc[t][0] * i0, oacc[t][1] * i0);
        *(uint32_t*)(Ch + (r0g + 8) * D_ + col) =
            pack_hf2(oacc[t][2] * i1, oacc[t][3] * i1);
    }
}

// ---------------------------------------------------------------------------
// Fused preprocessing: ALL weight transposes (fp32 [K,N] -> fp16 [N,K]),
// QKV bias concat, and hidden-state fp32 copy + fp16 cast — ONE launch.
// Block ranges:
//   [0,16384):      Wq/Wk/Wv/Wp 32x32 transpose tiles (4096 each)
//   [16384,32768):  W1 tiles
//   [32768,49152):  W2 tiles
//   [49152,49200):  bias concat (12288 elems)
//   [49200,65584):  hs copy + cast (4M elems)
// ---------------------------------------------------------------------------
#define PREP_BLOCKS 65584

__global__ void __launch_bounds__(256) prep_all(
    const float* __restrict__ hs,
    const float* __restrict__ Wq, const float* __restrict__ Wk,
    const float* __restrict__ Wv, const float* __restrict__ Wp,
    const float* __restrict__ W1, const float* __restrict__ W2,
    const float* __restrict__ bq, const float* __restrict__ bk,
    const float* __restrict__ bv,
    __half* __restrict__ wqkv, __half* __restrict__ wpw,
    __half* __restrict__ w1w, __half* __restrict__ w2w,
    float* __restrict__ bqkv, float* __restrict__ x,
    __half* __restrict__ xh)
{
    const int bid = blockIdx.x;

    if (bid >= 49200) {                         // hidden copy + cast
        const int i = (bid - 49200) * 256 + threadIdx.x;
        const float v = hs[i];
        x[i] = v;
        xh[i] = __float2half_rn(v);
        return;
    }
    if (bid >= 49152) {                         // bias concat
        const int i = (bid - 49152) * 256 + threadIdx.x;
        const int l = i / QKV_N, j = i % QKV_N;
        float v;
        if (j < D_)            v = bq[l * D_ + j];
        else if (j < 2 * D_)   v = bk[l * D_ + j - D_];
        else                   v = bv[l * D_ + j - 2 * D_];
        bqkv[i] = v;
        return;
    }

    // ---- weight transpose tile
    const float* src; __half* dst; int K, N;
    size_t in_ls, out_ls;
    int local;
    if (bid < 16384) {
        const int g = bid >> 12;                // 0..3
        local = bid & 4095;
        K = D_; N = D_; in_ls = (size_t)D_ * D_;
        if (g == 0)      { src = Wq; dst = wqkv;                     out_ls = (size_t)QKV_N * D_; }
        else if (g == 1) { src = Wk; dst = wqkv + (size_t)D_ * D_;   out_ls = (size_t)QKV_N * D_; }
        else if (g == 2) { src = Wv; dst = wqkv + (size_t)2*D_ * D_; out_ls = (size_t)QKV_N * D_; }
        else             { src = Wp; dst = wpw;                      out_ls = (size_t)D_ * D_; }
    } else if (bid < 32768) {
        local = bid - 16384;
        src = W1; dst = w1w; K = D_; N = FF_;
        in_ls = (size_t)D_ * FF_; out_ls = (size_t)FF_ * D_;
    } else {
        local = bid - 32768;
        src = W2; dst = w2w; K = FF_; N = D_;
        in_ls = (size_t)FF_ * D_; out_ls = (size_t)D_ * FF_;
    }
    const int ntn = N / 32;
    const int tpl = ntn * (K / 32);
    const int l = local / tpl, rem = local % tpl;
    const int n0 = (rem % ntn) * 32, k0 = (rem / ntn) * 32;
    const float* Wl = src + (size_t)l * in_ls;
    __half* Ol = dst + (size_t)l * out_ls;

    __shared__ float t[32][33];
    const int tx = threadIdx.x & 31, ty = threadIdx.x >> 5;
    #pragma unroll
    for (int i = 0; i < 32; i += 8)
        t[ty + i][tx] = Wl[(size_t)(k0 + ty + i) * N + n0 + tx];
    __syncthreads();
    #pragma unroll
    for (int i = 0; i < 32; i += 8)
        Ol[(size_t)(n0 + ty + i) * K + k0 + tx] = __float2half_rn(t[tx][ty + i]);
}

// ---------------------------------------------------------------------------
// LayerNorm over last dim (D=1024); fused fp32 + optional fp16 output.
// ---------------------------------------------------------------------------
__inline__ __device__ float warpSum(float v) {
    #pragma unroll
    for (int o = 16; o > 0; o >>= 1) v += __shfl_xor_sync(0xffffffffu, v, o);
    return v;
}

__global__ void __launch_bounds__(256) ln_kernel(
    const float* __restrict__ in, const float* __restrict__ gamma,
    const float* __restrict__ beta, float* __restrict__ out,
    __half* __restrict__ oh)
{
    const size_t row = blockIdx.x;
    const float4 val = ((const float4*)(in + row * D_))[threadIdx.x];

    float s  = val.x + val.y + val.z + val.w;
    float sq = val.x * val.x + val.y * val.y + val.z * val.z + val.w * val.w;

    __shared__ float ssum[8], ssq[8];
    s  = warpSum(s);
    sq = warpSum(sq);
    const int wid = threadIdx.x >> 5, lane = threadIdx.x & 31;
    if (lane == 0) { ssum[wid] = s; ssq[wid] = sq; }
    __syncthreads();
    s = 0.f; sq = 0.f;
    #pragma unroll
    for (int i = 0; i < 8; i++) { s += ssum[i]; sq += ssq[i]; }

    const float mean = s * (1.0f / D_);
    const float var  = sq * (1.0f / D_) - mean * mean;
    const float rstd = rsqrtf(var + 1e-6f);

    const int c = threadIdx.x << 2;
    const float4 gv = *(const float4*)(gamma + c);
    const float4 bb = *(const float4*)(beta + c);
    float4 o;
    o.x = (val.x - mean) * rstd * gv.x + bb.x;
    o.y = (val.y - mean) * rstd * gv.y + bb.y;
    o.z = (val.z - mean) * rstd * gv.z + bb.z;
    o.w = (val.w - mean) * rstd * gv.w + bb.w;
    ((float4*)(out + row * D_))[threadIdx.x] = o;

    if (oh) {
        *(uint2*)(oh + row * D_ + c) =
            make_uint2(pack_hf2(o.x, o.y), pack_hf2(o.z, o.w));
    }
}

// ---------------------------------------------------------------------------
// Launch
// ---------------------------------------------------------------------------
extern "C" void kernel_launch(void* const* d_in, const int* in_sizes, int n_in,
                              void* d_out, int out_size)
{
    (void)in_sizes; (void)n_in; (void)out_size;

    const float* hs  = (const float*)d_in[0];
    const float* Wq  = (const float*)d_in[1];
    const float* bq  = (const float*)d_in[2];
    const float* Wk  = (const float*)d_in[3];
    const float* bk  = (const float*)d_in[4];
    const float* Wv  = (const float*)d_in[5];
    const float* bv  = (const float*)d_in[6];
    const float* Wp  = (const float*)d_in[7];
    const float* bp  = (const float*)d_in[8];
    const float* g1  = (const float*)d_in[9];
    const float* be1 = (const float*)d_in[10];
    const float* W1  = (const float*)d_in[11];
    const float* b1  = (const float*)d_in[12];
    const float* W2  = (const float*)d_in[13];
    const float* b2  = (const float*)d_in[14];
    const float* g2  = (const float*)d_in[15];
    const float* be2 = (const float*)d_in[16];

    float *x, *t, *bqkv;
    __half *xh, *qkv, *ch, *ff, *wqkv, *wp, *w1, *w2;
    cudaGetSymbolAddress((void**)&x,    g_x);
    cudaGetSymbolAddress((void**)&t,    g_t);
    cudaGetSymbolAddress((void**)&bqkv, g_bqkv);
    cudaGetSymbolAddress((void**)&xh,   g_xh);
    cudaGetSymbolAddress((void**)&qkv,  g_qkv);
    cudaGetSymbolAddress((void**)&ch,   g_ch);
    cudaGetSymbolAddress((void**)&ff,   g_ff);
    cudaGetSymbolAddress((void**)&wqkv, g_wqkv);
    cudaGetSymbolAddress((void**)&wp,   g_wp);
    cudaGetSymbolAddress((void**)&w1,   g_w1);
    cudaGetSymbolAddress((void**)&w2,   g_w2);

    cudaFuncSetAttribute(gemm_mma, cudaFuncAttributeMaxDynamicSharedMemorySize,
                         GSMEM);
    cudaFuncSetAttribute(attn_mma, cudaFuncAttributeMaxDynamicSharedMemorySize,
                         ATTN_SMEM);

    const dim3 tb(256);

    // ---- single fused preprocessing launch ----
    prep_all<<<PREP_BLOCKS, tb>>>(hs, Wq, Wk, Wv, Wp, W1, W2, bq, bk, bv,
                                  wqkv, wp, w1, w2, bqkv, x, xh);

    const dim3 gQKV(QKV_N / 128, MTOK / 128);   // (24, 32)
    const dim3 gD  (D_    / 128, MTOK / 128);   // (8, 32)
    const dim3 gFF (FF_   / 128, MTOK / 128);   // (32, 32)
    const dim3 gA  (S_ / 64, H_, B_);           // (32, 16, 2)

    for (int l = 0; l < L_; l++) {
        const size_t lDD = (size_t)l * D_ * D_;
        const size_t lDF = (size_t)l * D_ * FF_;

        gemm_mma<<<gQKV, tb, GSMEM>>>(
            xh, wqkv + (size_t)l * QKV_N * D_,
            bqkv + (size_t)l * QKV_N, nullptr, nullptr, qkv,
            D_, QKV_N, 0);

        attn_mma<<<gA, dim3(128), ATTN_SMEM>>>(qkv, ch);

        gemm_mma<<<gD, tb, GSMEM>>>(
            ch, wp + lDD, bp + (size_t)l * D_, x,
            t, nullptr, D_, D_, 0);
        ln_kernel<<<MTOK, tb>>>(t, g1 + (size_t)l * D_, be1 + (size_t)l * D_,
                                x, xh);

        gemm_mma<<<gFF, tb, GSMEM>>>(
            xh, w1 + lDF, b1 + (size_t)l * FF_, nullptr,
            nullptr, ff, D_, FF_, 1);

        gemm_mma<<<gD, tb, GSMEM>>>(
            ff, w2 + lDF, b2 + (size_t)l * D_, x,
            t, nullptr, FF_, D_, 0);

        if (l == L_ - 1) {
            ln_kernel<<<MTOK, tb>>>(t, g2 + (size_t)l * D_, be2 + (size_t)l * D_,
                                    (float*)d_out, nullptr);
        } else {
            ln_kernel<<<MTOK, tb>>>(t, g2 + (size_t)l * D_, be2 + (size_t)l * D_,
                                    x, xh);
        }
    }
}

// round 14
// speedup vs baseline: 7.7264x; 1.0798x over previous
#include <cuda_runtime.h>
#include <cuda_fp16.h>
#include <cstdint>

// Problem constants
#define B_    2
#define S_    2048
#define D_    1024
#define FF_   4096
#define H_    16
#define DH_   64
#define L_    4
#define MTOK  (B_ * S_)      // 4096 tokens
#define QKV_N (3 * D_)       // 3072

// ---------------------------------------------------------------------------
// Scratch (static device globals; no runtime allocation)
// ---------------------------------------------------------------------------
__device__ float  g_x   [MTOK * D_];          // running hidden (fp32)
__device__ __half g_xh  [MTOK * D_];          // fp16 hidden
__device__ __half g_qkv [MTOK * QKV_N];       // fused QKV (fp16)
__device__ __half g_ch  [MTOK * D_];          // attention ctx (fp16)
__device__ float  g_t   [MTOK * D_];          // pre-LN temp
__device__ __half g_ff  [MTOK * FF_];         // FFN hidden (fp16)

// transposed fp16 weights ([N, K] row-major)
__device__ __half g_wqkv[L_ * QKV_N * D_];
__device__ __half g_wp  [L_ * D_ * D_];
__device__ __half g_w1  [L_ * FF_ * D_];      // [FF, D]
__device__ __half g_w2  [L_ * D_ * FF_];      // [D, FF]
__device__ float  g_bqkv[L_ * QKV_N];

// ---------------------------------------------------------------------------
// Baseline-PTX helpers (sm_75/80 features only)
// ---------------------------------------------------------------------------
__device__ __forceinline__ uint32_t smem_u32(const void* p) {
    uint32_t a;
    asm("{ .reg .u64 t; cvta.to.shared.u64 t, %1; cvt.u32.u64 %0, t; }"
        : "=r"(a) : "l"(p));
    return a;
}
__device__ __forceinline__ void cp16(uint32_t s, const void* g) {
    asm volatile("cp.async.cg.shared.global [%0], [%1], 16;" :: "r"(s), "l"(g));
}
#define CP_COMMIT() asm volatile("cp.async.commit_group;" ::: "memory")

__device__ __forceinline__ void cp_wait_dyn(int more) {
    if (more) asm volatile("cp.async.wait_group 1;" ::: "memory");
    else      asm volatile("cp.async.wait_group 0;" ::: "memory");
}

__device__ __forceinline__ void ldsm4(uint32_t r[4], uint32_t addr) {
    asm volatile("ldmatrix.sync.aligned.m8n8.x4.shared.b16 {%0,%1,%2,%3}, [%4];"
        : "=r"(r[0]), "=r"(r[1]), "=r"(r[2]), "=r"(r[3]) : "r"(addr));
}
__device__ __forceinline__ void ldsm4t(uint32_t r[4], uint32_t addr) {
    asm volatile("ldmatrix.sync.aligned.m8n8.x4.trans.shared.b16 {%0,%1,%2,%3}, [%4];"
        : "=r"(r[0]), "=r"(r[1]), "=r"(r[2]), "=r"(r[3]) : "r"(addr));
}
__device__ __forceinline__ void mma16816(float c[4], const uint32_t a[4],
                                         const uint32_t b[2]) {
    asm volatile(
        "mma.sync.aligned.m16n8k16.row.col.f32.f16.f16.f32 "
        "{%0,%1,%2,%3}, {%4,%5,%6,%7}, {%8,%9}, {%0,%1,%2,%3};"
        : "+f"(c[0]), "+f"(c[1]), "+f"(c[2]), "+f"(c[3])
        : "r"(a[0]), "r"(a[1]), "r"(a[2]), "r"(a[3]),
          "r"(b[0]), "r"(b[1]));
}
__device__ __forceinline__ uint32_t pack_hf2(float a, float b) {
    __half2 t = __halves2half2(__float2half_rn(a), __float2half_rn(b));
    return reinterpret_cast<uint32_t&>(t);
}

// ---------------------------------------------------------------------------
// fp16 1-pass GEMM:  C[M,N] = A[M,K] @ B[N,K]^T + bias (+residual) (+relu)
// Block 128x128, 8 warps (2x4), K-stage 64, cp.async 3-stage ring, single
// __syncthreads per stage. Stage smem: A 128x(64 half)=16KB (natural 128B
// rows, swizzle ch^(r&7) — layout validated by the attention Q/K tiles),
// B same at +16KB. Stage 32KB; 3 stages 96KB; 2 CTAs/SM.
// 4 kk-steps per stage give ptxas a deep window to pipeline LDSM vs HMMA.
// ---------------------------------------------------------------------------
#define GSTAGE  32768
#define GSMEM   (3 * GSTAGE)   // 98304

__device__ __forceinline__ void gemm_load_stage(
    uint32_t sbase, const __half* __restrict__ Ah,
    const __half* __restrict__ Bh,
    int m0, int n0, int K, int k0, int tid)
{
    #pragma unroll
    for (int i = 0; i < 8; i++) {
        const int task = tid + i * 256;          // 2048 tasks
        const int arr = task >> 10;              // 0=A, 1=B
        const int idx = task & 1023;
        const int r = idx >> 3, ch = idx & 7;
        const uint32_t dst = sbase + arr * 16384 + r * 128
                           + (uint32_t)((ch ^ (r & 7)) << 4);
        const __half* src = arr
            ? Bh + (size_t)(n0 + r) * K + k0 + ch * 8
            : Ah + (size_t)(m0 + r) * K + k0 + ch * 8;
        cp16(dst, src);
    }
}

__global__ void __launch_bounds__(256, 2) gemm_mma(
    const __half* __restrict__ Ah, const __half* __restrict__ Bh,
    const float* __restrict__ bias, const float* __restrict__ Rsd,
    float* __restrict__ Cf, __half* __restrict__ Ch,
    int K, int N, int relu)
{
    extern __shared__ char sm[];
    const uint32_t smb = smem_u32(sm);
    const int tid = threadIdx.x;
    const int wid = tid >> 5, lane = tid & 31;
    const int wm = wid >> 2, wn = wid & 3;          // warp grid 2x4
    const int lq = lane >> 2, lr = lane & 3;
    const int m0 = blockIdx.y * 128, n0 = blockIdx.x * 128;

    float acc[4][4][4];
    #pragma unroll
    for (int i = 0; i < 4; i++)
        #pragma unroll
        for (int j = 0; j < 4; j++)
            #pragma unroll
            for (int k = 0; k < 4; k++) acc[i][j][k] = 0.0f;

    const int NS = K / 64;    // 16 (K=1024) or 64 (K=4096)

    gemm_load_stage(smb,          Ah, Bh, m0, n0, K, 0,  tid);
    CP_COMMIT();
    gemm_load_stage(smb + GSTAGE, Ah, Bh, m0, n0, K, 64, tid);
    CP_COMMIT();

    const int a_rl = ((lane >> 3) & 1) * 8 + (lane & 7);  // A row grp
    const int a_cg = (lane >> 4) & 1;                     // A k-chunk
    const int b_rl = ((lane >> 4) & 1) * 8 + (lane & 7);  // B row grp
    const int b_cg = (lane >> 3) & 1;                     // B k-chunk

    int bufc = 0;                  // s % 3
    int bufn = 2;                  // (s+2) % 3
    for (int s = 0; s < NS; s++) {
        cp_wait_dyn(s + 1 < NS);
        __syncthreads();
        if (s + 2 < NS) {
            gemm_load_stage(smb + bufn * GSTAGE,
                            Ah, Bh, m0, n0, K, (s + 2) * 64, tid);
            CP_COMMIT();
        }

        const uint32_t sA = smb + bufc * GSTAGE;
        const uint32_t sB = sA + 16384;
        bufc = (bufc == 2) ? 0 : bufc + 1;
        bufn = (bufn == 2) ? 0 : bufn + 1;

        #pragma unroll
        for (int kk = 0; kk < 4; kk++) {
            uint32_t ah[4][4];
            #pragma unroll
            for (int mt = 0; mt < 4; mt++) {
                const int row = wm * 64 + mt * 16 + a_rl;
                const int c = 2 * kk + a_cg;
                ldsm4(ah[mt], sA + row * 128 + ((c ^ (row & 7)) << 4));
            }
            uint32_t bh[4][2];
            #pragma unroll
            for (int u = 0; u < 2; u++) {
                const int j = wn * 32 + u * 16 + b_rl;
                const int c = 2 * kk + b_cg;
                uint32_t t4[4];
                ldsm4(t4, sB + j * 128 + ((c ^ (j & 7)) << 4));
                bh[2*u][0] = t4[0]; bh[2*u][1] = t4[1];
                bh[2*u+1][0] = t4[2]; bh[2*u+1][1] = t4[3];
            }
            #pragma unroll
            for (int mt = 0; mt < 4; mt++)
                #pragma unroll
                for (int nt = 0; nt < 4; nt++)
                    mma16816(acc[mt][nt], ah[mt], bh[nt]);
        }
    }

    // Epilogue (fragment: c0,c1 at (lq, 2lr), c2,c3 at (lq+8, 2lr))
    const int row0 = m0 + wm * 64;
    const int col0 = n0 + wn * 32;
    #pragma unroll
    for (int mt = 0; mt < 4; mt++) {
        #pragma unroll
        for (int nt = 0; nt < 4; nt++) {
            const int c = col0 + nt * 8 + lr * 2;
            const float b0 = bias[c], b1 = bias[c + 1];
            #pragma unroll
            for (int h = 0; h < 2; h++) {
                const int r = row0 + mt * 16 + lq + h * 8;
                float v0 = acc[mt][nt][2 * h]     + b0;
                float v1 = acc[mt][nt][2 * h + 1] + b1;
                const size_t o = (size_t)r * N + c;
                if (Rsd) {
                    const float2 rv = *(const float2*)(Rsd + o);
                    v0 += rv.x; v1 += rv.y;
                }
                if (relu) { v0 = fmaxf(v0, 0.0f); v1 = fmaxf(v1, 0.0f); }
                if (Cf) *(float2*)(Cf + o) = make_float2(v0, v1);
                if (Ch) *(uint32_t*)(Ch + o) = pack_hf2(v0, v1);
            }
        }
    }
}

// ---------------------------------------------------------------------------
// FA2-style attention, pure fp16 1-pass on QK^T and PV.
// Block 64 q-rows, 4 warps, Bc=64, DH=64 (rows naturally 128B).
// 3-stage KV ring, single __syncthreads per key tile.
// smem: Q 8KB + 3 stages x (K 8KB + V 8KB) = 56KB -> 3 CTAs/SM.
// Swizzle ch^(r&7). Grid: (S/64, H, B), 128 threads.
// ---------------------------------------------------------------------------
#define A_STG  8192
#define A_SSZ  16384
#define ATTN_SMEM (A_STG + 3 * A_SSZ)   // 57344

__device__ __forceinline__ void attn_load_kv(
    uint32_t sbase, const __half* __restrict__ QKV,
    size_t krow0, int hcol, int tid)
{
    // 2 arrays (K, V) x 64 rows x 8 chunks = 1024 tasks, 128 threads
    #pragma unroll
    for (int i = 0; i < 8; i++) {
        const int task = tid + i * 128;
        const int arr = task >> 9;               // 0 = K, 1 = V
        const int r = (task >> 3) & 63;
        const int ch = task & 7;
        const uint32_t dst = sbase + arr * 8192 + r * 128
                           + (uint32_t)((ch ^ (r & 7)) << 4);
        const int col = (arr ? 2 * D_ : D_) + hcol + ch * 8;
        cp16(dst, QKV + (krow0 + r) * QKV_N + col);
    }
}

__global__ void __launch_bounds__(128, 3) attn_mma(
    const __half* __restrict__ QKV, __half* __restrict__ Ch)
{
    extern __shared__ char sm[];
    const uint32_t smb = smem_u32(sm);
    const int tid = threadIdx.x;
    const int w = tid >> 5, lane = tid & 31;
    const int lq = lane >> 2, lr = lane & 3;
    const int qt = blockIdx.x, h = blockIdx.y, b = blockIdx.z;
    const size_t qrow0 = (size_t)b * S_ + qt * 64;
    const size_t krowb = (size_t)b * S_;
    const int hcol = h * DH_;

    // ---- load Q tile (512 tasks) + KV stages 0,1
    #pragma unroll
    for (int i = 0; i < 4; i++) {
        const int task = tid + i * 128;
        const int r = task >> 3, ch = task & 7;
        const uint32_t dst = smb + r * 128 + (uint32_t)((ch ^ (r & 7)) << 4);
        cp16(dst, QKV + (qrow0 + r) * QKV_N + hcol + ch * 8);
    }
    attn_load_kv(smb + A_STG, QKV, krowb, hcol, tid);
    CP_COMMIT();
    attn_load_kv(smb + A_STG + A_SSZ, QKV, krowb + 64, hcol, tid);
    CP_COMMIT();

    float m0 = -1e30f, m1 = -1e30f, l0 = 0.0f, l1 = 0.0f;
    float oacc[8][4];
    #pragma unroll
    for (int t = 0; t < 8; t++)
        #pragma unroll
        for (int i = 0; i < 4; i++) oacc[t][i] = 0.0f;

    uint32_t qh[4][4];

    const int a_rl = ((lane >> 3) & 1) * 8 + (lane & 7);
    const int a_cg = (lane >> 4) & 1;
    const int b_rl = ((lane >> 4) & 1) * 8 + (lane & 7);
    const int b_cg = (lane >> 3) & 1;

    const int NT = S_ / 64;   // 32 key tiles
    int bufc = 0, bufn = 2;
    for (int j = 0; j < NT; j++) {
        cp_wait_dyn(j + 1 < NT);
        __syncthreads();
        if (j + 2 < NT) {
            attn_load_kv(smb + A_STG + bufn * A_SSZ,
                         QKV, krowb + (size_t)(j + 2) * 64, hcol, tid);
            CP_COMMIT();
        }

        if (j == 0) {
            // load Q fragments once; fold in softmax scale 1/8 (exact)
            const __half2 s2 = __float2half2_rn(0.125f);
            #pragma unroll
            for (int kk = 0; kk < 4; kk++) {
                const int row = w * 16 + a_rl;
                const int chh = a_cg + 2 * kk;
                ldsm4(qh[kk], smb + row * 128 + ((chh ^ (row & 7)) << 4));
                #pragma unroll
                for (int i = 0; i < 4; i++) {
                    __half2 vh = reinterpret_cast<__half2&>(qh[kk][i]);
                    vh = __hmul2(vh, s2);
                    qh[kk][i] = reinterpret_cast<uint32_t&>(vh);
                }
            }
        }

        const uint32_t sK = smb + A_STG + bufc * A_SSZ;
        const uint32_t sV = sK + 8192;
        bufc = (bufc == 2) ? 0 : bufc + 1;
        bufn = (bufn == 2) ? 0 : bufn + 1;

        // ---- S = Q @ K^T (1 pass): 16x64 per warp
        float sacc[8][4];
        #pragma unroll
        for (int t = 0; t < 8; t++)
            #pragma unroll
            for (int i = 0; i < 4; i++) sacc[t][i] = 0.0f;

        #pragma unroll
        for (int kk = 0; kk < 4; kk++) {
            uint32_t kh[8][2];
            #pragma unroll
            for (int u = 0; u < 4; u++) {
                const int row = u * 16 + b_rl;      // key index
                const int chh = 2 * kk + b_cg;      // d chunk
                uint32_t t4[4];
                ldsm4(t4, sK + row * 128 + ((chh ^ (row & 7)) << 4));
                kh[2*u][0] = t4[0]; kh[2*u][1] = t4[1];
                kh[2*u+1][0] = t4[2]; kh[2*u+1][1] = t4[3];
            }
            #pragma unroll
            for (int t = 0; t < 8; t++)
                mma16816(sacc[t], qh[kk], kh[t]);
        }

        // ---- online softmax (rows lq and lq+8)
        float mx0 = -1e30f, mx1 = -1e30f;
        #pragma unroll
        for (int t = 0; t < 8; t++) {
            mx0 = fmaxf(mx0, fmaxf(sacc[t][0], sacc[t][1]));
            mx1 = fmaxf(mx1, fmaxf(sacc[t][2], sacc[t][3]));
        }
        mx0 = fmaxf(mx0, __shfl_xor_sync(0xffffffffu, mx0, 1));
        mx0 = fmaxf(mx0, __shfl_xor_sync(0xffffffffu, mx0, 2));
        mx1 = fmaxf(mx1, __shfl_xor_sync(0xffffffffu, mx1, 1));
        mx1 = fmaxf(mx1, __shfl_xor_sync(0xffffffffu, mx1, 2));
        const float nm0 = fmaxf(m0, mx0), nm1 = fmaxf(m1, mx1);
        const float al0 = __expf(m0 - nm0), al1 = __expf(m1 - nm1);
        m0 = nm0; m1 = nm1;

        float ps0 = 0.0f, ps1 = 0.0f;
        #pragma unroll
        for (int t = 0; t < 8; t++) {
            sacc[t][0] = __expf(sacc[t][0] - m0);
            sacc[t][1] = __expf(sacc[t][1] - m0);
            sacc[t][2] = __expf(sacc[t][2] - m1);
            sacc[t][3] = __expf(sacc[t][3] - m1);
            ps0 += sacc[t][0] + sacc[t][1];
            ps1 += sacc[t][2] + sacc[t][3];
        }
        ps0 += __shfl_xor_sync(0xffffffffu, ps0, 1);
        ps0 += __shfl_xor_sync(0xffffffffu, ps0, 2);
        ps1 += __shfl_xor_sync(0xffffffffu, ps1, 1);
        ps1 += __shfl_xor_sync(0xffffffffu, ps1, 2);
        l0 = l0 * al0 + ps0;
        l1 = l1 * al1 + ps1;

        #pragma unroll
        for (int t = 0; t < 8; t++) {
            oacc[t][0] *= al0; oacc[t][1] *= al0;
            oacc[t][2] *= al1; oacc[t][3] *= al1;
        }

        // ---- P -> fp16 A-fragments (C-layout -> A-layout identity)
        uint32_t ph[4][4];
        #pragma unroll
        for (int kk = 0; kk < 4; kk++) {
            const int t0 = 2 * kk, t1 = 2 * kk + 1;
            ph[kk][0] = pack_hf2(sacc[t0][0], sacc[t0][1]);
            ph[kk][1] = pack_hf2(sacc[t0][2], sacc[t0][3]);
            ph[kk][2] = pack_hf2(sacc[t1][0], sacc[t1][1]);
            ph[kk][3] = pack_hf2(sacc[t1][2], sacc[t1][3]);
        }

        // ---- O += P @ V (1 pass); V^T via ldmatrix.trans
        #pragma unroll
        for (int kk = 0; kk < 4; kk++) {           // key window 16*kk
            uint32_t vh[8][2];
            #pragma unroll
            for (int u = 0; u < 4; u++) {
                const int row = 16 * kk + a_rl;    // key row
                const int chh = 2 * u + a_cg;      // d chunk
                uint32_t t4[4];
                ldsm4t(t4, sV + row * 128 + ((chh ^ (row & 7)) << 4));
                vh[2*u][0] = t4[0]; vh[2*u][1] = t4[1];
                vh[2*u+1][0] = t4[2]; vh[2*u+1][1] = t4[3];
            }
            #pragma unroll
            for (int t = 0; t < 8; t++)
                mma16816(oacc[t], ph[kk], vh[t]);
        }
    }

    // ---- epilogue: O /= l, write ctx fp16
    const float i0 = 1.0f / l0, i1 = 1.0f / l1;
    const size_t r0g = qrow0 + w * 16 + lq;
    #pragma unroll
    for (int t = 0; t < 8; t++) {
        const int col = hcol + t * 8 + 2 * lr;
        *(uint32_t*)(Ch + r0g * D_ + col) =
            pack_hf2(oacc[t][0] * i0, oacc[t][1] * i0);
        *(uint32_t*)(Ch + (r0g + 8) * D_ + col) =
            pack_hf2(oacc[t][2] * i1, oacc[t][3] * i1);
    }
}

// ---------------------------------------------------------------------------
// Fused preprocessing: ALL weight transposes (fp32 [K,N] -> fp16 [N,K]),
// QKV bias concat, and hidden-state fp32 copy + fp16 cast — ONE launch.
// ---------------------------------------------------------------------------
#define PREP_BLOCKS 65584

__global__ void __launch_bounds__(256) prep_all(
    const float* __restrict__ hs,
    const float* __restrict__ Wq, const float* __restrict__ Wk,
    const float* __restrict__ Wv, const float* __restrict__ Wp,
    const float* __restrict__ W1, const float* __restrict__ W2,
    const float* __restrict__ bq, const float* __restrict__ bk,
    const float* __restrict__ bv,
    __half* __restrict__ wqkv, __half* __restrict__ wpw,
    __half* __restrict__ w1w, __half* __restrict__ w2w,
    float* __restrict__ bqkv, float* __restrict__ x,
    __half* __restrict__ xh)
{
    const int bid = blockIdx.x;

    if (bid >= 49200) {                         // hidden copy + cast
        const int i = (bid - 49200) * 256 + threadIdx.x;
        const float v = hs[i];
        x[i] = v;
        xh[i] = __float2half_rn(v);
        return;
    }
    if (bid >= 49152) {                         // bias concat
        const int i = (bid - 49152) * 256 + threadIdx.x;
        const int l = i / QKV_N, j = i % QKV_N;
        float v;
        if (j < D_)            v = bq[l * D_ + j];
        else if (j < 2 * D_)   v = bk[l * D_ + j - D_];
        else                   v = bv[l * D_ + j - 2 * D_];
        bqkv[i] = v;
        return;
    }

    // ---- weight transpose tile
    const float* src; __half* dst; int K, N;
    size_t in_ls, out_ls;
    int local;
    if (bid < 16384) {
        const int g = bid >> 12;                // 0..3
        local = bid & 4095;
        K = D_; N = D_; in_ls = (size_t)D_ * D_;
        if (g == 0)      { src = Wq; dst = wqkv;                     out_ls = (size_t)QKV_N * D_; }
        else if (g == 1) { src = Wk; dst = wqkv + (size_t)D_ * D_;   out_ls = (size_t)QKV_N * D_; }
        else if (g == 2) { src = Wv; dst = wqkv + (size_t)2*D_ * D_; out_ls = (size_t)QKV_N * D_; }
        else             { src = Wp; dst = wpw;                      out_ls = (size_t)D_ * D_; }
    } else if (bid < 32768) {
        local = bid - 16384;
        src = W1; dst = w1w; K = D_; N = FF_;
        in_ls = (size_t)D_ * FF_; out_ls = (size_t)FF_ * D_;
    } else {
        local = bid - 32768;
        src = W2; dst = w2w; K = FF_; N = D_;
        in_ls = (size_t)FF_ * D_; out_ls = (size_t)D_ * FF_;
    }
    const int ntn = N / 32;
    const int tpl = ntn * (K / 32);
    const int l = local / tpl, rem = local % tpl;
    const int n0 = (rem % ntn) * 32, k0 = (rem / ntn) * 32;
    const float* Wl = src + (size_t)l * in_ls;
    __half* Ol = dst + (size_t)l * out_ls;

    __shared__ float t[32][33];
    const int tx = threadIdx.x & 31, ty = threadIdx.x >> 5;
    #pragma unroll
    for (int i = 0; i < 32; i += 8)
        t[ty + i][tx] = Wl[(size_t)(k0 + ty + i) * N + n0 + tx];
    __syncthreads();
    #pragma unroll
    for (int i = 0; i < 32; i += 8)
        Ol[(size_t)(n0 + ty + i) * K + k0 + tx] = __float2half_rn(t[tx][ty + i]);
}

// ---------------------------------------------------------------------------
// LayerNorm over last dim (D=1024); fused fp32 + optional fp16 output.
// ---------------------------------------------------------------------------
__inline__ __device__ float warpSum(float v) {
    #pragma unroll
    for (int o = 16; o > 0; o >>= 1) v += __shfl_xor_sync(0xffffffffu, v, o);
    return v;
}

__global__ void __launch_bounds__(256) ln_kernel(
    const float* __restrict__ in, const float* __restrict__ gamma,
    const float* __restrict__ beta, float* __restrict__ out,
    __half* __restrict__ oh)
{
    const size_t row = blockIdx.x;
    const float4 val = ((const float4*)(in + row * D_))[threadIdx.x];

    float s  = val.x + val.y + val.z + val.w;
    float sq = val.x * val.x + val.y * val.y + val.z * val.z + val.w * val.w;

    __shared__ float ssum[8], ssq[8];
    s  = warpSum(s);
    sq = warpSum(sq);
    const int wid = threadIdx.x >> 5, lane = threadIdx.x & 31;
    if (lane == 0) { ssum[wid] = s; ssq[wid] = sq; }
    __syncthreads();
    s = 0.f; sq = 0.f;
    #pragma unroll
    for (int i = 0; i < 8; i++) { s += ssum[i]; sq += ssq[i]; }

    const float mean = s * (1.0f / D_);
    const float var  = sq * (1.0f / D_) - mean * mean;
    const float rstd = rsqrtf(var + 1e-6f);

    const int c = threadIdx.x << 2;
    const float4 gv = *(const float4*)(gamma + c);
    const float4 bb = *(const float4*)(beta + c);
    float4 o;
    o.x = (val.x - mean) * rstd * gv.x + bb.x;
    o.y = (val.y - mean) * rstd * gv.y + bb.y;
    o.z = (val.z - mean) * rstd * gv.z + bb.z;
    o.w = (val.w - mean) * rstd * gv.w + bb.w;
    ((float4*)(out + row * D_))[threadIdx.x] = o;

    if (oh) {
        *(uint2*)(oh + row * D_ + c) =
            make_uint2(pack_hf2(o.x, o.y), pack_hf2(o.z, o.w));
    }
}

// ---------------------------------------------------------------------------
// Launch
// ---------------------------------------------------------------------------
extern "C" void kernel_launch(void* const* d_in, const int* in_sizes, int n_in,
                              void* d_out, int out_size)
{
    (void)in_sizes; (void)n_in; (void)out_size;

    const float* hs  = (const float*)d_in[0];
    const float* Wq  = (const float*)d_in[1];
    const float* bq  = (const float*)d_in[2];
    const float* Wk  = (const float*)d_in[3];
    const float* bk  = (const float*)d_in[4];
    const float* Wv  = (const float*)d_in[5];
    const float* bv  = (const float*)d_in[6];
    const float* Wp  = (const float*)d_in[7];
    const float* bp  = (const float*)d_in[8];
    const float* g1  = (const float*)d_in[9];
    const float* be1 = (const float*)d_in[10];
    const float* W1  = (const float*)d_in[11];
    const float* b1  = (const float*)d_in[12];
    const float* W2  = (const float*)d_in[13];
    const float* b2  = (const float*)d_in[14];
    const float* g2  = (const float*)d_in[15];
    const float* be2 = (const float*)d_in[16];

    float *x, *t, *bqkv;
    __half *xh, *qkv, *ch, *ff, *wqkv, *wp, *w1, *w2;
    cudaGetSymbolAddress((void**)&x,    g_x);
    cudaGetSymbolAddress((void**)&t,    g_t);
    cudaGetSymbolAddress((void**)&bqkv, g_bqkv);
    cudaGetSymbolAddress((void**)&xh,   g_xh);
    cudaGetSymbolAddress((void**)&qkv,  g_qkv);
    cudaGetSymbolAddress((void**)&ch,   g_ch);
    cudaGetSymbolAddress((void**)&ff,   g_ff);
    cudaGetSymbolAddress((void**)&wqkv, g_wqkv);
    cudaGetSymbolAddress((void**)&wp,   g_wp);
    cudaGetSymbolAddress((void**)&w1,   g_w1);
    cudaGetSymbolAddress((void**)&w2,   g_w2);

    cudaFuncSetAttribute(gemm_mma, cudaFuncAttributeMaxDynamicSharedMemorySize,
                         GSMEM);
    cudaFuncSetAttribute(attn_mma, cudaFuncAttributeMaxDynamicSharedMemorySize,
                         ATTN_SMEM);

    const dim3 tb(256);

    // ---- single fused preprocessing launch ----
    prep_all<<<PREP_BLOCKS, tb>>>(hs, Wq, Wk, Wv, Wp, W1, W2, bq, bk, bv,
                                  wqkv, wp, w1, w2, bqkv, x, xh);

    const dim3 gQKV(QKV_N / 128, MTOK / 128);   // (24, 32)
    const dim3 gD  (D_    / 128, MTOK / 128);   // (8, 32)
    const dim3 gFF (FF_   / 128, MTOK / 128);   // (32, 32)
    const dim3 gA  (S_ / 64, H_, B_);           // (32, 16, 2)

    for (int l = 0; l < L_; l++) {
        const size_t lDD = (size_t)l * D_ * D_;
        const size_t lDF = (size_t)l * D_ * FF_;

        gemm_mma<<<gQKV, tb, GSMEM>>>(
            xh, wqkv + (size_t)l * QKV_N * D_,
            bqkv + (size_t)l * QKV_N, nullptr, nullptr, qkv,
            D_, QKV_N, 0);

        attn_mma<<<gA, dim3(128), ATTN_SMEM>>>(qkv, ch);

        gemm_mma<<<gD, tb, GSMEM>>>(
            ch, wp + lDD, bp + (size_t)l * D_, x,
            t, nullptr, D_, D_, 0);
        ln_kernel<<<MTOK, tb>>>(t, g1 + (size_t)l * D_, be1 + (size_t)l * D_,
                                x, xh);

        gemm_mma<<<gFF, tb, GSMEM>>>(
            xh, w1 + lDF, b1 + (size_t)l * FF_, nullptr,
            nullptr, ff, D_, FF_, 1);

        gemm_mma<<<gD, tb, GSMEM>>>(
            ff, w2 + lDF, b2 + (size_t)l * D_, x,
            t, nullptr, FF_, D_, 0);

        if (l == L_ - 1) {
            ln_kernel<<<MTOK, tb>>>(t, g2 + (size_t)l * D_, be2 + (size_t)l * D_,
                                    (float*)d_out, nullptr);
        } else {
            ln_kernel<<<MTOK, tb>>>(t, g2 + (size_t)l * D_, be2 + (size_t)l * D_,
                                    x, xh);
        }
    }
}

// round 15
// speedup vs baseline: 7.9710x; 1.0317x over previous
#include <cuda_runtime.h>
#include <cuda_fp16.h>
#include <cstdint>

// Problem constants
#define B_    2
#define S_    2048
#define D_    1024
#define FF_   4096
#define H_    16
#define DH_   64
#define L_    4
#define MTOK  (B_ * S_)      // 4096 tokens
#define QKV_N (3 * D_)       // 3072

// ---------------------------------------------------------------------------
// Scratch (static device globals; no runtime allocation)
// ---------------------------------------------------------------------------
__device__ float  g_x   [MTOK * D_];          // running hidden (fp32)
__device__ __half g_xh  [MTOK * D_];          // fp16 hidden
__device__ __half g_qkv [MTOK * QKV_N];       // fused QKV (fp16)
__device__ __half g_ch  [MTOK * D_];          // attention ctx (fp16)
__device__ float  g_t   [MTOK * D_];          // pre-LN temp
__device__ __half g_ff  [MTOK * FF_];         // FFN hidden (fp16)

// transposed fp16 weights ([N, K] row-major)
__device__ __half g_wqkv[L_ * QKV_N * D_];
__device__ __half g_wp  [L_ * D_ * D_];
__device__ __half g_w1  [L_ * FF_ * D_];      // [FF, D]
__device__ __half g_w2  [L_ * D_ * FF_];      // [D, FF]
__device__ float  g_bqkv[L_ * QKV_N];

// ---------------------------------------------------------------------------
// Baseline-PTX helpers (sm_75/80 features only)
// ---------------------------------------------------------------------------
__device__ __forceinline__ uint32_t smem_u32(const void* p) {
    uint32_t a;
    asm("{ .reg .u64 t; cvta.to.shared.u64 t, %1; cvt.u32.u64 %0, t; }"
        : "=r"(a) : "l"(p));
    return a;
}
__device__ __forceinline__ void cp16(uint32_t s, const void* g) {
    asm volatile("cp.async.cg.shared.global [%0], [%1], 16;" :: "r"(s), "l"(g));
}
#define CP_COMMIT() asm volatile("cp.async.commit_group;" ::: "memory")

__device__ __forceinline__ void cp_wait_dyn(int more) {
    if (more) asm volatile("cp.async.wait_group 1;" ::: "memory");
    else      asm volatile("cp.async.wait_group 0;" ::: "memory");
}

__device__ __forceinline__ void ldsm4(uint32_t r[4], uint32_t addr) {
    asm volatile("ldmatrix.sync.aligned.m8n8.x4.shared.b16 {%0,%1,%2,%3}, [%4];"
        : "=r"(r[0]), "=r"(r[1]), "=r"(r[2]), "=r"(r[3]) : "r"(addr));
}
__device__ __forceinline__ void ldsm4t(uint32_t r[4], uint32_t addr) {
    asm volatile("ldmatrix.sync.aligned.m8n8.x4.trans.shared.b16 {%0,%1,%2,%3}, [%4];"
        : "=r"(r[0]), "=r"(r[1]), "=r"(r[2]), "=r"(r[3]) : "r"(addr));
}
__device__ __forceinline__ void mma16816(float c[4], const uint32_t a[4],
                                         const uint32_t b[2]) {
    asm volatile(
        "mma.sync.aligned.m16n8k16.row.col.f32.f16.f16.f32 "
        "{%0,%1,%2,%3}, {%4,%5,%6,%7}, {%8,%9}, {%0,%1,%2,%3};"
        : "+f"(c[0]), "+f"(c[1]), "+f"(c[2]), "+f"(c[3])
        : "r"(a[0]), "r"(a[1]), "r"(a[2]), "r"(a[3]),
          "r"(b[0]), "r"(b[1]));
}
__device__ __forceinline__ uint32_t pack_hf2(float a, float b) {
    __half2 t = __halves2half2(__float2half_rn(a), __float2half_rn(b));
    return reinterpret_cast<uint32_t&>(t);
}

// ---------------------------------------------------------------------------
// fp16 1-pass GEMM:  C[M,N] = A[M,K] @ B[N,K]^T + bias (+residual) (+relu)
// Block 128x128, FOUR warps (2x2 -> warp tile 64x64), 128 threads.
// Per kk-step: 8 LDSM.x4 -> 32 HMMA (4:1 density; the B-fragment pattern is
// the attention kernel's validated kh loader). K-stage 64, 3-stage cp.async
// ring, single __syncthreads per stage. Stage 32KB; 96KB total; 2 CTAs/SM
// (reg budget 256/thread -> acc 128 + frags fit without spills).
// ---------------------------------------------------------------------------
#define GSTAGE  32768
#define GSMEM   (3 * GSTAGE)   // 98304

__device__ __forceinline__ void gemm_load_stage(
    uint32_t sbase, const __half* __restrict__ Ah,
    const __half* __restrict__ Bh,
    int m0, int n0, int K, int k0, int tid)
{
    #pragma unroll
    for (int i = 0; i < 16; i++) {
        const int task = tid + i * 128;          // 2048 tasks, 128 threads
        const int arr = task >> 10;              // 0=A, 1=B
        const int idx = task & 1023;
        const int r = idx >> 3, ch = idx & 7;
        const uint32_t dst = sbase + arr * 16384 + r * 128
                           + (uint32_t)((ch ^ (r & 7)) << 4);
        const __half* src = arr
            ? Bh + (size_t)(n0 + r) * K + k0 + ch * 8
            : Ah + (size_t)(m0 + r) * K + k0 + ch * 8;
        cp16(dst, src);
    }
}

__global__ void __launch_bounds__(128, 2) gemm_mma(
    const __half* __restrict__ Ah, const __half* __restrict__ Bh,
    const float* __restrict__ bias, const float* __restrict__ Rsd,
    float* __restrict__ Cf, __half* __restrict__ Ch,
    int K, int N, int relu)
{
    extern __shared__ char sm[];
    const uint32_t smb = smem_u32(sm);
    const int tid = threadIdx.x;
    const int wid = tid >> 5, lane = tid & 31;
    const int wm = wid >> 1, wn = wid & 1;          // warp grid 2x2
    const int lq = lane >> 2, lr = lane & 3;
    const int m0 = blockIdx.y * 128, n0 = blockIdx.x * 128;

    float acc[4][8][4];
    #pragma unroll
    for (int i = 0; i < 4; i++)
        #pragma unroll
        for (int j = 0; j < 8; j++)
            #pragma unroll
            for (int k = 0; k < 4; k++) acc[i][j][k] = 0.0f;

    const int NS = K / 64;    // 16 (K=1024) or 64 (K=4096)

    gemm_load_stage(smb,          Ah, Bh, m0, n0, K, 0,  tid);
    CP_COMMIT();
    gemm_load_stage(smb + GSTAGE, Ah, Bh, m0, n0, K, 64, tid);
    CP_COMMIT();

    const int a_rl = ((lane >> 3) & 1) * 8 + (lane & 7);  // A row grp
    const int a_cg = (lane >> 4) & 1;                     // A k-chunk
    const int b_rl = ((lane >> 4) & 1) * 8 + (lane & 7);  // B row grp
    const int b_cg = (lane >> 3) & 1;                     // B k-chunk

    int bufc = 0;                  // s % 3
    int bufn = 2;                  // (s+2) % 3
    for (int s = 0; s < NS; s++) {
        cp_wait_dyn(s + 1 < NS);
        __syncthreads();
        if (s + 2 < NS) {
            gemm_load_stage(smb + bufn * GSTAGE,
                            Ah, Bh, m0, n0, K, (s + 2) * 64, tid);
            CP_COMMIT();
        }

        const uint32_t sA = smb + bufc * GSTAGE;
        const uint32_t sB = sA + 16384;
        bufc = (bufc == 2) ? 0 : bufc + 1;
        bufn = (bufn == 2) ? 0 : bufn + 1;

        #pragma unroll
        for (int kk = 0; kk < 4; kk++) {
            uint32_t ah[4][4];
            #pragma unroll
            for (int mt = 0; mt < 4; mt++) {
                const int row = wm * 64 + mt * 16 + a_rl;
                const int c = 2 * kk + a_cg;
                ldsm4(ah[mt], sA + row * 128 + ((c ^ (row & 7)) << 4));
            }
            uint32_t bh[8][2];
            #pragma unroll
            for (int u = 0; u < 4; u++) {
                const int j = wn * 64 + u * 16 + b_rl;
                const int c = 2 * kk + b_cg;
                uint32_t t4[4];
                ldsm4(t4, sB + j * 128 + ((c ^ (j & 7)) << 4));
                bh[2*u][0] = t4[0]; bh[2*u][1] = t4[1];
                bh[2*u+1][0] = t4[2]; bh[2*u+1][1] = t4[3];
            }
            #pragma unroll
            for (int mt = 0; mt < 4; mt++)
                #pragma unroll
                for (int nt = 0; nt < 8; nt++)
                    mma16816(acc[mt][nt], ah[mt], bh[nt]);
        }
    }

    // Epilogue (fragment: c0,c1 at (lq, 2lr), c2,c3 at (lq+8, 2lr))
    const int row0 = m0 + wm * 64;
    const int col0 = n0 + wn * 64;
    #pragma unroll
    for (int mt = 0; mt < 4; mt++) {
        #pragma unroll
        for (int nt = 0; nt < 8; nt++) {
            const int c = col0 + nt * 8 + lr * 2;
            const float b0 = bias[c], b1 = bias[c + 1];
            #pragma unroll
            for (int h = 0; h < 2; h++) {
                const int r = row0 + mt * 16 + lq + h * 8;
                float v0 = acc[mt][nt][2 * h]     + b0;
                float v1 = acc[mt][nt][2 * h + 1] + b1;
                const size_t o = (size_t)r * N + c;
                if (Rsd) {
                    const float2 rv = *(const float2*)(Rsd + o);
                    v0 += rv.x; v1 += rv.y;
                }
                if (relu) { v0 = fmaxf(v0, 0.0f); v1 = fmaxf(v1, 0.0f); }
                if (Cf) *(float2*)(Cf + o) = make_float2(v0, v1);
                if (Ch) *(uint32_t*)(Ch + o) = pack_hf2(v0, v1);
            }
        }
    }
}

// ---------------------------------------------------------------------------
// FA2-style attention, pure fp16 1-pass on QK^T and PV.
// Block 64 q-rows, 4 warps, Bc=64, DH=64 (rows naturally 128B).
// 3-stage KV ring, single __syncthreads per key tile.
// smem: Q 8KB + 3 stages x (K 8KB + V 8KB) = 56KB -> 3 CTAs/SM.
// Swizzle ch^(r&7). Grid: (S/64, H, B), 128 threads.
// ---------------------------------------------------------------------------
#define A_STG  8192
#define A_SSZ  16384
#define ATTN_SMEM (A_STG + 3 * A_SSZ)   // 57344

__device__ __forceinline__ void attn_load_kv(
    uint32_t sbase, const __half* __restrict__ QKV,
    size_t krow0, int hcol, int tid)
{
    // 2 arrays (K, V) x 64 rows x 8 chunks = 1024 tasks, 128 threads
    #pragma unroll
    for (int i = 0; i < 8; i++) {
        const int task = tid + i * 128;
        const int arr = task >> 9;               // 0 = K, 1 = V
        const int r = (task >> 3) & 63;
        const int ch = task & 7;
        const uint32_t dst = sbase + arr * 8192 + r * 128
                           + (uint32_t)((ch ^ (r & 7)) << 4);
        const int col = (arr ? 2 * D_ : D_) + hcol + ch * 8;
        cp16(dst, QKV + (krow0 + r) * QKV_N + col);
    }
}

__global__ void __launch_bounds__(128, 3) attn_mma(
    const __half* __restrict__ QKV, __half* __restrict__ Ch)
{
    extern __shared__ char sm[];
    const uint32_t smb = smem_u32(sm);
    const int tid = threadIdx.x;
    const int w = tid >> 5, lane = tid & 31;
    const int lq = lane >> 2, lr = lane & 3;
    const int qt = blockIdx.x, h = blockIdx.y, b = blockIdx.z;
    const size_t qrow0 = (size_t)b * S_ + qt * 64;
    const size_t krowb = (size_t)b * S_;
    const int hcol = h * DH_;

    // ---- load Q tile (512 tasks) + KV stages 0,1
    #pragma unroll
    for (int i = 0; i < 4; i++) {
        const int task = tid + i * 128;
        const int r = task >> 3, ch = task & 7;
        const uint32_t dst = smb + r * 128 + (uint32_t)((ch ^ (r & 7)) << 4);
        cp16(dst, QKV + (qrow0 + r) * QKV_N + hcol + ch * 8);
    }
    attn_load_kv(smb + A_STG, QKV, krowb, hcol, tid);
    CP_COMMIT();
    attn_load_kv(smb + A_STG + A_SSZ, QKV, krowb + 64, hcol, tid);
    CP_COMMIT();

    float m0 = -1e30f, m1 = -1e30f, l0 = 0.0f, l1 = 0.0f;
    float oacc[8][4];
    #pragma unroll
    for (int t = 0; t < 8; t++)
        #pragma unroll
        for (int i = 0; i < 4; i++) oacc[t][i] = 0.0f;

    uint32_t qh[4][4];

    const int a_rl = ((lane >> 3) & 1) * 8 + (lane & 7);
    const int a_cg = (lane >> 4) & 1;
    const int b_rl = ((lane >> 4) & 1) * 8 + (lane & 7);
    const int b_cg = (lane >> 3) & 1;

    const int NT = S_ / 64;   // 32 key tiles
    int bufc = 0, bufn = 2;
    for (int j = 0; j < NT; j++) {
        cp_wait_dyn(j + 1 < NT);
        __syncthreads();
        if (j + 2 < NT) {
            attn_load_kv(smb + A_STG + bufn * A_SSZ,
                         QKV, krowb + (size_t)(j + 2) * 64, hcol, tid);
            CP_COMMIT();
        }

        if (j == 0) {
            // load Q fragments once; fold in softmax scale 1/8 (exact)
            const __half2 s2 = __float2half2_rn(0.125f);
            #pragma unroll
            for (int kk = 0; kk < 4; kk++) {
                const int row = w * 16 + a_rl;
                const int chh = a_cg + 2 * kk;
                ldsm4(qh[kk], smb + row * 128 + ((chh ^ (row & 7)) << 4));
                #pragma unroll
                for (int i = 0; i < 4; i++) {
                    __half2 vh = reinterpret_cast<__half2&>(qh[kk][i]);
                    vh = __hmul2(vh, s2);
                    qh[kk][i] = reinterpret_cast<uint32_t&>(vh);
                }
            }
        }

        const uint32_t sK = smb + A_STG + bufc * A_SSZ;
        const uint32_t sV = sK + 8192;
        bufc = (bufc == 2) ? 0 : bufc + 1;
        bufn = (bufn == 2) ? 0 : bufn + 1;

        // ---- S = Q @ K^T (1 pass): 16x64 per warp
        float sacc[8][4];
        #pragma unroll
        for (int t = 0; t < 8; t++)
            #pragma unroll
            for (int i = 0; i < 4; i++) sacc[t][i] = 0.0f;

        #pragma unroll
        for (int kk = 0; kk < 4; kk++) {
            uint32_t kh[8][2];
            #pragma unroll
            for (int u = 0; u < 4; u++) {
                const int row = u * 16 + b_rl;      // key index
                const int chh = 2 * kk + b_cg;      // d chunk
                uint32_t t4[4];
                ldsm4(t4, sK + row * 128 + ((chh ^ (row & 7)) << 4));
                kh[2*u][0] = t4[0]; kh[2*u][1] = t4[1];
                kh[2*u+1][0] = t4[2]; kh[2*u+1][1] = t4[3];
            }
            #pragma unroll
            for (int t = 0; t < 8; t++)
                mma16816(sacc[t], qh[kk], kh[t]);
        }

        // ---- online softmax (rows lq and lq+8)
        float mx0 = -1e30f, mx1 = -1e30f;
        #pragma unroll
        for (int t = 0; t < 8; t++) {
            mx0 = fmaxf(mx0, fmaxf(sacc[t][0], sacc[t][1]));
            mx1 = fmaxf(mx1, fmaxf(sacc[t][2], sacc[t][3]));
        }
        mx0 = fmaxf(mx0, __shfl_xor_sync(0xffffffffu, mx0, 1));
        mx0 = fmaxf(mx0, __shfl_xor_sync(0xffffffffu, mx0, 2));
        mx1 = fmaxf(mx1, __shfl_xor_sync(0xffffffffu, mx1, 1));
        mx1 = fmaxf(mx1, __shfl_xor_sync(0xffffffffu, mx1, 2));
        const float nm0 = fmaxf(m0, mx0), nm1 = fmaxf(m1, mx1);
        const float al0 = __expf(m0 - nm0), al1 = __expf(m1 - nm1);
        m0 = nm0; m1 = nm1;

        float ps0 = 0.0f, ps1 = 0.0f;
        #pragma unroll
        for (int t = 0; t < 8; t++) {
            sacc[t][0] = __expf(sacc[t][0] - m0);
            sacc[t][1] = __expf(sacc[t][1] - m0);
            sacc[t][2] = __expf(sacc[t][2] - m1);
            sacc[t][3] = __expf(sacc[t][3] - m1);
            ps0 += sacc[t][0] + sacc[t][1];
            ps1 += sacc[t][2] + sacc[t][3];
        }
        ps0 += __shfl_xor_sync(0xffffffffu, ps0, 1);
        ps0 += __shfl_xor_sync(0xffffffffu, ps0, 2);
        ps1 += __shfl_xor_sync(0xffffffffu, ps1, 1);
        ps1 += __shfl_xor_sync(0xffffffffu, ps1, 2);
        l0 = l0 * al0 + ps0;
        l1 = l1 * al1 + ps1;

        #pragma unroll
        for (int t = 0; t < 8; t++) {
            oacc[t][0] *= al0; oacc[t][1] *= al0;
            oacc[t][2] *= al1; oacc[t][3] *= al1;
        }

        // ---- P -> fp16 A-fragments (C-layout -> A-layout identity)
        uint32_t ph[4][4];
        #pragma unroll
        for (int kk = 0; kk < 4; kk++) {
            const int t0 = 2 * kk, t1 = 2 * kk + 1;
            ph[kk][0] = pack_hf2(sacc[t0][0], sacc[t0][1]);
            ph[kk][1] = pack_hf2(sacc[t0][2], sacc[t0][3]);
            ph[kk][2] = pack_hf2(sacc[t1][0], sacc[t1][1]);
            ph[kk][3] = pack_hf2(sacc[t1][2], sacc[t1][3]);
        }

        // ---- O += P @ V (1 pass); V^T via ldmatrix.trans
        #pragma unroll
        for (int kk = 0; kk < 4; kk++) {           // key window 16*kk
            uint32_t vh[8][2];
            #pragma unroll
            for (int u = 0; u < 4; u++) {
                const int row = 16 * kk + a_rl;    // key row
                const int chh = 2 * u + a_cg;      // d chunk
                uint32_t t4[4];
                ldsm4t(t4, sV + row * 128 + ((chh ^ (row & 7)) << 4));
                vh[2*u][0] = t4[0]; vh[2*u][1] = t4[1];
                vh[2*u+1][0] = t4[2]; vh[2*u+1][1] = t4[3];
            }
            #pragma unroll
            for (int t = 0; t < 8; t++)
                mma16816(oacc[t], ph[kk], vh[t]);
        }
    }

    // ---- epilogue: O /= l, write ctx fp16
    const float i0 = 1.0f / l0, i1 = 1.0f / l1;
    const size_t r0g = qrow0 + w * 16 + lq;
    #pragma unroll
    for (int t = 0; t < 8; t++) {
        const int col = hcol + t * 8 + 2 * lr;
        *(uint32_t*)(Ch + r0g * D_ + col) =
            pack_hf2(oacc[t][0] * i0, oacc[t][1] * i0);
        *(uint32_t*)(Ch + (r0g + 8) * D_ + col) =
            pack_hf2(oacc[t][2] * i1, oacc[t][3] * i1);
    }
}

// ---------------------------------------------------------------------------
// Fused preprocessing: ALL weight transposes (fp32 [K,N] -> fp16 [N,K]),
// QKV bias concat, and hidden-state fp32 copy + fp16 cast — ONE launch.
// ---------------------------------------------------------------------------
#define PREP_BLOCKS 65584

__global__ void __launch_bounds__(256) prep_all(
    const float* __restrict__ hs,
    const float* __restrict__ Wq, const float* __restrict__ Wk,
    const float* __restrict__ Wv, const float* __restrict__ Wp,
    const float* __restrict__ W1, const float* __restrict__ W2,
    const float* __restrict__ bq, const float* __restrict__ bk,
    const float* __restrict__ bv,
    __half* __restrict__ wqkv, __half* __restrict__ wpw,
    __half* __restrict__ w1w, __half* __restrict__ w2w,
    float* __restrict__ bqkv, float* __restrict__ x,
    __half* __restrict__ xh)
{
    const int bid = blockIdx.x;

    if (bid >= 49200) {                         // hidden copy + cast
        const int i = (bid - 49200) * 256 + threadIdx.x;
        const float v = hs[i];
        x[i] = v;
        xh[i] = __float2half_rn(v);
        return;
    }
    if (bid >= 49152) {                         // bias concat
        const int i = (bid - 49152) * 256 + threadIdx.x;
        const int l = i / QKV_N, j = i % QKV_N;
        float v;
        if (j < D_)            v = bq[l * D_ + j];
        else if (j < 2 * D_)   v = bk[l * D_ + j - D_];
        else                   v = bv[l * D_ + j - 2 * D_];
        bqkv[i] = v;
        return;
    }

    // ---- weight transpose tile
    const float* src; __half* dst; int K, N;
    size_t in_ls, out_ls;
    int local;
    if (bid < 16384) {
        const int g = bid >> 12;                // 0..3
        local = bid & 4095;
        K = D_; N = D_; in_ls = (size_t)D_ * D_;
        if (g == 0)      { src = Wq; dst = wqkv;                     out_ls = (size_t)QKV_N * D_; }
        else if (g == 1) { src = Wk; dst = wqkv + (size_t)D_ * D_;   out_ls = (size_t)QKV_N * D_; }
        else if (g == 2) { src = Wv; dst = wqkv + (size_t)2*D_ * D_; out_ls = (size_t)QKV_N * D_; }
        else             { src = Wp; dst = wpw;                      out_ls = (size_t)D_ * D_; }
    } else if (bid < 32768) {
        local = bid - 16384;
        src = W1; dst = w1w; K = D_; N = FF_;
        in_ls = (size_t)D_ * FF_; out_ls = (size_t)FF_ * D_;
    } else {
        local = bid - 32768;
        src = W2; dst = w2w; K = FF_; N = D_;
        in_ls = (size_t)FF_ * D_; out_ls = (size_t)D_ * FF_;
    }
    const int ntn = N / 32;
    const int tpl = ntn * (K / 32);
    const int l = local / tpl, rem = local % tpl;
    const int n0 = (rem % ntn) * 32, k0 = (rem / ntn) * 32;
    const float* Wl = src + (size_t)l * in_ls;
    __half* Ol = dst + (size_t)l * out_ls;

    __shared__ float t[32][33];
    const int tx = threadIdx.x & 31, ty = threadIdx.x >> 5;
    #pragma unroll
    for (int i = 0; i < 32; i += 8)
        t[ty + i][tx] = Wl[(size_t)(k0 + ty + i) * N + n0 + tx];
    __syncthreads();
    #pragma unroll
    for (int i = 0; i < 32; i += 8)
        Ol[(size_t)(n0 + ty + i) * K + k0 + tx] = __float2half_rn(t[tx][ty + i]);
}

// ---------------------------------------------------------------------------
// LayerNorm over last dim (D=1024); fused fp32 + optional fp16 output.
// ---------------------------------------------------------------------------
__inline__ __device__ float warpSum(float v) {
    #pragma unroll
    for (int o = 16; o > 0; o >>= 1) v += __shfl_xor_sync(0xffffffffu, v, o);
    return v;
}

__global__ void __launch_bounds__(256) ln_kernel(
    const float* __restrict__ in, const float* __restrict__ gamma,
    const float* __restrict__ beta, float* __restrict__ out,
    __half* __restrict__ oh)
{
    const size_t row = blockIdx.x;
    const float4 val = ((const float4*)(in + row * D_))[threadIdx.x];

    float s  = val.x + val.y + val.z + val.w;
    float sq = val.x * val.x + val.y * val.y + val.z * val.z + val.w * val.w;

    __shared__ float ssum[8], ssq[8];
    s  = warpSum(s);
    sq = warpSum(sq);
    const int wid = threadIdx.x >> 5, lane = threadIdx.x & 31;
    if (lane == 0) { ssum[wid] = s; ssq[wid] = sq; }
    __syncthreads();
    s = 0.f; sq = 0.f;
    #pragma unroll
    for (int i = 0; i < 8; i++) { s += ssum[i]; sq += ssq[i]; }

    const float mean = s * (1.0f / D_);
    const float var  = sq * (1.0f / D_) - mean * mean;
    const float rstd = rsqrtf(var + 1e-6f);

    const int c = threadIdx.x << 2;
    const float4 gv = *(const float4*)(gamma + c);
    const float4 bb = *(const float4*)(beta + c);
    float4 o;
    o.x = (val.x - mean) * rstd * gv.x + bb.x;
    o.y = (val.y - mean) * rstd * gv.y + bb.y;
    o.z = (val.z - mean) * rstd * gv.z + bb.z;
    o.w = (val.w - mean) * rstd * gv.w + bb.w;
    ((float4*)(out + row * D_))[threadIdx.x] = o;

    if (oh) {
        *(uint2*)(oh + row * D_ + c) =
            make_uint2(pack_hf2(o.x, o.y), pack_hf2(o.z, o.w));
    }
}

// ---------------------------------------------------------------------------
// Launch
// ---------------------------------------------------------------------------
extern "C" void kernel_launch(void* const* d_in, const int* in_sizes, int n_in,
                              void* d_out, int out_size)
{
    (void)in_sizes; (void)n_in; (void)out_size;

    const float* hs  = (const float*)d_in[0];
    const float* Wq  = (const float*)d_in[1];
    const float* bq  = (const float*)d_in[2];
    const float* Wk  = (const float*)d_in[3];
    const float* bk  = (const float*)d_in[4];
    const float* Wv  = (const float*)d_in[5];
    const float* bv  = (const float*)d_in[6];
    const float* Wp  = (const float*)d_in[7];
    const float* bp  = (const float*)d_in[8];
    const float* g1  = (const float*)d_in[9];
    const float* be1 = (const float*)d_in[10];
    const float* W1  = (const float*)d_in[11];
    const float* b1  = (const float*)d_in[12];
    const float* W2  = (const float*)d_in[13];
    const float* b2  = (const float*)d_in[14];
    const float* g2  = (const float*)d_in[15];
    const float* be2 = (const float*)d_in[16];

    float *x, *t, *bqkv;
    __half *xh, *qkv, *ch, *ff, *wqkv, *wp, *w1, *w2;
    cudaGetSymbolAddress((void**)&x,    g_x);
    cudaGetSymbolAddress((void**)&t,    g_t);
    cudaGetSymbolAddress((void**)&bqkv, g_bqkv);
    cudaGetSymbolAddress((void**)&xh,   g_xh);
    cudaGetSymbolAddress((void**)&qkv,  g_qkv);
    cudaGetSymbolAddress((void**)&ch,   g_ch);
    cudaGetSymbolAddress((void**)&ff,   g_ff);
    cudaGetSymbolAddress((void**)&wqkv, g_wqkv);
    cudaGetSymbolAddress((void**)&wp,   g_wp);
    cudaGetSymbolAddress((void**)&w1,   g_w1);
    cudaGetSymbolAddress((void**)&w2,   g_w2);

    cudaFuncSetAttribute(gemm_mma, cudaFuncAttributeMaxDynamicSharedMemorySize,
                         GSMEM);
    cudaFuncSetAttribute(attn_mma, cudaFuncAttributeMaxDynamicSharedMemorySize,
                         ATTN_SMEM);

    const dim3 tb(256);

    // ---- single fused preprocessing launch ----
    prep_all<<<PREP_BLOCKS, tb>>>(hs, Wq, Wk, Wv, Wp, W1, W2, bq, bk, bv,
                                  wqkv, wp, w1, w2, bqkv, x, xh);

    const dim3 gQKV(QKV_N / 128, MTOK / 128);   // (24, 32)
    const dim3 gD  (D_    / 128, MTOK / 128);   // (8, 32)
    const dim3 gFF (FF_   / 128, MTOK / 128);   // (32, 32)
    const dim3 gA  (S_ / 64, H_, B_);           // (32, 16, 2)
    const dim3 gb(128);                          // GEMM/attn blocks

    for (int l = 0; l < L_; l++) {
        const size_t lDD = (size_t)l * D_ * D_;
        const size_t lDF = (size_t)l * D_ * FF_;

        gemm_mma<<<gQKV, gb, GSMEM>>>(
            xh, wqkv + (size_t)l * QKV_N * D_,
            bqkv + (size_t)l * QKV_N, nullptr, nullptr, qkv,
            D_, QKV_N, 0);

        attn_mma<<<gA, gb, ATTN_SMEM>>>(qkv, ch);

        gemm_mma<<<gD, gb, GSMEM>>>(
            ch, wp + lDD, bp + (size_t)l * D_, x,
            t, nullptr, D_, D_, 0);
        ln_kernel<<<MTOK, tb>>>(t, g1 + (size_t)l * D_, be1 + (size_t)l * D_,
                                x, xh);

        gemm_mma<<<gFF, gb, GSMEM>>>(
            xh, w1 + lDF, b1 + (size_t)l * FF_, nullptr,
            nullptr, ff, D_, FF_, 1);

        gemm_mma<<<gD, gb, GSMEM>>>(
            ff, w2 + lDF, b2 + (size_t)l * D_, x,
            t, nullptr, FF_, D_, 0);

        if (l == L_ - 1) {
            ln_kernel<<<MTOK, tb>>>(t, g2 + (size_t)l * D_, be2 + (size_t)l * D_,
                                    (float*)d_out, nullptr);
        } else {
            ln_kernel<<<MTOK, tb>>>(t, g2 + (size_t)l * D_, be2 + (size_t)l * D_,
                                    x, xh);
        }
    }
}